// round 7
// baseline (speedup 1.0000x reference)
#include <cuda_runtime.h>
#include <cuda_bf16.h>
#include <math.h>

#define NB    2048
#define CIN   16
#define VMD   42
#define NNODE (NB*8*VMD)            // 688128 = 1344*512
#define EINC  (4*NNODE)             // 2752512
#define EMB   336
#define ROWS  (NB*8)                // 16384
#define KDIM  336
#define NSTEP 21
#define NN16  (NNODE*16)
#define NBLK  1344

// ---------------- scratch ----------------
__device__ __align__(16) float  g_xn[NN16];
__device__ __align__(16) float  g_xb[NN16];
__device__ __align__(16) float  g_e [NN16];
__device__ __align__(16) float  g_h [NN16];
__device__ __align__(16) float  g_D [NNODE];   // Dinv
__device__ __align__(16) float  g_B [NNODE];   // Binv
__device__ __align__(16) float  g_qkv[ROWS*3*EMB];
__device__ __align__(16) float  g_Wc [3*EMB*EMB];
__device__ __align__(16) float  g_bc [3*EMB];
__device__ double g_sum[CIN], g_sum2[CIN];
__device__ float  g_scale[CIN], g_shift[CIN];
// CSR build
__device__ int g_cntE[NNODE], g_cntD[NNODE];
__device__ int g_offE[NNODE], g_offD[NNODE];
__device__ int g_curE[NNODE], g_curD[NNODE];
__device__ int g_csrE[EINC],  g_csrD[EINC];
__device__ int g_bsum[2*NBLK];
// bf16 hi/lo staging
__device__ __align__(16) __nv_bfloat16 g_seqh[ROWS*KDIM], g_seql[ROWS*KDIM];
__device__ __align__(16) __nv_bfloat16 g_aoh [ROWS*KDIM], g_aol [ROWS*KDIM];
__device__ __align__(16) __nv_bfloat16 g_o2h [ROWS*KDIM], g_o2l [ROWS*KDIM];
__device__ __align__(16) __nv_bfloat16 g_wch [1024*KDIM], g_wcl [1024*KDIM];
__device__ __align__(16) __nv_bfloat16 g_oph [384*KDIM],  g_opl [384*KDIM];
__device__ __align__(16) __nv_bfloat16 g_fwh [2688*KDIM], g_fwl [2688*KDIM];

// ---------------- helpers ----------------
__device__ __forceinline__ unsigned smem_u32(const void* p) {
    unsigned a;
    asm("{ .reg .u64 t; cvta.to.shared.u64 t, %1; cvt.u32.u64 %0, t; }" : "=r"(a) : "l"(p));
    return a;
}
__device__ __forceinline__ void ldm4(unsigned* r, unsigned addr) {
    asm volatile("ldmatrix.sync.aligned.m8n8.x4.shared.b16 {%0,%1,%2,%3}, [%4];"
        : "=r"(r[0]), "=r"(r[1]), "=r"(r[2]), "=r"(r[3]) : "r"(addr));
}
__device__ __forceinline__ void mma16816(float* d, const unsigned* a, const unsigned* b) {
    asm volatile("mma.sync.aligned.m16n8k16.row.col.f32.bf16.bf16.f32 "
        "{%0,%1,%2,%3}, {%4,%5,%6,%7}, {%8,%9}, {%0,%1,%2,%3};"
        : "+f"(d[0]), "+f"(d[1]), "+f"(d[2]), "+f"(d[3])
        : "r"(a[0]), "r"(a[1]), "r"(a[2]), "r"(a[3]), "r"(b[0]), "r"(b[1]));
}
__device__ __forceinline__ void cpa16(unsigned dst, const void* src) {
    asm volatile("cp.async.cg.shared.global [%0], [%1], 16;" :: "r"(dst), "l"(src));
}
__device__ __forceinline__ unsigned long long ffma2(unsigned long long a,
                                                    unsigned long long b,
                                                    unsigned long long c) {
    unsigned long long d;
    asm("fma.rn.f32x2 %0, %1, %2, %3;" : "=l"(d) : "l"(a), "l"(b), "l"(c));
    return d;
}
__device__ __forceinline__ unsigned long long pack2(float x, float y) {
    unsigned long long d;
    asm("mov.b64 %0, {%1, %2};" : "=l"(d) : "f"(x), "f"(y));
    return d;
}
__device__ __forceinline__ float2 unpack2(unsigned long long v) {
    float2 r;
    asm("mov.b64 {%0, %1}, %2;" : "=f"(r.x), "=f"(r.y) : "l"(v));
    return r;
}
__device__ __forceinline__ void split_store(float v, __nv_bfloat16* hi, __nv_bfloat16* lo,
                                            size_t off) {
    __nv_bfloat16 h = __float2bfloat16(v);
    hi[off] = h;
    lo[off] = __float2bfloat16(v - __bfloat162float(h));
}

// ---------------- init (small) ----------------
__global__ void k_zero_small() {
    int i = blockIdx.x*blockDim.x + threadIdx.x;
    if (i < NNODE) { g_cntE[i] = 0; g_cntD[i] = 0; }
    if (i < CIN) { g_sum[i] = 0.0; g_sum2[i] = 0.0; }
}

// ---------------- stage x node-major (transpose) ----------------
__global__ void k_stage(const float* __restrict__ x) {
    __shared__ float sx[16*337];
    const int n = blockIdx.x, tid = threadIdx.x;
    const float* xp = x + (size_t)n*5376;
    for (int i = tid; i < 5376; i += 256) {
        int c = i / 336, rem = i % 336;
        sx[c*337 + rem] = xp[i];
    }
    __syncthreads();
    const size_t base = (size_t)n*5376;
    for (int i = tid; i < 5376; i += 256) {
        int rem = i >> 4, c = i & 15;
        g_xn[base + i] = sx[c*337 + rem];
    }
}

// ---------------- BatchNorm ----------------
__global__ void k_bnstats(const float* __restrict__ x) {
    __shared__ double sh[128], sh2[128];
    int b = blockIdx.x;
    const float* p = x + b*336;
    double s = 0.0, s2 = 0.0;
    for (int i = threadIdx.x; i < 336; i += 128) { double v = p[i]; s += v; s2 += v*v; }
    sh[threadIdx.x] = s; sh2[threadIdx.x] = s2; __syncthreads();
    for (int o = 64; o > 0; o >>= 1) {
        if (threadIdx.x < o) { sh[threadIdx.x] += sh[threadIdx.x+o]; sh2[threadIdx.x] += sh2[threadIdx.x+o]; }
        __syncthreads();
    }
    if (threadIdx.x == 0) {
        int c = b & 15;
        atomicAdd(&g_sum[c], sh[0]);
        atomicAdd(&g_sum2[c], sh2[0]);
    }
}

__global__ void k_bnfin(const float* __restrict__ gamma, const float* __restrict__ beta) {
    int c = threadIdx.x;
    if (c >= CIN) return;
    double cnt = (double)NNODE;
    double mean = g_sum[c] / cnt;
    double var  = g_sum2[c] / cnt - mean*mean;
    float sc = gamma[c] * rsqrtf((float)var + 1e-5f);
    g_scale[c] = sc;
    g_shift[c] = beta[c] - (float)mean * sc;
}

__global__ void k_bnxlin() {
    int i = blockIdx.x*blockDim.x + threadIdx.x;
    if (i >= NN16) return;
    int c = i & 15;
    g_xb[i] = g_xn[i] * g_scale[c] + g_shift[c];
}

// ---------------- CSR build ----------------
__global__ void k_count(const int* __restrict__ hi) {
    int i = blockIdx.x*blockDim.x + threadIdx.x;
    if (i >= EINC) return;
    atomicAdd(&g_cntD[hi[i]], 1);
    atomicAdd(&g_cntE[hi[EINC + i]], 1);
}

__global__ void k_scanA() {
    __shared__ int sh[512];
    const int a = blockIdx.y, b = blockIdx.x, tid = threadIdx.x;
    const int* cnt = a ? g_cntD : g_cntE;
    sh[tid] = cnt[b*512 + tid];
    __syncthreads();
    for (int o = 256; o > 0; o >>= 1) {
        if (tid < o) sh[tid] += sh[tid + o];
        __syncthreads();
    }
    if (tid == 0) g_bsum[a*NBLK + b] = sh[0];
}

__global__ void k_scanB() {
    __shared__ int sv[1536];
    __shared__ int ls[512], lt[512];
    const int a = blockIdx.x, tid = threadIdx.x;
    for (int i = tid; i < 1536; i += 512) sv[i] = (i < NBLK) ? g_bsum[a*NBLK + i] : 0;
    __syncthreads();
    int base = tid*3;
    int s0 = sv[base], s1 = sv[base+1], s2 = sv[base+2];
    ls[tid] = s0 + s1 + s2;
    __syncthreads();
    int* in = ls; int* out = lt;
    for (int o = 1; o < 512; o <<= 1) {
        out[tid] = in[tid] + (tid >= o ? in[tid - o] : 0);
        __syncthreads();
        int* t = in; in = out; out = t;
    }
    int chunk_ex = in[tid] - (s0 + s1 + s2);
    if (base     < NBLK) g_bsum[a*NBLK + base]     = chunk_ex;
    if (base + 1 < NBLK) g_bsum[a*NBLK + base + 1] = chunk_ex + s0;
    if (base + 2 < NBLK) g_bsum[a*NBLK + base + 2] = chunk_ex + s0 + s1;
}

__global__ void k_scanC() {
    __shared__ int s1[512], s2[512];
    const int a = blockIdx.y, b = blockIdx.x, tid = threadIdx.x;
    const int gid = b*512 + tid;
    const int* cnt = a ? g_cntD : g_cntE;
    int v = cnt[gid];
    s1[tid] = v;
    __syncthreads();
    int* in = s1; int* out = s2;
    for (int o = 1; o < 512; o <<= 1) {
        out[tid] = in[tid] + (tid >= o ? in[tid - o] : 0);
        __syncthreads();
        int* t = in; in = out; out = t;
    }
    int off = in[tid] - v + g_bsum[a*NBLK + b];
    if (a) { g_offD[gid] = off; g_curD[gid] = off; }
    else   { g_offE[gid] = off; g_curE[gid] = off; }
}

__global__ void k_place(const int* __restrict__ hi) {
    int i = blockIdx.x*blockDim.x + threadIdx.x;
    if (i >= EINC) return;
    int node = hi[i], edge = hi[EINC + i];
    int sE = atomicAdd(&g_curE[edge], 1);
    g_csrE[sE] = node;
    int sD = atomicAdd(&g_curD[node], 1);
    g_csrD[sD] = edge;
}

__global__ void k_inv2() {
    int i = blockIdx.x*blockDim.x + threadIdx.x;
    if (i >= NNODE) return;
    int ce = g_cntE[i], cd = g_cntD[i];
    g_B[i] = ce > 0 ? 1.f/(float)ce : 0.f;
    g_D[i] = cd > 0 ? 1.f/(float)cd : 0.f;
}

// ---------------- gather passes (no atomics, no pre-zero) ----------------
__global__ void k_gather_e() {
    unsigned t = blockIdx.x*blockDim.x + threadIdx.x;
    if (t >= (unsigned)NNODE * 4u) return;
    int edge = (int)(t >> 2), q = (int)((t & 3u) << 2);
    int b0 = g_offE[edge], n = g_cntE[edge];
    float4 acc = make_float4(0.f,0.f,0.f,0.f);
    for (int k = 0; k < n; k++) {
        int node = __ldg(&g_csrE[b0 + k]);
        float4 v = *(const float4*)(g_xn + (size_t)node*16 + q);
        acc.x += v.x; acc.y += v.y; acc.z += v.z; acc.w += v.w;
    }
    *(float4*)(g_e + (size_t)edge*16 + q) = acc;
}

__global__ void k_gather_h() {
    unsigned t = blockIdx.x*blockDim.x + threadIdx.x;
    if (t >= (unsigned)NNODE * 4u) return;
    int node = (int)(t >> 2), q = (int)((t & 3u) << 2);
    int b0 = g_offD[node], n = g_cntD[node];
    float4 acc = make_float4(0.f,0.f,0.f,0.f);
    for (int k = 0; k < n; k++) {
        int edge = __ldg(&g_csrD[b0 + k]);
        float w = g_B[edge];
        float4 v = *(const float4*)(g_e + (size_t)edge*16 + q);
        acc.x += w*v.x; acc.y += w*v.y; acc.z += w*v.z; acc.w += w*v.w;
    }
    *(float4*)(g_h + (size_t)node*16 + q) = acc;
}

// ---------------- fused hconv + time-conv -> seq (bf16 hi/lo out) ----------------
__global__ __launch_bounds__(256) void k_seq2(
        const float* __restrict__ hcw, const float* __restrict__ hcb,
        const float* __restrict__ cw,  const float* __restrict__ cb) {
    __shared__ float sh_h[336*16];
    __shared__ float sh_w[16*64];
    __shared__ float sh_hv[336];
    __shared__ float sh_cw[64], sh_cb[8], sh_hcb[64];
    const int n = blockIdx.x, tid = threadIdx.x;
    const float4* hsrc = (const float4*)(g_h + (size_t)n*5376);
    const float* dsrc = g_D + n*336;
    for (int i = tid; i < 1344; i += 256) {
        float d = dsrc[i >> 2];
        float4 v = hsrc[i];
        v.x *= d; v.y *= d; v.z *= d; v.w *= d;
        *(float4*)(sh_h + 4*i) = v;
    }
    for (int i = tid; i < 1024; i += 256) {
        int co = i & 63, ci = i >> 6;
        sh_w[ci*64 + co] = hcw[co*16 + ci];
    }
    if (tid < 64) { sh_cw[tid] = cw[tid]; sh_hcb[tid] = hcb[tid]; }
    if (tid < 8)  sh_cb[tid] = cb[tid];

    for (int w = 0; w < 8; w++) {
        __syncthreads();
        for (int inner = tid; inner < 336; inner += 256) {
            int nodeL = w*42 + (inner >> 6);
            int c = inner & 63;
            const float* hr = sh_h + nodeL*16;
            float acc = sh_hcb[c];
            #pragma unroll
            for (int j = 0; j < 16; j++) acc += hr[j] * sh_w[j*64 + c];
            sh_hv[inner] = acc;
        }
        __syncthreads();
        for (int p = tid; p < 336; p += 256) {
            int o = p / 42, vm = p % 42;
            float acc = sh_cb[o];
            #pragma unroll
            for (int t = 0; t < 8; t++) acc += sh_cw[o*8 + t] * sh_hv[t*42 + vm];
            split_store(acc, g_seqh, g_seql, (size_t)(n*8 + o)*336 + w*42 + vm);
        }
    }
}

// ---------------- weight folding ----------------
__global__ void k_cw(const float* __restrict__ W1, const float* __restrict__ wq,
                     float* __restrict__ Wc) {
    int i = blockIdx.x*blockDim.x + threadIdx.x;
    if (i >= EMB*EMB) return;
    int o = i / EMB, ii = i % EMB;
    float acc = 0.f;
    for (int m = 0; m < EMB; m++) acc += W1[o*EMB + m] * wq[m*EMB + ii];
    Wc[i] = acc;
}

__global__ void k_cb(const float* __restrict__ W1, const float* __restrict__ b1,
                     const float* __restrict__ bq, float* __restrict__ bc) {
    int o = blockIdx.x*blockDim.x + threadIdx.x;
    if (o >= EMB) return;
    float acc = b1[o];
    for (int m = 0; m < EMB; m++) acc += W1[o*EMB + m] * bq[m];
    bc[o] = acc;
}

// ---------------- fp32 -> bf16 hi/lo (weights) ----------------
__global__ void k_prep(const float* __restrict__ src,
                       __nv_bfloat16* __restrict__ hi, __nv_bfloat16* __restrict__ lo,
                       int total_rows, int rows_src) {
    int i = blockIdx.x*blockDim.x + threadIdx.x;
    if (i >= total_rows*KDIM) return;
    int r = i / KDIM;
    float v = (r < rows_src) ? src[i] : 0.f;
    __nv_bfloat16 h = __float2bfloat16(v);
    hi[i] = h;
    lo[i] = __float2bfloat16(v - __bfloat162float(h));
}

// ---------------- mma.sync bf16 hi/lo GEMM, cp.async 3-stage ----------------
#define STG3     3
#define BUFB     6144
#define ARRB     (STG3*BUFB)
#define SMEM_DYN (4*ARRB + 4096 + 256)

template<int MODE>
__global__ __launch_bounds__(256) void k_gemm_mma(
        const __nv_bfloat16* __restrict__ Ah, const __nv_bfloat16* __restrict__ Al,
        const __nv_bfloat16* __restrict__ Bh, const __nv_bfloat16* __restrict__ Bl,
        const float* __restrict__ bias, float* __restrict__ C,
        __nv_bfloat16* __restrict__ Oh, __nv_bfloat16* __restrict__ Ol, int Nn,
        const float* __restrict__ pw, const float* __restrict__ pb) {
    extern __shared__ __align__(16) char dsm[];
    float* s_pw = (float*)(dsm + 4*ARRB);
    float* s_pb = s_pw + 1024;

    const int tid = threadIdx.x, lane = tid & 31, wid = tid >> 5;
    const int warpM = wid & 1, warpN = wid >> 1;
    const int row0 = blockIdx.y << 7, col0 = blockIdx.x << 7;

    if (MODE == 1) {
        for (int i = tid; i < 1024; i += 256) {
            int c = i >> 6, co = i & 63;
            s_pw[i] = pw[co*16 + c];
        }
        if (tid < 64) s_pb[tid] = pb[tid];
    }

    const int lrow = tid >> 1, lhalf = tid & 1;
    const __nv_bfloat16* gAh = Ah + (size_t)(row0 + lrow)*KDIM + lhalf*8;
    const __nv_bfloat16* gAl = Al + (size_t)(row0 + lrow)*KDIM + lhalf*8;
    const __nv_bfloat16* gBh = Bh + (size_t)(col0 + lrow)*KDIM + lhalf*8;
    const __nv_bfloat16* gBl = Bl + (size_t)(col0 + lrow)*KDIM + lhalf*8;
    const unsigned sb = smem_u32(dsm);
    const int so = lrow*48 + lhalf*16;

    const int rsubA = (lane & 7) + ((lane >> 3) & 1)*8;
    const int cA = (warpM*64 + rsubA)*48 + ((lane >> 4) & 1)*16;
    const int rsubB = (lane & 7) + ((lane >> 4) & 1)*8;
    const int cB = (warpN*32 + rsubB)*48 + ((lane >> 3) & 1)*16;

    float acc[4][4][4];
    #pragma unroll
    for (int i = 0; i < 4; i++)
        #pragma unroll
        for (int j = 0; j < 4; j++)
            #pragma unroll
            for (int q = 0; q < 4; q++) acc[i][j][q] = 0.f;

    #pragma unroll
    for (int st = 0; st < 2; st++) {
        unsigned d = sb + st*BUFB + so;
        cpa16(d,          gAh + st*16);
        cpa16(d + ARRB,   gAl + st*16);
        cpa16(d + 2*ARRB, gBh + st*16);
        cpa16(d + 3*ARRB, gBl + st*16);
        asm volatile("cp.async.commit_group;");
    }

    #pragma unroll 1
    for (int ch = 0; ch < NSTEP; ch++) {
        if (ch == NSTEP-1) asm volatile("cp.async.wait_group 0;");
        else               asm volatile("cp.async.wait_group 1;");
        __syncthreads();
        if (ch + 2 < NSTEP) {
            unsigned d = sb + ((ch+2)%3)*BUFB + so;
            cpa16(d,          gAh + (ch+2)*16);
            cpa16(d + ARRB,   gAl + (ch+2)*16);
            cpa16(d + 2*ARRB, gBh + (ch+2)*16);
            cpa16(d + 3*ARRB, gBl + (ch+2)*16);
            asm volatile("cp.async.commit_group;");
        }
        const unsigned bo = sb + (ch%3)*BUFB;
        unsigned AH[4][4], AL[4][4];
        #pragma unroll
        for (int mt = 0; mt < 4; mt++) {
            ldm4(AH[mt], bo + cA + mt*768);
            ldm4(AL[mt], bo + ARRB + cA + mt*768);
        }
        #pragma unroll
        for (int p = 0; p < 2; p++) {
            unsigned BH[4], BL[4];
            ldm4(BH, bo + 2*ARRB + cB + p*768);
            ldm4(BL, bo + 3*ARRB + cB + p*768);
            #pragma unroll
            for (int mt = 0; mt < 4; mt++) {
                #pragma unroll
                for (int q = 0; q < 2; q++) {
                    float* ac = acc[mt][2*p + q];
                    mma16816(ac, AH[mt], BH + 2*q);
                    mma16816(ac, AH[mt], BL + 2*q);
                    mma16816(ac, AL[mt], BH + 2*q);
                }
            }
        }
    }

    if (MODE == 0) {
        #pragma unroll
        for (int mt = 0; mt < 4; mt++) {
            int r1 = row0 + warpM*64 + mt*16 + (lane >> 2);
            #pragma unroll
            for (int nt = 0; nt < 4; nt++) {
                int gc = col0 + warpN*32 + nt*8 + (lane & 3)*2;
                if (gc < Nn) {
                    float b0 = __ldg(bias + gc), b1 = __ldg(bias + gc + 1);
                    float* ac = acc[mt][nt];
                    *(float2*)(C + (size_t)r1*Nn + gc)     = make_float2(ac[0]+b0, ac[1]+b1);
                    *(float2*)(C + (size_t)(r1+8)*Nn + gc) = make_float2(ac[2]+b0, ac[3]+b1);
                }
            }
        }
    } else if (MODE == 2) {
        #pragma unroll
        for (int mt = 0; mt < 4; mt++) {
            int r1 = row0 + warpM*64 + mt*16 + (lane >> 2);
            #pragma unroll
            for (int nt = 0; nt < 4; nt++) {
                int gc = col0 + warpN*32 + nt*8 + (lane & 3)*2;
                if (gc < Nn) {
                    float b0 = __ldg(bias + gc), b1 = __ldg(bias + gc + 1);
                    float* ac = acc[mt][nt];
                    size_t o0 = (size_t)r1*KDIM + gc;
                    size_t o1 = (size_t)(r1+8)*KDIM + gc;
                    split_store(ac[0]+b0, Oh, Ol, o0);
                    split_store(ac[1]+b1, Oh, Ol, o0+1);
                    split_store(ac[2]+b0, Oh, Ol, o1);
                    split_store(ac[3]+b1, Oh, Ol, o1+1);
                }
            }
        }
    } else {
        __syncthreads();
        float* xs = (float*)dsm;
        const int v0 = col0 >> 6;
        for (int i = tid; i < 4096; i += 256) {
            int vml = i >> 11, r = (i >> 4) & 127, c = i & 15;
            xs[vml*2176 + r*17 + c] = g_xb[((size_t)(row0 + r)*42 + v0 + vml)*16 + c];
        }
        __syncthreads();

        const int vml = warpN >> 1;
        #pragma unroll
        for (int mt = 0; mt < 4; mt++) {
            int rl1 = warpM*64 + mt*16 + (lane >> 2);
            int rl2 = rl1 + 8;
            float xa[16], xc2[16];
            #pragma unroll
            for (int c = 0; c < 16; c++) {
                xa[c]  = xs[vml*2176 + rl1*17 + c];
                xc2[c] = xs[vml*2176 + rl2*17 + c];
            }
            #pragma unroll
            for (int nt = 0; nt < 4; nt++) {
                int co = (warpN & 1)*32 + nt*8 + (lane & 3)*2;
                int gc = col0 + (warpN & 1)*32 + (vml ? 64 : 0) + nt*8 + (lane & 3)*2;
                float fb0 = __ldg(bias + gc) + s_pb[co];
                float fb1 = __ldg(bias + gc + 1) + s_pb[co + 1];
                unsigned long long rv1 = pack2(fb0, fb1);
                unsigned long long rv2 = rv1;
                #pragma unroll
                for (int c = 0; c < 16; c++) {
                    unsigned long long w2 = *(const unsigned long long*)&s_pw[c*64 + co];
                    rv1 = ffma2(pack2(xa[c],  xa[c]),  w2, rv1);
                    rv2 = ffma2(pack2(xc2[c], xc2[c]), w2, rv2);
                }
                float2 u1 = unpack2(rv1), u2 = unpack2(rv2);
                float* ac = acc[mt][nt];
                int r1 = row0 + rl1, r2 = row0 + rl2;
                *(float2*)(C + (size_t)r1*2688 + gc) =
                    make_float2(fmaxf(ac[0]+u1.x, 0.f), fmaxf(ac[1]+u1.y, 0.f));
                *(float2*)(C + (size_t)r2*2688 + gc) =
                    make_float2(fmaxf(ac[2]+u2.x, 0.f), fmaxf(ac[3]+u2.y, 0.f));
            }
        }
    }
}

// ---------------- attention ----------------
__global__ __launch_bounds__(256) void k_attn2() {
    __shared__ float sq[8*1012];
    __shared__ float sc[256], at[256];
    const int n = blockIdx.x, tid = threadIdx.x;
    const float* src = g_qkv + (size_t)n*8064;
    for (int i = tid; i < 8064; i += 256) {
        int r = i / 1008, c = i - r*1008;
        sq[r*1012 + c] = src[i];
    }
    __syncthreads();
    const int h = tid >> 6, s = (tid >> 3) & 7, t = tid & 7;
    {
        const float* qr = sq + s*1012 + h*84;
        const float* kr = sq + t*1012 + 336 + h*84;
        float acc = 0.f;
        #pragma unroll 12
        for (int d = 0; d < 84; d++) acc += qr[d]*kr[d];
        sc[tid] = acc * 0.1091089451179961805f;
    }
    __syncthreads();
    const int rb = tid & ~7;
    float mx = sc[rb];
    #pragma unroll
    for (int k = 1; k < 8; k++) mx = fmaxf(mx, sc[rb + k]);
    float e = expf(sc[tid] - mx);
    at[tid] = e;
    __syncthreads();
    float sum = 0.f;
    #pragma unroll
    for (int k = 0; k < 8; k++) sum += at[rb + k];
    float a = e / sum;
    __syncthreads();
    at[tid] = a;
    __syncthreads();
    for (int idx = tid; idx < 2688; idx += 256) {
        int s2 = idx / 336, c = idx - s2*336;
        int hh = c / 84, d = c - hh*84;
        const float* vr = sq + 672 + hh*84 + d;
        const float* ar = at + hh*64 + s2*8;
        float o = 0.f;
        #pragma unroll
        for (int k = 0; k < 8; k++) o += ar[k] * vr[k*1012];
        split_store(o, g_aoh, g_aol, (size_t)(n*8 + s2)*336 + c);
    }
}

// ---------------- launcher ----------------
extern "C" void kernel_launch(void* const* d_in, const int* in_sizes, int n_in,
                              void* d_out, int out_size) {
    const float* x   = (const float*)d_in[0];
    const int*   hi  = (const int*)  d_in[1];
    const float* hcw = (const float*)d_in[2];
    const float* hcb = (const float*)d_in[3];
    const float* cw  = (const float*)d_in[4];
    const float* cb  = (const float*)d_in[5];
    const float* gam = (const float*)d_in[6];
    const float* bet = (const float*)d_in[7];
    const float* pw  = (const float*)d_in[8];
    const float* pb  = (const float*)d_in[9];
    const float* wq  = (const float*)d_in[10];
    const float* bq  = (const float*)d_in[11];
    const float* wk  = (const float*)d_in[12];
    const float* bk  = (const float*)d_in[13];
    const float* wv  = (const float*)d_in[14];
    const float* bv  = (const float*)d_in[15];
    const float* ipw = (const float*)d_in[16];
    const float* ipb = (const float*)d_in[17];
    const float* opw = (const float*)d_in[18];
    const float* opb = (const float*)d_in[19];
    const float* fw  = (const float*)d_in[20];
    const float* fb  = (const float*)d_in[21];
    float* out = (float*)d_out;

    float *p_qkv, *p_Wc, *p_bc;
    cudaGetSymbolAddress((void**)&p_qkv, g_qkv);
    cudaGetSymbolAddress((void**)&p_Wc,  g_Wc);
    cudaGetSymbolAddress((void**)&p_bc,  g_bc);
    __nv_bfloat16 *p_seqh,*p_seql,*p_aoh,*p_aol,*p_o2h,*p_o2l,*p_wch,*p_wcl,*p_oph,*p_opl,*p_fwh,*p_fwl;
    cudaGetSymbolAddress((void**)&p_seqh, g_seqh); cudaGetSymbolAddress((void**)&p_seql, g_seql);
    cudaGetSymbolAddress((void**)&p_aoh,  g_aoh);  cudaGetSymbolAddress((void**)&p_aol,  g_aol);
    cudaGetSymbolAddress((void**)&p_o2h,  g_o2h);  cudaGetSymbolAddress((void**)&p_o2l,  g_o2l);
    cudaGetSymbolAddress((void**)&p_wch,  g_wch);  cudaGetSymbolAddress((void**)&p_wcl,  g_wcl);
    cudaGetSymbolAddress((void**)&p_oph,  g_oph);  cudaGetSymbolAddress((void**)&p_opl,  g_opl);
    cudaGetSymbolAddress((void**)&p_fwh,  g_fwh);  cudaGetSymbolAddress((void**)&p_fwl,  g_fwl);

    cudaFuncSetAttribute(k_gemm_mma<0>, cudaFuncAttributeMaxDynamicSharedMemorySize, SMEM_DYN);
    cudaFuncSetAttribute(k_gemm_mma<1>, cudaFuncAttributeMaxDynamicSharedMemorySize, SMEM_DYN);
    cudaFuncSetAttribute(k_gemm_mma<2>, cudaFuncAttributeMaxDynamicSharedMemorySize, SMEM_DYN);

    // CSR hypergraph path
    k_zero_small<<<(NNODE + 255)/256, 256>>>();
    k_stage<<<NB, 256>>>(x);
    k_count<<<(EINC + 255)/256, 256>>>(hi);
    k_scanA<<<dim3(NBLK, 2), 512>>>();
    k_scanB<<<2, 512>>>();
    k_scanC<<<dim3(NBLK, 2), 512>>>();
    k_place<<<(EINC + 255)/256, 256>>>(hi);
    k_inv2<<<(NNODE + 255)/256, 256>>>();
    k_gather_e<<<(NNODE*4 + 255)/256, 256>>>();
    k_gather_h<<<(NNODE*4 + 255)/256, 256>>>();

    // BN
    k_bnstats<<<NB*CIN, 128>>>(x);
    k_bnfin<<<1, 32>>>(gam, bet);
    k_bnxlin<<<(NN16 + 255)/256, 256>>>();

    k_seq2<<<NB, 256>>>(hcw, hcb, cw, cb);

    // weight folding + bf16 prep (weights only)
    k_cw<<<(EMB*EMB + 255)/256, 256>>>(ipw,             wq, p_Wc);
    k_cw<<<(EMB*EMB + 255)/256, 256>>>(ipw +   EMB*EMB, wk, p_Wc +   EMB*EMB);
    k_cw<<<(EMB*EMB + 255)/256, 256>>>(ipw + 2*EMB*EMB, wv, p_Wc + 2*EMB*EMB);
    k_cb<<<2, 256>>>(ipw,             ipb,         bq, p_bc);
    k_cb<<<2, 256>>>(ipw +   EMB*EMB, ipb +   EMB, bk, p_bc + EMB);
    k_cb<<<2, 256>>>(ipw + 2*EMB*EMB, ipb + 2*EMB, bv, p_bc + 2*EMB);
    k_prep<<<(1024*KDIM + 255)/256, 256>>>(p_Wc, p_wch, p_wcl, 1024, 1008);
    k_prep<<<(384*KDIM + 255)/256, 256>>>(opw, p_oph, p_opl, 384, 336);
    k_prep<<<(2688*KDIM + 255)/256, 256>>>(fw, p_fwh, p_fwl, 2688, 2688);

    // GEMMs + attention
    k_gemm_mma<0><<<dim3(8, ROWS/128), 256, SMEM_DYN>>>(
        p_seqh, p_seql, p_wch, p_wcl, p_bc, p_qkv, nullptr, nullptr, 1008, nullptr, nullptr);
    k_attn2<<<NB, 256>>>();
    k_gemm_mma<2><<<dim3(3, ROWS/128), 256, SMEM_DYN>>>(
        p_aoh, p_aol, p_oph, p_opl, opb, nullptr, p_o2h, p_o2l, 336, nullptr, nullptr);
    k_gemm_mma<1><<<dim3(21, ROWS/128), 256, SMEM_DYN>>>(
        p_o2h, p_o2l, p_fwh, p_fwl, fb, out, nullptr, nullptr, 2688, pw, pb);
}

// round 8
// speedup vs baseline: 1.1566x; 1.1566x over previous
#include <cuda_runtime.h>
#include <cuda_bf16.h>
#include <math.h>

#define NB    2048
#define CIN   16
#define VMD   42
#define NNODE (NB*8*VMD)            // 688128
#define EINC  (4*NNODE)             // 2752512
#define EMB   336
#define ROWS  (NB*8)                // 16384
#define KDIM  336
#define NSTEP 21
#define NN16  (NNODE*16)

// ---------------- scratch ----------------
__device__ __align__(16) float  g_xn[NN16];
__device__ __align__(16) float  g_xb[NN16];
__device__ __align__(16) float  g_e [NN16];
__device__ __align__(16) float  g_h [NN16];
__device__ __align__(16) float  g_D [NNODE];
__device__ __align__(16) float  g_B [NNODE];
__device__ __align__(16) float  g_qkv[ROWS*3*EMB];
__device__ __align__(16) float  g_Wc [3*EMB*EMB];
__device__ __align__(16) float  g_bc [3*EMB];
__device__ double g_sum[CIN], g_sum2[CIN];
__device__ float  g_scale[CIN], g_shift[CIN];
// bf16 staging: activations hi+lo, weights hi only
__device__ __align__(16) __nv_bfloat16 g_seqh[ROWS*KDIM], g_seql[ROWS*KDIM];
__device__ __align__(16) __nv_bfloat16 g_aoh [ROWS*KDIM], g_aol [ROWS*KDIM];
__device__ __align__(16) __nv_bfloat16 g_o2h [ROWS*KDIM], g_o2l [ROWS*KDIM];
__device__ __align__(16) __nv_bfloat16 g_wch [1024*KDIM];
__device__ __align__(16) __nv_bfloat16 g_oph [384*KDIM];
__device__ __align__(16) __nv_bfloat16 g_fwh [2688*KDIM];

// ---------------- helpers ----------------
__device__ __forceinline__ unsigned smem_u32(const void* p) {
    unsigned a;
    asm("{ .reg .u64 t; cvta.to.shared.u64 t, %1; cvt.u32.u64 %0, t; }" : "=r"(a) : "l"(p));
    return a;
}
__device__ __forceinline__ void ldm4(unsigned* r, unsigned addr) {
    asm volatile("ldmatrix.sync.aligned.m8n8.x4.shared.b16 {%0,%1,%2,%3}, [%4];"
        : "=r"(r[0]), "=r"(r[1]), "=r"(r[2]), "=r"(r[3]) : "r"(addr));
}
__device__ __forceinline__ void mma16816(float* d, const unsigned* a, const unsigned* b) {
    asm volatile("mma.sync.aligned.m16n8k16.row.col.f32.bf16.bf16.f32 "
        "{%0,%1,%2,%3}, {%4,%5,%6,%7}, {%8,%9}, {%0,%1,%2,%3};"
        : "+f"(d[0]), "+f"(d[1]), "+f"(d[2]), "+f"(d[3])
        : "r"(a[0]), "r"(a[1]), "r"(a[2]), "r"(a[3]), "r"(b[0]), "r"(b[1]));
}
__device__ __forceinline__ void cpa16(unsigned dst, const void* src) {
    asm volatile("cp.async.cg.shared.global [%0], [%1], 16;" :: "r"(dst), "l"(src));
}
__device__ __forceinline__ unsigned long long ffma2(unsigned long long a,
                                                    unsigned long long b,
                                                    unsigned long long c) {
    unsigned long long d;
    asm("fma.rn.f32x2 %0, %1, %2, %3;" : "=l"(d) : "l"(a), "l"(b), "l"(c));
    return d;
}
__device__ __forceinline__ unsigned long long pack2(float x, float y) {
    unsigned long long d;
    asm("mov.b64 %0, {%1, %2};" : "=l"(d) : "f"(x), "f"(y));
    return d;
}
__device__ __forceinline__ float2 unpack2(unsigned long long v) {
    float2 r;
    asm("mov.b64 {%0, %1}, %2;" : "=f"(r.x), "=f"(r.y) : "l"(v));
    return r;
}
__device__ __forceinline__ void split_store(float v, __nv_bfloat16* hi, __nv_bfloat16* lo,
                                            size_t off) {
    __nv_bfloat16 h = __float2bfloat16(v);
    hi[off] = h;
    lo[off] = __float2bfloat16(v - __bfloat162float(h));
}

// ---------------- init ----------------
__global__ void k_zero() {
    int i = blockIdx.x*blockDim.x + threadIdx.x;
    float4 z = make_float4(0.f,0.f,0.f,0.f);
    if (i < NN16/4) { ((float4*)g_e)[i] = z; ((float4*)g_h)[i] = z; }
    if (i < NNODE) { g_D[i] = 0.f; g_B[i] = 0.f; }
    if (i < CIN) { g_sum[i] = 0.0; g_sum2[i] = 0.0; }
}

// ---------------- BatchNorm ----------------
__global__ void k_bnstats(const float* __restrict__ x) {
    __shared__ double sh[128], sh2[128];
    int b = blockIdx.x;
    const float* p = x + b*336;
    double s = 0.0, s2 = 0.0;
    for (int i = threadIdx.x; i < 336; i += 128) { double v = p[i]; s += v; s2 += v*v; }
    sh[threadIdx.x] = s; sh2[threadIdx.x] = s2; __syncthreads();
    for (int o = 64; o > 0; o >>= 1) {
        if (threadIdx.x < o) { sh[threadIdx.x] += sh[threadIdx.x+o]; sh2[threadIdx.x] += sh2[threadIdx.x+o]; }
        __syncthreads();
    }
    if (threadIdx.x == 0) {
        int c = b & 15;
        atomicAdd(&g_sum[c], sh[0]);
        atomicAdd(&g_sum2[c], sh2[0]);
    }
}

__global__ void k_bnfin(const float* __restrict__ gamma, const float* __restrict__ beta) {
    int c = threadIdx.x;
    if (c >= CIN) return;
    double cnt = (double)NNODE;
    double mean = g_sum[c] / cnt;
    double var  = g_sum2[c] / cnt - mean*mean;
    float sc = gamma[c] * rsqrtf((float)var + 1e-5f);
    g_scale[c] = sc;
    g_shift[c] = beta[c] - (float)mean * sc;
}

__global__ void k_bnx2(const float* __restrict__ x) {
    __shared__ float sx[16*337];
    const int n = blockIdx.x, tid = threadIdx.x;
    const float* xp = x + (size_t)n*5376;
    for (int i = tid; i < 5376; i += 256) {
        int c = i / 336, rem = i % 336;
        sx[c*337 + rem] = xp[i];
    }
    __syncthreads();
    const size_t base = (size_t)n*5376;
    for (int i = tid; i < 5376; i += 256) {
        int rem = i >> 4, c = i & 15;
        float v = sx[c*337 + rem];
        g_xn[base + i] = v;
        g_xb[base + i] = v * g_scale[c] + g_shift[c];
    }
}

// ---------------- hypergraph ----------------
__global__ void k_deg(const int* __restrict__ hi) {
    int i = blockIdx.x*blockDim.x + threadIdx.x;
    if (i >= EINC) return;
    atomicAdd(&g_D[hi[i]], 1.f);
    atomicAdd(&g_B[hi[EINC + i]], 1.f);
}

__global__ void k_inv() {
    int i = blockIdx.x*blockDim.x + threadIdx.x;
    if (i >= NNODE) return;
    float d = g_D[i]; g_D[i] = (d > 0.f) ? (1.f/d) : 0.f;
    float b = g_B[i]; g_B[i] = (b > 0.f) ? (1.f/b) : 0.f;
}

__global__ void k_scatter_e(const int* __restrict__ hi) {
    unsigned gi = blockIdx.x*blockDim.x + threadIdx.x;
    if (gi >= (unsigned)EINC * 4u) return;
    int i = (int)(gi >> 2), g = (int)((gi & 3u) << 2);
    int node = __ldg(&hi[i]), edge = __ldg(&hi[EINC + i]);
    float4 v = *(const float4*)(g_xn + (size_t)node*16 + g);
    float* dst = g_e + (size_t)edge*16 + g;
    asm volatile("red.global.add.v4.f32 [%0], {%1, %2, %3, %4};"
                 :: "l"(dst), "f"(v.x), "f"(v.y), "f"(v.z), "f"(v.w) : "memory");
}

__global__ void k_scatter_h(const int* __restrict__ hi) {
    unsigned gi = blockIdx.x*blockDim.x + threadIdx.x;
    if (gi >= (unsigned)EINC * 4u) return;
    int i = (int)(gi >> 2), g = (int)((gi & 3u) << 2);
    int node = __ldg(&hi[i]), edge = __ldg(&hi[EINC + i]);
    float w = g_B[edge];
    float4 v = *(const float4*)(g_e + (size_t)edge*16 + g);
    v.x *= w; v.y *= w; v.z *= w; v.w *= w;
    float* dst = g_h + (size_t)node*16 + g;
    asm volatile("red.global.add.v4.f32 [%0], {%1, %2, %3, %4};"
                 :: "l"(dst), "f"(v.x), "f"(v.y), "f"(v.z), "f"(v.w) : "memory");
}

// ---------------- fused hconv + time-conv -> seq (bf16 hi/lo out) ----------------
__global__ __launch_bounds__(256) void k_seq2(
        const float* __restrict__ hcw, const float* __restrict__ hcb,
        const float* __restrict__ cw,  const float* __restrict__ cb) {
    __shared__ float sh_h[336*16];
    __shared__ float sh_w[16*64];
    __shared__ float sh_hv[336];
    __shared__ float sh_cw[64], sh_cb[8], sh_hcb[64];
    const int n = blockIdx.x, tid = threadIdx.x;
    const float4* hsrc = (const float4*)(g_h + (size_t)n*5376);
    const float* dsrc = g_D + n*336;
    for (int i = tid; i < 1344; i += 256) {
        float d = dsrc[i >> 2];
        float4 v = hsrc[i];
        v.x *= d; v.y *= d; v.z *= d; v.w *= d;
        *(float4*)(sh_h + 4*i) = v;
    }
    for (int i = tid; i < 1024; i += 256) {
        int co = i & 63, ci = i >> 6;
        sh_w[ci*64 + co] = hcw[co*16 + ci];
    }
    if (tid < 64) { sh_cw[tid] = cw[tid]; sh_hcb[tid] = hcb[tid]; }
    if (tid < 8)  sh_cb[tid] = cb[tid];

    for (int w = 0; w < 8; w++) {
        __syncthreads();
        for (int inner = tid; inner < 336; inner += 256) {
            int nodeL = w*42 + (inner >> 6);
            int c = inner & 63;
            const float* hr = sh_h + nodeL*16;
            float acc = sh_hcb[c];
            #pragma unroll
            for (int j = 0; j < 16; j++) acc += hr[j] * sh_w[j*64 + c];
            sh_hv[inner] = acc;
        }
        __syncthreads();
        for (int p = tid; p < 336; p += 256) {
            int o = p / 42, vm = p % 42;
            float acc = sh_cb[o];
            #pragma unroll
            for (int t = 0; t < 8; t++) acc += sh_cw[o*8 + t] * sh_hv[t*42 + vm];
            split_store(acc, g_seqh, g_seql, (size_t)(n*8 + o)*336 + w*42 + vm);
        }
    }
}

// ---------------- weight folding ----------------
__global__ void k_cw(const float* __restrict__ W1, const float* __restrict__ wq,
                     float* __restrict__ Wc) {
    int i = blockIdx.x*blockDim.x + threadIdx.x;
    if (i >= EMB*EMB) return;
    int o = i / EMB, ii = i % EMB;
    float acc = 0.f;
    for (int m = 0; m < EMB; m++) acc += W1[o*EMB + m] * wq[m*EMB + ii];
    Wc[i] = acc;
}

__global__ void k_cb(const float* __restrict__ W1, const float* __restrict__ b1,
                     const float* __restrict__ bq, float* __restrict__ bc) {
    int o = blockIdx.x*blockDim.x + threadIdx.x;
    if (o >= EMB) return;
    float acc = b1[o];
    for (int m = 0; m < EMB; m++) acc += W1[o*EMB + m] * bq[m];
    bc[o] = acc;
}

// ---------------- fp32 -> bf16 (weights, hi only) ----------------
__global__ void k_preph(const float* __restrict__ src, __nv_bfloat16* __restrict__ hi,
                        int total_rows, int rows_src) {
    int i = blockIdx.x*blockDim.x + threadIdx.x;
    if (i >= total_rows*KDIM) return;
    int r = i / KDIM;
    float v = (r < rows_src) ? src[i] : 0.f;
    hi[i] = __float2bfloat16(v);
}

// ---------------- mma.sync GEMM: C = (Ah+Al)·Bh^T + bias ----------------
// MODE 0: fp32 C + bias.  MODE 1: fc fused residual+relu.  MODE 2: bf16 hi/lo out.
#define STG3     3
#define BUFB     6144
#define ARRB     (STG3*BUFB)
#define SMEM_DYN (3*ARRB + 4096 + 256)

template<int MODE>
__global__ __launch_bounds__(256) void k_gemm_mma(
        const __nv_bfloat16* __restrict__ Ah, const __nv_bfloat16* __restrict__ Al,
        const __nv_bfloat16* __restrict__ Bh,
        const float* __restrict__ bias, float* __restrict__ C,
        __nv_bfloat16* __restrict__ Oh, __nv_bfloat16* __restrict__ Ol, int Nn,
        const float* __restrict__ pw, const float* __restrict__ pb) {
    extern __shared__ __align__(16) char dsm[];
    float* s_pw = (float*)(dsm + 3*ARRB);
    float* s_pb = s_pw + 1024;

    const int tid = threadIdx.x, lane = tid & 31, wid = tid >> 5;
    const int warpM = wid & 1, warpN = wid >> 1;
    const int row0 = blockIdx.y << 7, col0 = blockIdx.x << 7;

    if (MODE == 1) {
        for (int i = tid; i < 1024; i += 256) {
            int c = i >> 6, co = i & 63;
            s_pw[i] = pw[co*16 + c];
        }
        if (tid < 64) s_pb[tid] = pb[tid];
    }

    const int lrow = tid >> 1, lhalf = tid & 1;
    const __nv_bfloat16* gAh = Ah + (size_t)(row0 + lrow)*KDIM + lhalf*8;
    const __nv_bfloat16* gAl = Al + (size_t)(row0 + lrow)*KDIM + lhalf*8;
    const __nv_bfloat16* gBh = Bh + (size_t)(col0 + lrow)*KDIM + lhalf*8;
    const unsigned sb = smem_u32(dsm);
    const int so = lrow*48 + lhalf*16;

    const int rsubA = (lane & 7) + ((lane >> 3) & 1)*8;
    const int cA = (warpM*64 + rsubA)*48 + ((lane >> 4) & 1)*16;
    const int rsubB = (lane & 7) + ((lane >> 4) & 1)*8;
    const int cB = (warpN*32 + rsubB)*48 + ((lane >> 3) & 1)*16;

    float acc[4][4][4];
    #pragma unroll
    for (int i = 0; i < 4; i++)
        #pragma unroll
        for (int j = 0; j < 4; j++)
            #pragma unroll
            for (int q = 0; q < 4; q++) acc[i][j][q] = 0.f;

    #pragma unroll
    for (int st = 0; st < 2; st++) {
        unsigned d = sb + st*BUFB + so;
        cpa16(d,          gAh + st*16);
        cpa16(d + ARRB,   gAl + st*16);
        cpa16(d + 2*ARRB, gBh + st*16);
        asm volatile("cp.async.commit_group;");
    }

    #pragma unroll 1
    for (int ch = 0; ch < NSTEP; ch++) {
        if (ch == NSTEP-1) asm volatile("cp.async.wait_group 0;");
        else               asm volatile("cp.async.wait_group 1;");
        __syncthreads();
        if (ch + 2 < NSTEP) {
            unsigned d = sb + ((ch+2)%3)*BUFB + so;
            cpa16(d,          gAh + (ch+2)*16);
            cpa16(d + ARRB,   gAl + (ch+2)*16);
            cpa16(d + 2*ARRB, gBh + (ch+2)*16);
            asm volatile("cp.async.commit_group;");
        }
        const unsigned bo = sb + (ch%3)*BUFB;
        unsigned AH[4][4], AL[4][4];
        #pragma unroll
        for (int mt = 0; mt < 4; mt++) {
            ldm4(AH[mt], bo + cA + mt*768);
            ldm4(AL[mt], bo + ARRB + cA + mt*768);
        }
        #pragma unroll
        for (int p = 0; p < 2; p++) {
            unsigned BH[4];
            ldm4(BH, bo + 2*ARRB + cB + p*768);
            #pragma unroll
            for (int mt = 0; mt < 4; mt++) {
                #pragma unroll
                for (int q = 0; q < 2; q++) {
                    float* ac = acc[mt][2*p + q];
                    mma16816(ac, AH[mt], BH + 2*q);
                    mma16816(ac, AL[mt], BH + 2*q);
                }
            }
        }
    }

    if (MODE == 0) {
        #pragma unroll
        for (int mt = 0; mt < 4; mt++) {
            int r1 = row0 + warpM*64 + mt*16 + (lane >> 2);
            #pragma unroll
            for (int nt = 0; nt < 4; nt++) {
                int gc = col0 + warpN*32 + nt*8 + (lane & 3)*2;
                if (gc < Nn) {
                    float b0 = __ldg(bias + gc), b1 = __ldg(bias + gc + 1);
                    float* ac = acc[mt][nt];
                    *(float2*)(C + (size_t)r1*Nn + gc)     = make_float2(ac[0]+b0, ac[1]+b1);
                    *(float2*)(C + (size_t)(r1+8)*Nn + gc) = make_float2(ac[2]+b0, ac[3]+b1);
                }
            }
        }
    } else if (MODE == 2) {
        #pragma unroll
        for (int mt = 0; mt < 4; mt++) {
            int r1 = row0 + warpM*64 + mt*16 + (lane >> 2);
            #pragma unroll
            for (int nt = 0; nt < 4; nt++) {
                int gc = col0 + warpN*32 + nt*8 + (lane & 3)*2;
                if (gc < Nn) {
                    float b0 = __ldg(bias + gc), b1 = __ldg(bias + gc + 1);
                    float* ac = acc[mt][nt];
                    size_t o0 = (size_t)r1*KDIM + gc;
                    size_t o1 = (size_t)(r1+8)*KDIM + gc;
                    split_store(ac[0]+b0, Oh, Ol, o0);
                    split_store(ac[1]+b1, Oh, Ol, o0+1);
                    split_store(ac[2]+b0, Oh, Ol, o1);
                    split_store(ac[3]+b1, Oh, Ol, o1+1);
                }
            }
        }
    } else {
        __syncthreads();
        float* xs = (float*)dsm;
        const int v0 = col0 >> 6;
        for (int i = tid; i < 4096; i += 256) {
            int vml = i >> 11, r = (i >> 4) & 127, c = i & 15;
            xs[vml*2176 + r*17 + c] = g_xb[((size_t)(row0 + r)*42 + v0 + vml)*16 + c];
        }
        __syncthreads();

        const int vml = warpN >> 1;
        #pragma unroll
        for (int mt = 0; mt < 4; mt++) {
            int rl1 = warpM*64 + mt*16 + (lane >> 2);
            int rl2 = rl1 + 8;
            float xa[16], xc2[16];
            #pragma unroll
            for (int c = 0; c < 16; c++) {
                xa[c]  = xs[vml*2176 + rl1*17 + c];
                xc2[c] = xs[vml*2176 + rl2*17 + c];
            }
            #pragma unroll
            for (int nt = 0; nt < 4; nt++) {
                int co = (warpN & 1)*32 + nt*8 + (lane & 3)*2;
                int gc = col0 + (warpN & 1)*32 + (vml ? 64 : 0) + nt*8 + (lane & 3)*2;
                float fb0 = __ldg(bias + gc) + s_pb[co];
                float fb1 = __ldg(bias + gc + 1) + s_pb[co + 1];
                unsigned long long rv1 = pack2(fb0, fb1);
                unsigned long long rv2 = rv1;
                #pragma unroll
                for (int c = 0; c < 16; c++) {
                    unsigned long long w2 = *(const unsigned long long*)&s_pw[c*64 + co];
                    rv1 = ffma2(pack2(xa[c],  xa[c]),  w2, rv1);
                    rv2 = ffma2(pack2(xc2[c], xc2[c]), w2, rv2);
                }
                float2 u1 = unpack2(rv1), u2 = unpack2(rv2);
                float* ac = acc[mt][nt];
                int r1 = row0 + rl1, r2 = row0 + rl2;
                *(float2*)(C + (size_t)r1*2688 + gc) =
                    make_float2(fmaxf(ac[0]+u1.x, 0.f), fmaxf(ac[1]+u1.y, 0.f));
                *(float2*)(C + (size_t)r2*2688 + gc) =
                    make_float2(fmaxf(ac[2]+u2.x, 0.f), fmaxf(ac[3]+u2.y, 0.f));
            }
        }
    }
}

// ---------------- attention ----------------
__global__ __launch_bounds__(256) void k_attn2() {
    __shared__ float sq[8*1012];
    __shared__ float sc[256], at[256];
    const int n = blockIdx.x, tid = threadIdx.x;
    const float* src = g_qkv + (size_t)n*8064;
    for (int i = tid; i < 8064; i += 256) {
        int r = i / 1008, c = i - r*1008;
        sq[r*1012 + c] = src[i];
    }
    __syncthreads();
    const int h = tid >> 6, s = (tid >> 3) & 7, t = tid & 7;
    {
        const float* qr = sq + s*1012 + h*84;
        const float* kr = sq + t*1012 + 336 + h*84;
        float acc = 0.f;
        #pragma unroll 12
        for (int d = 0; d < 84; d++) acc += qr[d]*kr[d];
        sc[tid] = acc * 0.1091089451179961805f;
    }
    __syncthreads();
    const int rb = tid & ~7;
    float mx = sc[rb];
    #pragma unroll
    for (int k = 1; k < 8; k++) mx = fmaxf(mx, sc[rb + k]);
    float e = expf(sc[tid] - mx);
    at[tid] = e;
    __syncthreads();
    float sum = 0.f;
    #pragma unroll
    for (int k = 0; k < 8; k++) sum += at[rb + k];
    float a = e / sum;
    __syncthreads();
    at[tid] = a;
    __syncthreads();
    for (int idx = tid; idx < 2688; idx += 256) {
        int s2 = idx / 336, c = idx - s2*336;
        int hh = c / 84, d = c - hh*84;
        const float* vr = sq + 672 + hh*84 + d;
        const float* ar = at + hh*64 + s2*8;
        float o = 0.f;
        #pragma unroll
        for (int k = 0; k < 8; k++) o += ar[k] * vr[k*1012];
        split_store(o, g_aoh, g_aol, (size_t)(n*8 + s2)*336 + c);
    }
}

// ---------------- launcher ----------------
extern "C" void kernel_launch(void* const* d_in, const int* in_sizes, int n_in,
                              void* d_out, int out_size) {
    const float* x   = (const float*)d_in[0];
    const int*   hi  = (const int*)  d_in[1];
    const float* hcw = (const float*)d_in[2];
    const float* hcb = (const float*)d_in[3];
    const float* cw  = (const float*)d_in[4];
    const float* cb  = (const float*)d_in[5];
    const float* gam = (const float*)d_in[6];
    const float* bet = (const float*)d_in[7];
    const float* pw  = (const float*)d_in[8];
    const float* pb  = (const float*)d_in[9];
    const float* wq  = (const float*)d_in[10];
    const float* bq  = (const float*)d_in[11];
    const float* wk  = (const float*)d_in[12];
    const float* bk  = (const float*)d_in[13];
    const float* wv  = (const float*)d_in[14];
    const float* bv  = (const float*)d_in[15];
    const float* ipw = (const float*)d_in[16];
    const float* ipb = (const float*)d_in[17];
    const float* opw = (const float*)d_in[18];
    const float* opb = (const float*)d_in[19];
    const float* fw  = (const float*)d_in[20];
    const float* fb  = (const float*)d_in[21];
    float* out = (float*)d_out;

    float *p_qkv, *p_Wc, *p_bc;
    cudaGetSymbolAddress((void**)&p_qkv, g_qkv);
    cudaGetSymbolAddress((void**)&p_Wc,  g_Wc);
    cudaGetSymbolAddress((void**)&p_bc,  g_bc);
    __nv_bfloat16 *p_seqh,*p_seql,*p_aoh,*p_aol,*p_o2h,*p_o2l,*p_wch,*p_oph,*p_fwh;
    cudaGetSymbolAddress((void**)&p_seqh, g_seqh); cudaGetSymbolAddress((void**)&p_seql, g_seql);
    cudaGetSymbolAddress((void**)&p_aoh,  g_aoh);  cudaGetSymbolAddress((void**)&p_aol,  g_aol);
    cudaGetSymbolAddress((void**)&p_o2h,  g_o2h);  cudaGetSymbolAddress((void**)&p_o2l,  g_o2l);
    cudaGetSymbolAddress((void**)&p_wch,  g_wch);
    cudaGetSymbolAddress((void**)&p_oph,  g_oph);
    cudaGetSymbolAddress((void**)&p_fwh,  g_fwh);

    cudaFuncSetAttribute(k_gemm_mma<0>, cudaFuncAttributeMaxDynamicSharedMemorySize, SMEM_DYN);
    cudaFuncSetAttribute(k_gemm_mma<1>, cudaFuncAttributeMaxDynamicSharedMemorySize, SMEM_DYN);
    cudaFuncSetAttribute(k_gemm_mma<2>, cudaFuncAttributeMaxDynamicSharedMemorySize, SMEM_DYN);

    // graph path (round-6 atomic scatter — measured faster than CSR gather)
    k_zero<<<(NN16/4 + 255)/256, 256>>>();
    k_bnstats<<<NB*CIN, 128>>>(x);
    k_bnfin<<<1, 32>>>(gam, bet);
    k_bnx2<<<NB, 256>>>(x);
    k_deg<<<(EINC + 255)/256, 256>>>(hi);
    k_inv<<<(NNODE + 255)/256, 256>>>();
    {
        long long tot = (long long)EINC * 4;
        int blocks = (int)((tot + 255) / 256);
        k_scatter_e<<<blocks, 256>>>(hi);
        k_scatter_h<<<blocks, 256>>>(hi);
    }
    k_seq2<<<NB, 256>>>(hcw, hcb, cw, cb);

    // weight folding + bf16 prep (hi only)
    k_cw<<<(EMB*EMB + 255)/256, 256>>>(ipw,             wq, p_Wc);
    k_cw<<<(EMB*EMB + 255)/256, 256>>>(ipw +   EMB*EMB, wk, p_Wc +   EMB*EMB);
    k_cw<<<(EMB*EMB + 255)/256, 256>>>(ipw + 2*EMB*EMB, wv, p_Wc + 2*EMB*EMB);
    k_cb<<<2, 256>>>(ipw,             ipb,         bq, p_bc);
    k_cb<<<2, 256>>>(ipw +   EMB*EMB, ipb +   EMB, bk, p_bc + EMB);
    k_cb<<<2, 256>>>(ipw + 2*EMB*EMB, ipb + 2*EMB, bv, p_bc + 2*EMB);
    k_preph<<<(1024*KDIM + 255)/256, 256>>>(p_Wc, p_wch, 1024, 1008);
    k_preph<<<(384*KDIM + 255)/256, 256>>>(opw, p_oph, 384, 336);
    k_preph<<<(2688*KDIM + 255)/256, 256>>>(fw, p_fwh, 2688, 2688);

    // GEMMs + attention
    k_gemm_mma<0><<<dim3(8, ROWS/128), 256, SMEM_DYN>>>(
        p_seqh, p_seql, p_wch, p_bc, p_qkv, nullptr, nullptr, 1008, nullptr, nullptr);
    k_attn2<<<NB, 256>>>();
    k_gemm_mma<2><<<dim3(3, ROWS/128), 256, SMEM_DYN>>>(
        p_aoh, p_aol, p_oph, opb, nullptr, p_o2h, p_o2l, 336, nullptr, nullptr);
    k_gemm_mma<1><<<dim3(21, ROWS/128), 256, SMEM_DYN>>>(
        p_o2h, p_o2l, p_fwh, fb, out, nullptr, nullptr, 2688, pw, pb);
}

// round 9
// speedup vs baseline: 1.3705x; 1.1849x over previous
#include <cuda_runtime.h>
#include <cuda_bf16.h>
#include <math.h>

#define NB    2048
#define CIN   16
#define VMD   42
#define NNODE (NB*8*VMD)            // 688128
#define EINC  (4*NNODE)             // 2752512
#define EMB   336
#define ROWS  (NB*8)                // 16384
#define KDIM  336
#define NSTEP 21
#define NN16  (NNODE*16)

// ---------------- scratch ----------------
__device__ __align__(16) float  g_xb[NN16];    // BN-normalized x (fp32, residual path)
__device__ __align__(16) __nv_bfloat16 g_xnb[NN16];   // raw x bf16, node-major
__device__ __align__(16) __nv_bfloat16 g_e [NN16];    // bf16 edge accumulators
__device__ __align__(16) __nv_bfloat16 g_h [NN16];    // bf16 node accumulators
__device__ __align__(16) float  g_D [NNODE];
__device__ __align__(16) float  g_B [NNODE];
__device__ __align__(16) float  g_qkv[ROWS*3*EMB];
__device__ __align__(16) float  g_Wc [3*EMB*EMB];
__device__ __align__(16) float  g_bc [3*EMB];
__device__ double g_sum[CIN], g_sum2[CIN];
__device__ float  g_scale[CIN], g_shift[CIN];
// bf16 staging (single precision level now)
__device__ __align__(16) __nv_bfloat16 g_seqh[ROWS*KDIM];
__device__ __align__(16) __nv_bfloat16 g_aoh [ROWS*KDIM];
__device__ __align__(16) __nv_bfloat16 g_o2h [ROWS*KDIM];
__device__ __align__(16) __nv_bfloat16 g_wch [1024*KDIM];
__device__ __align__(16) __nv_bfloat16 g_oph [384*KDIM];
__device__ __align__(16) __nv_bfloat16 g_fwh [2688*KDIM];

// ---------------- helpers ----------------
__device__ __forceinline__ unsigned smem_u32(const void* p) {
    unsigned a;
    asm("{ .reg .u64 t; cvta.to.shared.u64 t, %1; cvt.u32.u64 %0, t; }" : "=r"(a) : "l"(p));
    return a;
}
__device__ __forceinline__ void ldm4(unsigned* r, unsigned addr) {
    asm volatile("ldmatrix.sync.aligned.m8n8.x4.shared.b16 {%0,%1,%2,%3}, [%4];"
        : "=r"(r[0]), "=r"(r[1]), "=r"(r[2]), "=r"(r[3]) : "r"(addr));
}
__device__ __forceinline__ void mma16816(float* d, const unsigned* a, const unsigned* b) {
    asm volatile("mma.sync.aligned.m16n8k16.row.col.f32.bf16.bf16.f32 "
        "{%0,%1,%2,%3}, {%4,%5,%6,%7}, {%8,%9}, {%0,%1,%2,%3};"
        : "+f"(d[0]), "+f"(d[1]), "+f"(d[2]), "+f"(d[3])
        : "r"(a[0]), "r"(a[1]), "r"(a[2]), "r"(a[3]), "r"(b[0]), "r"(b[1]));
}
__device__ __forceinline__ void cpa16(unsigned dst, const void* src) {
    asm volatile("cp.async.cg.shared.global [%0], [%1], 16;" :: "r"(dst), "l"(src));
}
__device__ __forceinline__ unsigned long long ffma2(unsigned long long a,
                                                    unsigned long long b,
                                                    unsigned long long c) {
    unsigned long long d;
    asm("fma.rn.f32x2 %0, %1, %2, %3;" : "=l"(d) : "l"(a), "l"(b), "l"(c));
    return d;
}
__device__ __forceinline__ unsigned long long pack2(float x, float y) {
    unsigned long long d;
    asm("mov.b64 %0, {%1, %2};" : "=l"(d) : "f"(x), "f"(y));
    return d;
}
__device__ __forceinline__ float2 unpack2(unsigned long long v) {
    float2 r;
    asm("mov.b64 {%0, %1}, %2;" : "=f"(r.x), "=f"(r.y) : "l"(v));
    return r;
}
__device__ __forceinline__ void red_v4bf16x2(__nv_bfloat16* dst, unsigned r0, unsigned r1,
                                             unsigned r2, unsigned r3) {
    asm volatile("red.global.add.noftz.v4.bf16x2 [%0], {%1, %2, %3, %4};"
                 :: "l"(dst), "r"(r0), "r"(r1), "r"(r2), "r"(r3) : "memory");
}

// ---------------- init ----------------
__global__ void k_zero() {
    int i = blockIdx.x*blockDim.x + threadIdx.x;
    uint4 z = make_uint4(0u,0u,0u,0u);
    if (i < NN16/8) { ((uint4*)g_e)[i] = z; ((uint4*)g_h)[i] = z; }
    if (i < NNODE) { g_D[i] = 0.f; g_B[i] = 0.f; }
    if (i < CIN) { g_sum[i] = 0.0; g_sum2[i] = 0.0; }
}

// ---------------- BatchNorm ----------------
__global__ void k_bnstats(const float* __restrict__ x) {
    __shared__ double sh[128], sh2[128];
    int b = blockIdx.x;
    const float* p = x + b*336;
    double s = 0.0, s2 = 0.0;
    for (int i = threadIdx.x; i < 336; i += 128) { double v = p[i]; s += v; s2 += v*v; }
    sh[threadIdx.x] = s; sh2[threadIdx.x] = s2; __syncthreads();
    for (int o = 64; o > 0; o >>= 1) {
        if (threadIdx.x < o) { sh[threadIdx.x] += sh[threadIdx.x+o]; sh2[threadIdx.x] += sh2[threadIdx.x+o]; }
        __syncthreads();
    }
    if (threadIdx.x == 0) {
        int c = b & 15;
        atomicAdd(&g_sum[c], sh[0]);
        atomicAdd(&g_sum2[c], sh2[0]);
    }
}

__global__ void k_bnfin(const float* __restrict__ gamma, const float* __restrict__ beta) {
    int c = threadIdx.x;
    if (c >= CIN) return;
    double cnt = (double)NNODE;
    double mean = g_sum[c] / cnt;
    double var  = g_sum2[c] / cnt - mean*mean;
    float sc = gamma[c] * rsqrtf((float)var + 1e-5f);
    g_scale[c] = sc;
    g_shift[c] = beta[c] - (float)mean * sc;
}

__global__ void k_bnx2(const float* __restrict__ x) {
    __shared__ float sx[16*337];
    const int n = blockIdx.x, tid = threadIdx.x;
    const float* xp = x + (size_t)n*5376;
    for (int i = tid; i < 5376; i += 256) {
        int c = i / 336, rem = i % 336;
        sx[c*337 + rem] = xp[i];
    }
    __syncthreads();
    const size_t base = (size_t)n*5376;
    for (int i = tid; i < 5376; i += 256) {
        int rem = i >> 4, c = i & 15;
        float v = sx[c*337 + rem];
        g_xnb[base + i] = __float2bfloat16(v);
        g_xb[base + i] = v * g_scale[c] + g_shift[c];
    }
}

// ---------------- hypergraph ----------------
__global__ void k_deg(const int* __restrict__ hi) {
    int i = blockIdx.x*blockDim.x + threadIdx.x;
    if (i >= EINC) return;
    atomicAdd(&g_D[hi[i]], 1.f);
    atomicAdd(&g_B[hi[EINC + i]], 1.f);
}

__global__ void k_inv() {
    int i = blockIdx.x*blockDim.x + threadIdx.x;
    if (i >= NNODE) return;
    float d = g_D[i]; g_D[i] = (d > 0.f) ? (1.f/d) : 0.f;
    float b = g_B[i]; g_B[i] = (b > 0.f) ? (1.f/b) : 0.f;
}

// pass 1: e[edge] += xn[node]  (16 bf16 per row; 2 halves of 8)
__global__ void k_scatter_e(const int* __restrict__ hi) {
    unsigned gi = blockIdx.x*blockDim.x + threadIdx.x;   // EINC*2
    if (gi >= (unsigned)EINC * 2u) return;
    int i = (int)(gi >> 1), g = (int)((gi & 1u) << 3);
    int node = __ldg(&hi[i]), edge = __ldg(&hi[EINC + i]);
    uint4 v = *(const uint4*)(g_xnb + (size_t)node*16 + g);
    red_v4bf16x2(g_e + (size_t)edge*16 + g, v.x, v.y, v.z, v.w);
}

// pass 2: h[node] += Binv[edge]*e[edge]
__global__ void k_scatter_h(const int* __restrict__ hi) {
    unsigned gi = blockIdx.x*blockDim.x + threadIdx.x;   // EINC*2
    if (gi >= (unsigned)EINC * 2u) return;
    int i = (int)(gi >> 1), g = (int)((gi & 1u) << 3);
    int node = __ldg(&hi[i]), edge = __ldg(&hi[EINC + i]);
    float w = g_B[edge];
    __nv_bfloat162 w2 = __float2bfloat162_rn(w);
    uint4 v = *(const uint4*)(g_e + (size_t)edge*16 + g);
    __nv_bfloat162 a = __hmul2(*(__nv_bfloat162*)&v.x, w2);
    __nv_bfloat162 b = __hmul2(*(__nv_bfloat162*)&v.y, w2);
    __nv_bfloat162 c = __hmul2(*(__nv_bfloat162*)&v.z, w2);
    __nv_bfloat162 d = __hmul2(*(__nv_bfloat162*)&v.w, w2);
    red_v4bf16x2(g_h + (size_t)node*16 + g,
                 *(unsigned*)&a, *(unsigned*)&b, *(unsigned*)&c, *(unsigned*)&d);
}

// ---------------- fused hconv + time-conv -> seq (bf16 out) ----------------
__global__ __launch_bounds__(256) void k_seq2(
        const float* __restrict__ hcw, const float* __restrict__ hcb,
        const float* __restrict__ cw,  const float* __restrict__ cb) {
    __shared__ float sh_h[336*16];
    __shared__ float sh_w[16*64];
    __shared__ float sh_hv[336];
    __shared__ float sh_cw[64], sh_cb[8], sh_hcb[64];
    const int n = blockIdx.x, tid = threadIdx.x;
    const uint4* hsrc = (const uint4*)(g_h + (size_t)n*5376);
    const float* dsrc = g_D + n*336;
    for (int i = tid; i < 672; i += 256) {           // 8 bf16 per iter
        float d = dsrc[i >> 1];
        uint4 v = hsrc[i];
        float2 f0 = __bfloat1622float2(*(__nv_bfloat162*)&v.x);
        float2 f1 = __bfloat1622float2(*(__nv_bfloat162*)&v.y);
        float2 f2 = __bfloat1622float2(*(__nv_bfloat162*)&v.z);
        float2 f3 = __bfloat1622float2(*(__nv_bfloat162*)&v.w);
        float* o = sh_h + 8*i;
        o[0] = f0.x*d; o[1] = f0.y*d; o[2] = f1.x*d; o[3] = f1.y*d;
        o[4] = f2.x*d; o[5] = f2.y*d; o[6] = f3.x*d; o[7] = f3.y*d;
    }
    for (int i = tid; i < 1024; i += 256) {
        int co = i & 63, ci = i >> 6;
        sh_w[ci*64 + co] = hcw[co*16 + ci];
    }
    if (tid < 64) { sh_cw[tid] = cw[tid]; sh_hcb[tid] = hcb[tid]; }
    if (tid < 8)  sh_cb[tid] = cb[tid];

    for (int w = 0; w < 8; w++) {
        __syncthreads();
        for (int inner = tid; inner < 336; inner += 256) {
            int nodeL = w*42 + (inner >> 6);
            int c = inner & 63;
            const float* hr = sh_h + nodeL*16;
            float acc = sh_hcb[c];
            #pragma unroll
            for (int j = 0; j < 16; j++) acc += hr[j] * sh_w[j*64 + c];
            sh_hv[inner] = acc;
        }
        __syncthreads();
        for (int p = tid; p < 336; p += 256) {
            int o = p / 42, vm = p % 42;
            float acc = sh_cb[o];
            #pragma unroll
            for (int t = 0; t < 8; t++) acc += sh_cw[o*8 + t] * sh_hv[t*42 + vm];
            g_seqh[(size_t)(n*8 + o)*336 + w*42 + vm] = __float2bfloat16(acc);
        }
    }
}

// ---------------- weight folding ----------------
__global__ void k_cw(const float* __restrict__ W1, const float* __restrict__ wq,
                     float* __restrict__ Wc) {
    int i = blockIdx.x*blockDim.x + threadIdx.x;
    if (i >= EMB*EMB) return;
    int o = i / EMB, ii = i % EMB;
    float acc = 0.f;
    for (int m = 0; m < EMB; m++) acc += W1[o*EMB + m] * wq[m*EMB + ii];
    Wc[i] = acc;
}

__global__ void k_cb(const float* __restrict__ W1, const float* __restrict__ b1,
                     const float* __restrict__ bq, float* __restrict__ bc) {
    int o = blockIdx.x*blockDim.x + threadIdx.x;
    if (o >= EMB) return;
    float acc = b1[o];
    for (int m = 0; m < EMB; m++) acc += W1[o*EMB + m] * bq[m];
    bc[o] = acc;
}

// ---------------- fp32 -> bf16 (weights) ----------------
__global__ void k_preph(const float* __restrict__ src, __nv_bfloat16* __restrict__ hi,
                        int total_rows, int rows_src) {
    int i = blockIdx.x*blockDim.x + threadIdx.x;
    if (i >= total_rows*KDIM) return;
    int r = i / KDIM;
    float v = (r < rows_src) ? src[i] : 0.f;
    hi[i] = __float2bfloat16(v);
}

// ---------------- pure-bf16 mma.sync GEMM: C = A·B^T + bias ----------------
// MODE 0: fp32 C + bias.  MODE 1: fc fused residual+relu.  MODE 2: bf16 out + bias.
#define STG3     3
#define BUFB     6144
#define ARRB     (STG3*BUFB)
#define SMEM_DYN (2*ARRB + 4096 + 256)

template<int MODE>
__global__ __launch_bounds__(256) void k_gemm_mma(
        const __nv_bfloat16* __restrict__ Ah, const __nv_bfloat16* __restrict__ Bh,
        const float* __restrict__ bias, float* __restrict__ C,
        __nv_bfloat16* __restrict__ Oh, int Nn,
        const float* __restrict__ pw, const float* __restrict__ pb) {
    extern __shared__ __align__(16) char dsm[];
    float* s_pw = (float*)(dsm + 2*ARRB);
    float* s_pb = s_pw + 1024;

    const int tid = threadIdx.x, lane = tid & 31, wid = tid >> 5;
    const int warpM = wid & 1, warpN = wid >> 1;
    const int row0 = blockIdx.y << 7, col0 = blockIdx.x << 7;

    if (MODE == 1) {
        for (int i = tid; i < 1024; i += 256) {
            int c = i >> 6, co = i & 63;
            s_pw[i] = pw[co*16 + c];
        }
        if (tid < 64) s_pb[tid] = pb[tid];
    }

    const int lrow = tid >> 1, lhalf = tid & 1;
    const __nv_bfloat16* gAh = Ah + (size_t)(row0 + lrow)*KDIM + lhalf*8;
    const __nv_bfloat16* gBh = Bh + (size_t)(col0 + lrow)*KDIM + lhalf*8;
    const unsigned sb = smem_u32(dsm);
    const int so = lrow*48 + lhalf*16;

    const int rsubA = (lane & 7) + ((lane >> 3) & 1)*8;
    const int cA = (warpM*64 + rsubA)*48 + ((lane >> 4) & 1)*16;
    const int rsubB = (lane & 7) + ((lane >> 4) & 1)*8;
    const int cB = (warpN*32 + rsubB)*48 + ((lane >> 3) & 1)*16;

    float acc[4][4][4];
    #pragma unroll
    for (int i = 0; i < 4; i++)
        #pragma unroll
        for (int j = 0; j < 4; j++)
            #pragma unroll
            for (int q = 0; q < 4; q++) acc[i][j][q] = 0.f;

    #pragma unroll
    for (int st = 0; st < 2; st++) {
        unsigned d = sb + st*BUFB + so;
        cpa16(d,        gAh + st*16);
        cpa16(d + ARRB, gBh + st*16);
        asm volatile("cp.async.commit_group;");
    }

    #pragma unroll 1
    for (int ch = 0; ch < NSTEP; ch++) {
        if (ch == NSTEP-1) asm volatile("cp.async.wait_group 0;");
        else               asm volatile("cp.async.wait_group 1;");
        __syncthreads();
        if (ch + 2 < NSTEP) {
            unsigned d = sb + ((ch+2)%3)*BUFB + so;
            cpa16(d,        gAh + (ch+2)*16);
            cpa16(d + ARRB, gBh + (ch+2)*16);
            asm volatile("cp.async.commit_group;");
        }
        const unsigned bo = sb + (ch%3)*BUFB;
        unsigned AH[4][4];
        #pragma unroll
        for (int mt = 0; mt < 4; mt++)
            ldm4(AH[mt], bo + cA + mt*768);
        #pragma unroll
        for (int p = 0; p < 2; p++) {
            unsigned BH[4];
            ldm4(BH, bo + ARRB + cB + p*768);
            #pragma unroll
            for (int mt = 0; mt < 4; mt++) {
                #pragma unroll
                for (int q = 0; q < 2; q++)
                    mma16816(acc[mt][2*p + q], AH[mt], BH + 2*q);
            }
        }
    }

    if (MODE == 0) {
        #pragma unroll
        for (int mt = 0; mt < 4; mt++) {
            int r1 = row0 + warpM*64 + mt*16 + (lane >> 2);
            #pragma unroll
            for (int nt = 0; nt < 4; nt++) {
                int gc = col0 + warpN*32 + nt*8 + (lane & 3)*2;
                if (gc < Nn) {
                    float b0 = __ldg(bias + gc), b1 = __ldg(bias + gc + 1);
                    float* ac = acc[mt][nt];
                    *(float2*)(C + (size_t)r1*Nn + gc)     = make_float2(ac[0]+b0, ac[1]+b1);
                    *(float2*)(C + (size_t)(r1+8)*Nn + gc) = make_float2(ac[2]+b0, ac[3]+b1);
                }
            }
        }
    } else if (MODE == 2) {
        #pragma unroll
        for (int mt = 0; mt < 4; mt++) {
            int r1 = row0 + warpM*64 + mt*16 + (lane >> 2);
            #pragma unroll
            for (int nt = 0; nt < 4; nt++) {
                int gc = col0 + warpN*32 + nt*8 + (lane & 3)*2;
                if (gc < Nn) {
                    float b0 = __ldg(bias + gc), b1 = __ldg(bias + gc + 1);
                    float* ac = acc[mt][nt];
                    __nv_bfloat162 v0 = __floats2bfloat162_rn(ac[0]+b0, ac[1]+b1);
                    __nv_bfloat162 v1 = __floats2bfloat162_rn(ac[2]+b0, ac[3]+b1);
                    *(__nv_bfloat162*)(Oh + (size_t)r1*KDIM + gc)     = v0;
                    *(__nv_bfloat162*)(Oh + (size_t)(r1+8)*KDIM + gc) = v1;
                }
            }
        }
    } else {
        __syncthreads();
        float* xs = (float*)dsm;
        const int v0 = col0 >> 6;
        for (int i = tid; i < 4096; i += 256) {
            int vml = i >> 11, r = (i >> 4) & 127, c = i & 15;
            xs[vml*2176 + r*17 + c] = g_xb[((size_t)(row0 + r)*42 + v0 + vml)*16 + c];
        }
        __syncthreads();

        const int vml = warpN >> 1;
        #pragma unroll
        for (int mt = 0; mt < 4; mt++) {
            int rl1 = warpM*64 + mt*16 + (lane >> 2);
            int rl2 = rl1 + 8;
            float xa[16], xc2[16];
            #pragma unroll
            for (int c = 0; c < 16; c++) {
                xa[c]  = xs[vml*2176 + rl1*17 + c];
                xc2[c] = xs[vml*2176 + rl2*17 + c];
            }
            #pragma unroll
            for (int nt = 0; nt < 4; nt++) {
                int co = (warpN & 1)*32 + nt*8 + (lane & 3)*2;
                int gc = col0 + (warpN & 1)*32 + (vml ? 64 : 0) + nt*8 + (lane & 3)*2;
                float fb0 = __ldg(bias + gc) + s_pb[co];
                float fb1 = __ldg(bias + gc + 1) + s_pb[co + 1];
                unsigned long long rv1 = pack2(fb0, fb1);
                unsigned long long rv2 = rv1;
                #pragma unroll
                for (int c = 0; c < 16; c++) {
                    unsigned long long w2 = *(const unsigned long long*)&s_pw[c*64 + co];
                    rv1 = ffma2(pack2(xa[c],  xa[c]),  w2, rv1);
                    rv2 = ffma2(pack2(xc2[c], xc2[c]), w2, rv2);
                }
                float2 u1 = unpack2(rv1), u2 = unpack2(rv2);
                float* ac = acc[mt][nt];
                int r1 = row0 + rl1, r2 = row0 + rl2;
                *(float2*)(C + (size_t)r1*2688 + gc) =
                    make_float2(fmaxf(ac[0]+u1.x, 0.f), fmaxf(ac[1]+u1.y, 0.f));
                *(float2*)(C + (size_t)r2*2688 + gc) =
                    make_float2(fmaxf(ac[2]+u2.x, 0.f), fmaxf(ac[3]+u2.y, 0.f));
            }
        }
    }
}

// ---------------- attention ----------------
__global__ __launch_bounds__(256) void k_attn2() {
    __shared__ float sq[8*1012];
    __shared__ float sc[256], at[256];
    const int n = blockIdx.x, tid = threadIdx.x;
    const float* src = g_qkv + (size_t)n*8064;
    for (int i = tid; i < 8064; i += 256) {
        int r = i / 1008, c = i - r*1008;
        sq[r*1012 + c] = src[i];
    }
    __syncthreads();
    const int h = tid >> 6, s = (tid >> 3) & 7, t = tid & 7;
    {
        const float* qr = sq + s*1012 + h*84;
        const float* kr = sq + t*1012 + 336 + h*84;
        float acc = 0.f;
        #pragma unroll 12
        for (int d = 0; d < 84; d++) acc += qr[d]*kr[d];
        sc[tid] = acc * 0.1091089451179961805f;
    }
    __syncthreads();
    const int rb = tid & ~7;
    float mx = sc[rb];
    #pragma unroll
    for (int k = 1; k < 8; k++) mx = fmaxf(mx, sc[rb + k]);
    float e = expf(sc[tid] - mx);
    at[tid] = e;
    __syncthreads();
    float sum = 0.f;
    #pragma unroll
    for (int k = 0; k < 8; k++) sum += at[rb + k];
    float a = e / sum;
    __syncthreads();
    at[tid] = a;
    __syncthreads();
    for (int idx = tid; idx < 2688; idx += 256) {
        int s2 = idx / 336, c = idx - s2*336;
        int hh = c / 84, d = c - hh*84;
        const float* vr = sq + 672 + hh*84 + d;
        const float* ar = at + hh*64 + s2*8;
        float o = 0.f;
        #pragma unroll
        for (int k = 0; k < 8; k++) o += ar[k] * vr[k*1012];
        g_aoh[(size_t)(n*8 + s2)*336 + c] = __float2bfloat16(o);
    }
}

// ---------------- launcher ----------------
extern "C" void kernel_launch(void* const* d_in, const int* in_sizes, int n_in,
                              void* d_out, int out_size) {
    const float* x   = (const float*)d_in[0];
    const int*   hi  = (const int*)  d_in[1];
    const float* hcw = (const float*)d_in[2];
    const float* hcb = (const float*)d_in[3];
    const float* cw  = (const float*)d_in[4];
    const float* cb  = (const float*)d_in[5];
    const float* gam = (const float*)d_in[6];
    const float* bet = (const float*)d_in[7];
    const float* pw  = (const float*)d_in[8];
    const float* pb  = (const float*)d_in[9];
    const float* wq  = (const float*)d_in[10];
    const float* bq  = (const float*)d_in[11];
    const float* wk  = (const float*)d_in[12];
    const float* bk  = (const float*)d_in[13];
    const float* wv  = (const float*)d_in[14];
    const float* bv  = (const float*)d_in[15];
    const float* ipw = (const float*)d_in[16];
    const float* ipb = (const float*)d_in[17];
    const float* opw = (const float*)d_in[18];
    const float* opb = (const float*)d_in[19];
    const float* fw  = (const float*)d_in[20];
    const float* fb  = (const float*)d_in[21];
    float* out = (float*)d_out;

    float *p_qkv, *p_Wc, *p_bc;
    cudaGetSymbolAddress((void**)&p_qkv, g_qkv);
    cudaGetSymbolAddress((void**)&p_Wc,  g_Wc);
    cudaGetSymbolAddress((void**)&p_bc,  g_bc);
    __nv_bfloat16 *p_seqh,*p_aoh,*p_o2h,*p_wch,*p_oph,*p_fwh;
    cudaGetSymbolAddress((void**)&p_seqh, g_seqh);
    cudaGetSymbolAddress((void**)&p_aoh,  g_aoh);
    cudaGetSymbolAddress((void**)&p_o2h,  g_o2h);
    cudaGetSymbolAddress((void**)&p_wch,  g_wch);
    cudaGetSymbolAddress((void**)&p_oph,  g_oph);
    cudaGetSymbolAddress((void**)&p_fwh,  g_fwh);

    cudaFuncSetAttribute(k_gemm_mma<0>, cudaFuncAttributeMaxDynamicSharedMemorySize, SMEM_DYN);
    cudaFuncSetAttribute(k_gemm_mma<1>, cudaFuncAttributeMaxDynamicSharedMemorySize, SMEM_DYN);
    cudaFuncSetAttribute(k_gemm_mma<2>, cudaFuncAttributeMaxDynamicSharedMemorySize, SMEM_DYN);

    // graph path (bf16 scatter)
    k_zero<<<(NN16/8 + 255)/256, 256>>>();
    k_bnstats<<<NB*CIN, 128>>>(x);
    k_bnfin<<<1, 32>>>(gam, bet);
    k_bnx2<<<NB, 256>>>(x);
    k_deg<<<(EINC + 255)/256, 256>>>(hi);
    k_inv<<<(NNODE + 255)/256, 256>>>();
    {
        long long tot = (long long)EINC * 2;
        int blocks = (int)((tot + 255) / 256);
        k_scatter_e<<<blocks, 256>>>(hi);
        k_scatter_h<<<blocks, 256>>>(hi);
    }
    k_seq2<<<NB, 256>>>(hcw, hcb, cw, cb);

    // weight folding + bf16 prep
    k_cw<<<(EMB*EMB + 255)/256, 256>>>(ipw,             wq, p_Wc);
    k_cw<<<(EMB*EMB + 255)/256, 256>>>(ipw +   EMB*EMB, wk, p_Wc +   EMB*EMB);
    k_cw<<<(EMB*EMB + 255)/256, 256>>>(ipw + 2*EMB*EMB, wv, p_Wc + 2*EMB*EMB);
    k_cb<<<2, 256>>>(ipw,             ipb,         bq, p_bc);
    k_cb<<<2, 256>>>(ipw +   EMB*EMB, ipb +   EMB, bk, p_bc + EMB);
    k_cb<<<2, 256>>>(ipw + 2*EMB*EMB, ipb + 2*EMB, bv, p_bc + 2*EMB);
    k_preph<<<(1024*KDIM + 255)/256, 256>>>(p_Wc, p_wch, 1024, 1008);
    k_preph<<<(384*KDIM + 255)/256, 256>>>(opw, p_oph, 384, 336);
    k_preph<<<(2688*KDIM + 255)/256, 256>>>(fw, p_fwh, 2688, 2688);

    // GEMMs + attention
    k_gemm_mma<0><<<dim3(8, ROWS/128), 256, SMEM_DYN>>>(
        p_seqh, p_wch, p_bc, p_qkv, nullptr, 1008, nullptr, nullptr);
    k_attn2<<<NB, 256>>>();
    k_gemm_mma<2><<<dim3(3, ROWS/128), 256, SMEM_DYN>>>(
        p_aoh, p_oph, opb, nullptr, p_o2h, 336, nullptr, nullptr);
    k_gemm_mma<1><<<dim3(21, ROWS/128), 256, SMEM_DYN>>>(
        p_o2h, p_fwh, fb, out, nullptr, 2688, pw, pb);
}

// round 10
// speedup vs baseline: 1.5443x; 1.1268x over previous
#include <cuda_runtime.h>
#include <cuda_bf16.h>
#include <cuda_fp8.h>
#include <math.h>

#define NB    2048
#define CIN   16
#define VMD   42
#define NNODE (NB*8*VMD)            // 688128
#define EINC  (4*NNODE)             // 2752512
#define EMB   336
#define ROWS  (NB*8)                // 16384
#define KPAD  352                   // K padded to 11*32 for fp8 k32 mma
#define NSTEP 11
#define NN16  (NNODE*16)

// fp8 scales
#define SW_W    256.f
#define SA_SEQ  64.f
#define SA_AO   4096.f
#define SA_O2   8192.f
#define INV_QKV (1.f/(SA_SEQ*SW_W))
#define INV_OP  (1.f/(SA_AO*SW_W))
#define INV_FC  (1.f/(SA_O2*SW_W))

// ---------------- scratch ----------------
__device__ __align__(16) float  g_xn[NN16];           // raw x fp32, node-major (residual)
__device__ __align__(16) __nv_bfloat16 g_xnb[NN16];   // raw x bf16, node-major (scatter+BN)
__device__ __align__(16) __nv_bfloat16 g_e [NN16];
__device__ __align__(16) __nv_bfloat16 g_h [NN16];
__device__ __align__(16) float  g_D [NNODE];
__device__ __align__(16) float  g_B [NNODE];
__device__ __align__(16) float  g_qkv[ROWS*3*EMB];
__device__ __align__(16) float  g_Wc [3*EMB*EMB];
__device__ __align__(16) float  g_bc [3*EMB];
__device__ double g_sum[CIN], g_sum2[CIN];
__device__ float  g_pwf[16*64];     // proj_w * bn_scale, [c][co]
__device__ float  g_pbf[64];        // proj_b + shift @ proj_w
// fp8 staging
__device__ __align__(16) unsigned char g_seq8[ROWS*KPAD];
__device__ __align__(16) unsigned char g_ao8 [ROWS*KPAD];
__device__ __align__(16) unsigned char g_o28 [ROWS*KPAD];
__device__ __align__(16) unsigned char g_wc8 [1024*KPAD];
__device__ __align__(16) unsigned char g_op8 [384*KPAD];
__device__ __align__(16) unsigned char g_fw8 [2688*KPAD];

// ---------------- helpers ----------------
__device__ __forceinline__ unsigned smem_u32(const void* p) {
    unsigned a;
    asm("{ .reg .u64 t; cvta.to.shared.u64 t, %1; cvt.u32.u64 %0, t; }" : "=r"(a) : "l"(p));
    return a;
}
__device__ __forceinline__ void ldm4(unsigned* r, unsigned addr) {
    asm volatile("ldmatrix.sync.aligned.m8n8.x4.shared.b16 {%0,%1,%2,%3}, [%4];"
        : "=r"(r[0]), "=r"(r[1]), "=r"(r[2]), "=r"(r[3]) : "r"(addr));
}
__device__ __forceinline__ void mma_fp8(float* d, const unsigned* a, const unsigned* b) {
    asm volatile("mma.sync.aligned.m16n8k32.row.col.f32.e4m3.e4m3.f32 "
        "{%0,%1,%2,%3}, {%4,%5,%6,%7}, {%8,%9}, {%0,%1,%2,%3};"
        : "+f"(d[0]), "+f"(d[1]), "+f"(d[2]), "+f"(d[3])
        : "r"(a[0]), "r"(a[1]), "r"(a[2]), "r"(a[3]), "r"(b[0]), "r"(b[1]));
}
__device__ __forceinline__ void cpa16(unsigned dst, const void* src) {
    asm volatile("cp.async.cg.shared.global [%0], [%1], 16;" :: "r"(dst), "l"(src));
}
__device__ __forceinline__ unsigned long long ffma2(unsigned long long a,
                                                    unsigned long long b,
                                                    unsigned long long c) {
    unsigned long long d;
    asm("fma.rn.f32x2 %0, %1, %2, %3;" : "=l"(d) : "l"(a), "l"(b), "l"(c));
    return d;
}
__device__ __forceinline__ unsigned long long pack2(float x, float y) {
    unsigned long long d;
    asm("mov.b64 %0, {%1, %2};" : "=l"(d) : "f"(x), "f"(y));
    return d;
}
__device__ __forceinline__ float2 unpack2(unsigned long long v) {
    float2 r;
    asm("mov.b64 {%0, %1}, %2;" : "=f"(r.x), "=f"(r.y) : "l"(v));
    return r;
}
__device__ __forceinline__ unsigned char to8(float v) {
    __nv_fp8_e4m3 f(v);
    return *(unsigned char*)&f;
}
__device__ __forceinline__ void red_v4bf16x2(__nv_bfloat16* dst, unsigned r0, unsigned r1,
                                             unsigned r2, unsigned r3) {
    asm volatile("red.global.add.noftz.v4.bf16x2 [%0], {%1, %2, %3, %4};"
                 :: "l"(dst), "r"(r0), "r"(r1), "r"(r2), "r"(r3) : "memory");
}

// ---------------- init ----------------
__global__ void k_zero() {
    int i = blockIdx.x*blockDim.x + threadIdx.x;
    uint4 z = make_uint4(0u,0u,0u,0u);
    if (i < NN16/8) { ((uint4*)g_e)[i] = z; ((uint4*)g_h)[i] = z; }
    if (i < NNODE) { g_D[i] = 0.f; g_B[i] = 0.f; }
    if (i < CIN) { g_sum[i] = 0.0; g_sum2[i] = 0.0; }
}

// zero pad columns [336,352) of fp8 activation tensors
__global__ void k_padz() {
    int i = blockIdx.x*blockDim.x + threadIdx.x;
    if (i >= ROWS*16) return;
    size_t off = (size_t)(i >> 4)*KPAD + 336 + (i & 15);
    g_seq8[off] = 0; g_ao8[off] = 0; g_o28[off] = 0;
}

// ---------------- stage x node-major (fp32 + bf16) ----------------
__global__ void k_stage(const float* __restrict__ x) {
    __shared__ float sx[16*337];
    const int n = blockIdx.x, tid = threadIdx.x;
    const float* xp = x + (size_t)n*5376;
    for (int i = tid; i < 5376; i += 256) {
        int c = i / 336, rem = i % 336;
        sx[c*337 + rem] = xp[i];
    }
    __syncthreads();
    const size_t base = (size_t)n*5376;
    for (int i = tid; i < 5376; i += 256) {
        int rem = i >> 4, c = i & 15;
        float v = sx[c*337 + rem];
        g_xn[base + i] = v;
        g_xnb[base + i] = __float2bfloat16(v);
    }
}

// ---------------- BN stats from bf16 staged x ----------------
__global__ void k_bnstats2() {
    __shared__ double sh[256], sh2[256];
    const int b = blockIdx.x, tid = threadIdx.x;     // 2048 blocks
    const int c = tid & 15, no = tid >> 4;
    const __nv_bfloat16* p = g_xnb + (size_t)b*5376;
    double s = 0.0, s2 = 0.0;
    for (int node = no; node < 336; node += 16) {
        double v = __bfloat162float(p[node*16 + c]);
        s += v; s2 += v*v;
    }
    sh[tid] = s; sh2[tid] = s2; __syncthreads();
    // reduce over the 16 node-offset slots per channel
    for (int o = 128; o >= 16; o >>= 1) {
        if (tid < o) { sh[tid] += sh[tid + o]; sh2[tid] += sh2[tid + o]; }
        __syncthreads();
    }
    if (tid < 16) {
        atomicAdd(&g_sum[tid], sh[tid]);
        atomicAdd(&g_sum2[tid], sh2[tid]);
    }
}

// finalize BN + fold scale/shift into proj weights
__global__ void k_bnfin(const float* __restrict__ gamma, const float* __restrict__ beta,
                        const float* __restrict__ pw, const float* __restrict__ pb) {
    __shared__ float ssc[16], ssh[16];
    int t = threadIdx.x;
    if (t < 16) {
        double cnt = (double)NNODE;
        double mean = g_sum[t] / cnt;
        double var  = g_sum2[t] / cnt - mean*mean;
        float sc = gamma[t] * rsqrtf((float)var + 1e-5f);
        ssc[t] = sc;
        ssh[t] = beta[t] - (float)mean * sc;
    }
    __syncthreads();
    if (t < 64) {
        float acc = pb[t];
        #pragma unroll
        for (int c = 0; c < 16; c++) {
            float w = pw[t*16 + c];
            acc += ssh[c] * w;
            g_pwf[c*64 + t] = w * ssc[c];
        }
        g_pbf[t] = acc;
    }
}

// ---------------- hypergraph ----------------
__global__ void k_deg(const int* __restrict__ hi) {
    int i = blockIdx.x*blockDim.x + threadIdx.x;
    if (i >= EINC) return;
    atomicAdd(&g_D[hi[i]], 1.f);
    atomicAdd(&g_B[hi[EINC + i]], 1.f);
}

__global__ void k_inv() {
    int i = blockIdx.x*blockDim.x + threadIdx.x;
    if (i >= NNODE) return;
    float d = g_D[i]; g_D[i] = (d > 0.f) ? (1.f/d) : 0.f;
    float b = g_B[i]; g_B[i] = (b > 0.f) ? (1.f/b) : 0.f;
}

__global__ void k_scatter_e(const int* __restrict__ hi) {
    unsigned gi = blockIdx.x*blockDim.x + threadIdx.x;
    if (gi >= (unsigned)EINC * 2u) return;
    int i = (int)(gi >> 1), g = (int)((gi & 1u) << 3);
    int node = __ldg(&hi[i]), edge = __ldg(&hi[EINC + i]);
    uint4 v = *(const uint4*)(g_xnb + (size_t)node*16 + g);
    red_v4bf16x2(g_e + (size_t)edge*16 + g, v.x, v.y, v.z, v.w);
}

__global__ void k_scatter_h(const int* __restrict__ hi) {
    unsigned gi = blockIdx.x*blockDim.x + threadIdx.x;
    if (gi >= (unsigned)EINC * 2u) return;
    int i = (int)(gi >> 1), g = (int)((gi & 1u) << 3);
    int node = __ldg(&hi[i]), edge = __ldg(&hi[EINC + i]);
    float w = g_B[edge];
    __nv_bfloat162 w2 = __float2bfloat162_rn(w);
    uint4 v = *(const uint4*)(g_e + (size_t)edge*16 + g);
    __nv_bfloat162 a = __hmul2(*(__nv_bfloat162*)&v.x, w2);
    __nv_bfloat162 b = __hmul2(*(__nv_bfloat162*)&v.y, w2);
    __nv_bfloat162 c = __hmul2(*(__nv_bfloat162*)&v.z, w2);
    __nv_bfloat162 d = __hmul2(*(__nv_bfloat162*)&v.w, w2);
    red_v4bf16x2(g_h + (size_t)node*16 + g,
                 *(unsigned*)&a, *(unsigned*)&b, *(unsigned*)&c, *(unsigned*)&d);
}

// ---------------- fused hconv + time-conv -> seq (fp8 out, scaled) ----------------
__global__ __launch_bounds__(256) void k_seq2(
        const float* __restrict__ hcw, const float* __restrict__ hcb,
        const float* __restrict__ cw,  const float* __restrict__ cb) {
    __shared__ float sh_h[336*16];
    __shared__ float sh_w[16*64];
    __shared__ float sh_hv[336];
    __shared__ float sh_cw[64], sh_cb[8], sh_hcb[64];
    const int n = blockIdx.x, tid = threadIdx.x;
    const uint4* hsrc = (const uint4*)(g_h + (size_t)n*5376);
    const float* dsrc = g_D + n*336;
    for (int i = tid; i < 672; i += 256) {
        float d = dsrc[i >> 1];
        uint4 v = hsrc[i];
        float2 f0 = __bfloat1622float2(*(__nv_bfloat162*)&v.x);
        float2 f1 = __bfloat1622float2(*(__nv_bfloat162*)&v.y);
        float2 f2 = __bfloat1622float2(*(__nv_bfloat162*)&v.z);
        float2 f3 = __bfloat1622float2(*(__nv_bfloat162*)&v.w);
        float* o = sh_h + 8*i;
        o[0] = f0.x*d; o[1] = f0.y*d; o[2] = f1.x*d; o[3] = f1.y*d;
        o[4] = f2.x*d; o[5] = f2.y*d; o[6] = f3.x*d; o[7] = f3.y*d;
    }
    for (int i = tid; i < 1024; i += 256) {
        int co = i & 63, ci = i >> 6;
        sh_w[ci*64 + co] = hcw[co*16 + ci];
    }
    if (tid < 64) { sh_cw[tid] = cw[tid]; sh_hcb[tid] = hcb[tid]; }
    if (tid < 8)  sh_cb[tid] = cb[tid];

    for (int w = 0; w < 8; w++) {
        __syncthreads();
        for (int inner = tid; inner < 336; inner += 256) {
            int nodeL = w*42 + (inner >> 6);
            int c = inner & 63;
            const float* hr = sh_h + nodeL*16;
            float acc = sh_hcb[c];
            #pragma unroll
            for (int j = 0; j < 16; j++) acc += hr[j] * sh_w[j*64 + c];
            sh_hv[inner] = acc;
        }
        __syncthreads();
        for (int p = tid; p < 336; p += 256) {
            int o = p / 42, vm = p % 42;
            float acc = sh_cb[o];
            #pragma unroll
            for (int t = 0; t < 8; t++) acc += sh_cw[o*8 + t] * sh_hv[t*42 + vm];
            g_seq8[(size_t)(n*8 + o)*KPAD + w*42 + vm] = to8(acc * SA_SEQ);
        }
    }
}

// ---------------- weight folding ----------------
__global__ void k_cw(const float* __restrict__ W1, const float* __restrict__ wq,
                     float* __restrict__ Wc) {
    int i = blockIdx.x*blockDim.x + threadIdx.x;
    if (i >= EMB*EMB) return;
    int o = i / EMB, ii = i % EMB;
    float acc = 0.f;
    for (int m = 0; m < EMB; m++) acc += W1[o*EMB + m] * wq[m*EMB + ii];
    Wc[i] = acc;
}

__global__ void k_cb(const float* __restrict__ W1, const float* __restrict__ b1,
                     const float* __restrict__ bq, float* __restrict__ bc) {
    int o = blockIdx.x*blockDim.x + threadIdx.x;
    if (o >= EMB) return;
    float acc = b1[o];
    for (int m = 0; m < EMB; m++) acc += W1[o*EMB + m] * bq[m];
    bc[o] = acc;
}

// ---------------- fp32 -> fp8 weights (scaled, zero-padded) ----------------
__global__ void k_prep8(const float* __restrict__ src, unsigned char* __restrict__ dst,
                        int total_rows, int rows_src) {
    int i = blockIdx.x*blockDim.x + threadIdx.x;
    if (i >= total_rows*KPAD) return;
    int r = i / KPAD, c = i - r*KPAD;
    float v = (r < rows_src && c < 336) ? src[(size_t)r*336 + c] * SW_W : 0.f;
    dst[i] = to8(v);
}

// ---------------- fp8 mma.sync GEMM: C = (A·B^T)*inv + bias ----------------
// MODE 0: fp32 out.  MODE 1: fc fused residual+relu.  MODE 2: fp8 out (scaled).
#define STG3     3
#define BUFB     6144
#define ARRB     (STG3*BUFB)
#define SMEM_DYN (2*ARRB + 4096 + 256)

template<int MODE>
__global__ __launch_bounds__(256) void k_gemm_mma(
        const unsigned char* __restrict__ A, const unsigned char* __restrict__ B,
        const float* __restrict__ bias, float* __restrict__ C,
        unsigned char* __restrict__ O8, int Nn, float inv, float outsc) {
    extern __shared__ __align__(16) char dsm[];
    float* s_pw = (float*)(dsm + 2*ARRB);
    float* s_pb = s_pw + 1024;

    const int tid = threadIdx.x, lane = tid & 31, wid = tid >> 5;
    const int warpM = wid & 1, warpN = wid >> 1;
    const int row0 = blockIdx.y << 7, col0 = blockIdx.x << 7;

    if (MODE == 1) {
        for (int i = tid; i < 1024; i += 256) s_pw[i] = g_pwf[i];
        if (tid < 64) s_pb[tid] = g_pbf[tid];
    }

    const int lrow = tid >> 1, lhalf = tid & 1;
    const unsigned char* gA = A + (size_t)(row0 + lrow)*KPAD + lhalf*16;
    const unsigned char* gB = B + (size_t)(col0 + lrow)*KPAD + lhalf*16;
    const unsigned sb = smem_u32(dsm);
    const int so = lrow*48 + lhalf*16;

    const int rsubA = (lane & 7) + ((lane >> 3) & 1)*8;
    const int cA = (warpM*64 + rsubA)*48 + ((lane >> 4) & 1)*16;
    const int rsubB = (lane & 7) + ((lane >> 4) & 1)*8;
    const int cB = (warpN*32 + rsubB)*48 + ((lane >> 3) & 1)*16;

    float acc[4][4][4];
    #pragma unroll
    for (int i = 0; i < 4; i++)
        #pragma unroll
        for (int j = 0; j < 4; j++)
            #pragma unroll
            for (int q = 0; q < 4; q++) acc[i][j][q] = 0.f;

    #pragma unroll
    for (int st = 0; st < 2; st++) {
        unsigned d = sb + st*BUFB + so;
        cpa16(d,        gA + st*32);
        cpa16(d + ARRB, gB + st*32);
        asm volatile("cp.async.commit_group;");
    }

    #pragma unroll 1
    for (int ch = 0; ch < NSTEP; ch++) {
        if (ch == NSTEP-1) asm volatile("cp.async.wait_group 0;");
        else               asm volatile("cp.async.wait_group 1;");
        __syncthreads();
        if (ch + 2 < NSTEP) {
            unsigned d = sb + ((ch+2)%3)*BUFB + so;
            cpa16(d,        gA + (ch+2)*32);
            cpa16(d + ARRB, gB + (ch+2)*32);
            asm volatile("cp.async.commit_group;");
        }
        const unsigned bo = sb + (ch%3)*BUFB;
        unsigned AH[4][4];
        #pragma unroll
        for (int mt = 0; mt < 4; mt++)
            ldm4(AH[mt], bo + cA + mt*768);
        #pragma unroll
        for (int p = 0; p < 2; p++) {
            unsigned BH[4];
            ldm4(BH, bo + ARRB + cB + p*768);
            #pragma unroll
            for (int mt = 0; mt < 4; mt++) {
                #pragma unroll
                for (int q = 0; q < 2; q++)
                    mma_fp8(acc[mt][2*p + q], AH[mt], BH + 2*q);
            }
        }
    }

    if (MODE == 0) {
        #pragma unroll
        for (int mt = 0; mt < 4; mt++) {
            int r1 = row0 + warpM*64 + mt*16 + (lane >> 2);
            #pragma unroll
            for (int nt = 0; nt < 4; nt++) {
                int gc = col0 + warpN*32 + nt*8 + (lane & 3)*2;
                if (gc < Nn) {
                    float b0 = __ldg(bias + gc), b1 = __ldg(bias + gc + 1);
                    float* ac = acc[mt][nt];
                    *(float2*)(C + (size_t)r1*Nn + gc) =
                        make_float2(ac[0]*inv + b0, ac[1]*inv + b1);
                    *(float2*)(C + (size_t)(r1+8)*Nn + gc) =
                        make_float2(ac[2]*inv + b0, ac[3]*inv + b1);
                }
            }
        }
    } else if (MODE == 2) {
        #pragma unroll
        for (int mt = 0; mt < 4; mt++) {
            int r1 = row0 + warpM*64 + mt*16 + (lane >> 2);
            #pragma unroll
            for (int nt = 0; nt < 4; nt++) {
                int gc = col0 + warpN*32 + nt*8 + (lane & 3)*2;
                if (gc < Nn) {
                    float b0 = __ldg(bias + gc), b1 = __ldg(bias + gc + 1);
                    float* ac = acc[mt][nt];
                    unsigned short p0 = (unsigned short)to8((ac[0]*inv + b0)*outsc)
                                      | ((unsigned short)to8((ac[1]*inv + b1)*outsc) << 8);
                    unsigned short p1 = (unsigned short)to8((ac[2]*inv + b0)*outsc)
                                      | ((unsigned short)to8((ac[3]*inv + b1)*outsc) << 8);
                    *(unsigned short*)(O8 + (size_t)r1*KPAD + gc)     = p0;
                    *(unsigned short*)(O8 + (size_t)(r1+8)*KPAD + gc) = p1;
                }
            }
        }
    } else {
        __syncthreads();
        float* xs = (float*)dsm;
        const int v0 = col0 >> 6;
        for (int i = tid; i < 4096; i += 256) {
            int vml = i >> 11, r = (i >> 4) & 127, c = i & 15;
            xs[vml*2176 + r*17 + c] = g_xn[((size_t)(row0 + r)*42 + v0 + vml)*16 + c];
        }
        __syncthreads();

        const int vml = warpN >> 1;
        #pragma unroll
        for (int mt = 0; mt < 4; mt++) {
            int rl1 = warpM*64 + mt*16 + (lane >> 2);
            int rl2 = rl1 + 8;
            float xa[16], xc2[16];
            #pragma unroll
            for (int c = 0; c < 16; c++) {
                xa[c]  = xs[vml*2176 + rl1*17 + c];
                xc2[c] = xs[vml*2176 + rl2*17 + c];
            }
            #pragma unroll
            for (int nt = 0; nt < 4; nt++) {
                int co = (warpN & 1)*32 + nt*8 + (lane & 3)*2;
                int gc = col0 + (warpN & 1)*32 + (vml ? 64 : 0) + nt*8 + (lane & 3)*2;
                float fb0 = __ldg(bias + gc) + s_pb[co];
                float fb1 = __ldg(bias + gc + 1) + s_pb[co + 1];
                unsigned long long rv1 = pack2(fb0, fb1);
                unsigned long long rv2 = rv1;
                #pragma unroll
                for (int c = 0; c < 16; c++) {
                    unsigned long long w2 = *(const unsigned long long*)&s_pw[c*64 + co];
                    rv1 = ffma2(pack2(xa[c],  xa[c]),  w2, rv1);
                    rv2 = ffma2(pack2(xc2[c], xc2[c]), w2, rv2);
                }
                float2 u1 = unpack2(rv1), u2 = unpack2(rv2);
                float* ac = acc[mt][nt];
                int r1 = row0 + rl1, r2 = row0 + rl2;
                *(float2*)(C + (size_t)r1*2688 + gc) =
                    make_float2(fmaxf(ac[0]*inv + u1.x, 0.f), fmaxf(ac[1]*inv + u1.y, 0.f));
                *(float2*)(C + (size_t)r2*2688 + gc) =
                    make_float2(fmaxf(ac[2]*inv + u2.x, 0.f), fmaxf(ac[3]*inv + u2.y, 0.f));
            }
        }
    }
}

// ---------------- attention (fp32 qkv in, fp8 ao out) ----------------
__global__ __launch_bounds__(256) void k_attn2() {
    __shared__ float sq[8*1012];
    __shared__ float sc[256], at[256];
    const int n = blockIdx.x, tid = threadIdx.x;
    const float* src = g_qkv + (size_t)n*8064;
    for (int i = tid; i < 8064; i += 256) {
        int r = i / 1008, c = i - r*1008;
        sq[r*1012 + c] = src[i];
    }
    __syncthreads();
    const int h = tid >> 6, s = (tid >> 3) & 7, t = tid & 7;
    {
        const float* qr = sq + s*1012 + h*84;
        const float* kr = sq + t*1012 + 336 + h*84;
        float acc = 0.f;
        #pragma unroll 12
        for (int d = 0; d < 84; d++) acc += qr[d]*kr[d];
        sc[tid] = acc * 0.1091089451179961805f;
    }
    __syncthreads();
    const int rb = tid & ~7;
    float mx = sc[rb];
    #pragma unroll
    for (int k = 1; k < 8; k++) mx = fmaxf(mx, sc[rb + k]);
    float e = expf(sc[tid] - mx);
    at[tid] = e;
    __syncthreads();
    float sum = 0.f;
    #pragma unroll
    for (int k = 0; k < 8; k++) sum += at[rb + k];
    float a = e / sum;
    __syncthreads();
    at[tid] = a;
    __syncthreads();
    for (int idx = tid; idx < 2688; idx += 256) {
        int s2 = idx / 336, c = idx - s2*336;
        int hh = c / 84, d = c - hh*84;
        const float* vr = sq + 672 + hh*84 + d;
        const float* ar = at + hh*64 + s2*8;
        float o = 0.f;
        #pragma unroll
        for (int k = 0; k < 8; k++) o += ar[k] * vr[k*1012];
        g_ao8[(size_t)(n*8 + s2)*KPAD + c] = to8(o * SA_AO);
    }
}

// ---------------- launcher ----------------
extern "C" void kernel_launch(void* const* d_in, const int* in_sizes, int n_in,
                              void* d_out, int out_size) {
    const float* x   = (const float*)d_in[0];
    const int*   hi  = (const int*)  d_in[1];
    const float* hcw = (const float*)d_in[2];
    const float* hcb = (const float*)d_in[3];
    const float* cw  = (const float*)d_in[4];
    const float* cb  = (const float*)d_in[5];
    const float* gam = (const float*)d_in[6];
    const float* bet = (const float*)d_in[7];
    const float* pw  = (const float*)d_in[8];
    const float* pb  = (const float*)d_in[9];
    const float* wq  = (const float*)d_in[10];
    const float* bq  = (const float*)d_in[11];
    const float* wk  = (const float*)d_in[12];
    const float* bk  = (const float*)d_in[13];
    const float* wv  = (const float*)d_in[14];
    const float* bv  = (const float*)d_in[15];
    const float* ipw = (const float*)d_in[16];
    const float* ipb = (const float*)d_in[17];
    const float* opw = (const float*)d_in[18];
    const float* opb = (const float*)d_in[19];
    const float* fw  = (const float*)d_in[20];
    const float* fb  = (const float*)d_in[21];
    float* out = (float*)d_out;

    float *p_qkv, *p_Wc, *p_bc;
    cudaGetSymbolAddress((void**)&p_qkv, g_qkv);
    cudaGetSymbolAddress((void**)&p_Wc,  g_Wc);
    cudaGetSymbolAddress((void**)&p_bc,  g_bc);
    unsigned char *p_seq8,*p_ao8,*p_o28,*p_wc8,*p_op8,*p_fw8;
    cudaGetSymbolAddress((void**)&p_seq8, g_seq8);
    cudaGetSymbolAddress((void**)&p_ao8,  g_ao8);
    cudaGetSymbolAddress((void**)&p_o28,  g_o28);
    cudaGetSymbolAddress((void**)&p_wc8,  g_wc8);
    cudaGetSymbolAddress((void**)&p_op8,  g_op8);
    cudaGetSymbolAddress((void**)&p_fw8,  g_fw8);

    cudaFuncSetAttribute(k_gemm_mma<0>, cudaFuncAttributeMaxDynamicSharedMemorySize, SMEM_DYN);
    cudaFuncSetAttribute(k_gemm_mma<1>, cudaFuncAttributeMaxDynamicSharedMemorySize, SMEM_DYN);
    cudaFuncSetAttribute(k_gemm_mma<2>, cudaFuncAttributeMaxDynamicSharedMemorySize, SMEM_DYN);

    // graph path
    k_zero<<<(NN16/8 + 255)/256, 256>>>();
    k_padz<<<(ROWS*16 + 255)/256, 256>>>();
    k_stage<<<NB, 256>>>(x);
    k_bnstats2<<<NB, 256>>>();
    k_bnfin<<<1, 64>>>(gam, bet, pw, pb);
    k_deg<<<(EINC + 255)/256, 256>>>(hi);
    k_inv<<<(NNODE + 255)/256, 256>>>();
    {
        long long tot = (long long)EINC * 2;
        int blocks = (int)((tot + 255) / 256);
        k_scatter_e<<<blocks, 256>>>(hi);
        k_scatter_h<<<blocks, 256>>>(hi);
    }
    k_seq2<<<NB, 256>>>(hcw, hcb, cw, cb);

    // weight folding + fp8 prep
    k_cw<<<(EMB*EMB + 255)/256, 256>>>(ipw,             wq, p_Wc);
    k_cw<<<(EMB*EMB + 255)/256, 256>>>(ipw +   EMB*EMB, wk, p_Wc +   EMB*EMB);
    k_cw<<<(EMB*EMB + 255)/256, 256>>>(ipw + 2*EMB*EMB, wv, p_Wc + 2*EMB*EMB);
    k_cb<<<2, 256>>>(ipw,             ipb,         bq, p_bc);
    k_cb<<<2, 256>>>(ipw +   EMB*EMB, ipb +   EMB, bk, p_bc + EMB);
    k_cb<<<2, 256>>>(ipw + 2*EMB*EMB, ipb + 2*EMB, bv, p_bc + 2*EMB);
    k_prep8<<<(1024*KPAD + 255)/256, 256>>>(p_Wc, p_wc8, 1024, 1008);
    k_prep8<<<(384*KPAD + 255)/256, 256>>>(opw, p_op8, 384, 336);
    k_prep8<<<(2688*KPAD + 255)/256, 256>>>(fw, p_fw8, 2688, 2688);

    // GEMMs + attention
    k_gemm_mma<0><<<dim3(8, ROWS/128), 256, SMEM_DYN>>>(
        p_seq8, p_wc8, p_bc, p_qkv, nullptr, 1008, INV_QKV, 0.f);
    k_attn2<<<NB, 256>>>();
    k_gemm_mma<2><<<dim3(3, ROWS/128), 256, SMEM_DYN>>>(
        p_ao8, p_op8, opb, nullptr, p_o28, 336, INV_OP, SA_O2);
    k_gemm_mma<1><<<dim3(21, ROWS/128), 256, SMEM_DYN>>>(
        p_o28, p_fw8, fb, out, nullptr, 2688, INV_FC, 0.f);
}

// round 11
// speedup vs baseline: 1.6416x; 1.0630x over previous
#include <cuda_runtime.h>
#include <cuda_bf16.h>
#include <cuda_fp8.h>
#include <math.h>

#define NB    2048
#define CIN   16
#define VMD   42
#define NNODE (NB*8*VMD)            // 688128
#define EINC  (4*NNODE)             // 2752512
#define EMB   336
#define ROWS  (NB*8)                // 16384
#define KPAD  352
#define NSTEP 11
#define NN16  (NNODE*16)

// fp8 scales
#define SW_W    256.f
#define SA_SEQ  64.f
#define SA_AO   4096.f
#define SA_O2   8192.f
#define INV_QKV (1.f/(SA_SEQ*SW_W))
#define INV_OP  (1.f/(SA_AO*SW_W))
#define INV_FC  (1.f/(SA_O2*SW_W))

// ---------------- scratch ----------------
__device__ __align__(16) float  g_xn[NN16];
__device__ __align__(16) __nv_bfloat16 g_xnb[NN16];
__device__ __align__(16) __nv_bfloat16 g_e [NN16];
__device__ __align__(16) __nv_bfloat16 g_h [NN16];
__device__ __align__(16) float  g_D [NNODE];
__device__ __align__(16) float  g_B [NNODE];
__device__ __align__(16) float  g_qkv[ROWS*3*EMB];
__device__ __align__(16) float  g_Wc [3*EMB*EMB];
__device__ __align__(16) float  g_bc [3*EMB];
__device__ double g_sum[CIN], g_sum2[CIN];
__device__ float  g_pwf[16*64];
__device__ float  g_pbf[64];
// fp8 staging
__device__ __align__(16) unsigned char g_seq8[ROWS*KPAD];
__device__ __align__(16) unsigned char g_ao8 [ROWS*KPAD];
__device__ __align__(16) unsigned char g_o28 [ROWS*KPAD];
__device__ __align__(16) unsigned char g_wc8 [1024*KPAD];
__device__ __align__(16) unsigned char g_op8 [384*KPAD];
__device__ __align__(16) unsigned char g_fw8 [2688*KPAD];

// ---------------- helpers ----------------
__device__ __forceinline__ unsigned smem_u32(const void* p) {
    unsigned a;
    asm("{ .reg .u64 t; cvta.to.shared.u64 t, %1; cvt.u32.u64 %0, t; }" : "=r"(a) : "l"(p));
    return a;
}
__device__ __forceinline__ void ldm4(unsigned* r, unsigned addr) {
    asm volatile("ldmatrix.sync.aligned.m8n8.x4.shared.b16 {%0,%1,%2,%3}, [%4];"
        : "=r"(r[0]), "=r"(r[1]), "=r"(r[2]), "=r"(r[3]) : "r"(addr));
}
__device__ __forceinline__ void mma_fp8(float* d, const unsigned* a, const unsigned* b) {
    asm volatile("mma.sync.aligned.m16n8k32.row.col.f32.e4m3.e4m3.f32 "
        "{%0,%1,%2,%3}, {%4,%5,%6,%7}, {%8,%9}, {%0,%1,%2,%3};"
        : "+f"(d[0]), "+f"(d[1]), "+f"(d[2]), "+f"(d[3])
        : "r"(a[0]), "r"(a[1]), "r"(a[2]), "r"(a[3]), "r"(b[0]), "r"(b[1]));
}
__device__ __forceinline__ void cpa16(unsigned dst, const void* src) {
    asm volatile("cp.async.cg.shared.global [%0], [%1], 16;" :: "r"(dst), "l"(src));
}
__device__ __forceinline__ unsigned long long ffma2(unsigned long long a,
                                                    unsigned long long b,
                                                    unsigned long long c) {
    unsigned long long d;
    asm("fma.rn.f32x2 %0, %1, %2, %3;" : "=l"(d) : "l"(a), "l"(b), "l"(c));
    return d;
}
__device__ __forceinline__ unsigned long long pack2(float x, float y) {
    unsigned long long d;
    asm("mov.b64 %0, {%1, %2};" : "=l"(d) : "f"(x), "f"(y));
    return d;
}
__device__ __forceinline__ float2 unpack2(unsigned long long v) {
    float2 r;
    asm("mov.b64 {%0, %1}, %2;" : "=f"(r.x), "=f"(r.y) : "l"(v));
    return r;
}
__device__ __forceinline__ unsigned char to8(float v) {
    __nv_fp8_e4m3 f(v);
    return *(unsigned char*)&f;
}
__device__ __forceinline__ void red_v4bf16x2(__nv_bfloat16* dst, unsigned r0, unsigned r1,
                                             unsigned r2, unsigned r3) {
    asm volatile("red.global.add.noftz.v4.bf16x2 [%0], {%1, %2, %3, %4};"
                 :: "l"(dst), "r"(r0), "r"(r1), "r"(r2), "r"(r3) : "memory");
}

// ---------------- init (zero + fp8 pad) ----------------
__global__ void k_zero() {
    int i = blockIdx.x*blockDim.x + threadIdx.x;
    uint4 z = make_uint4(0u,0u,0u,0u);
    if (i < NN16/8) { ((uint4*)g_e)[i] = z; ((uint4*)g_h)[i] = z; }
    if (i < NNODE) { g_D[i] = 0.f; g_B[i] = 0.f; }
    if (i < CIN) { g_sum[i] = 0.0; g_sum2[i] = 0.0; }
    if (i < ROWS*16) {
        size_t off = (size_t)(i >> 4)*KPAD + 336 + (i & 15);
        g_seq8[off] = 0; g_ao8[off] = 0; g_o28[off] = 0;
    }
}

// ---------------- stage x node-major + fused BN partial stats ----------------
__global__ __launch_bounds__(256) void k_stage(const float* __restrict__ x) {
    __shared__ float sx[16*337];
    __shared__ float rs[256], rs2[256];
    const int n = blockIdx.x, tid = threadIdx.x;
    const float* xp = x + (size_t)n*5376;
    float s = 0.f, s2 = 0.f;
    for (int i = tid; i < 5376; i += 256) {
        int c = i / 336, rem = i % 336;
        float v = xp[i];
        sx[c*337 + rem] = v;
        s += v; s2 += v*v;        // per-thread: fixed channel (336 stride pattern)
    }
    // NOTE: each thread's i-set spans a fixed c only if 5376/256 divides per c;
    // it does: stride 256, c = i/336 varies — so reduce per-channel via smem pass below.
    __syncthreads();
    // per-channel sums computed fresh from smem (cheap LDS, correct per channel)
    const int c = tid & 15, no = tid >> 4;
    float cs = 0.f, cs2 = 0.f;
    for (int node = no; node < 336; node += 16) {
        float v = sx[c*337 + node];
        cs += v; cs2 += v*v;
    }
    rs[tid] = cs; rs2[tid] = cs2;
    __syncthreads();
    for (int o = 128; o >= 16; o >>= 1) {
        if (tid < o) { rs[tid] += rs[tid + o]; rs2[tid] += rs2[tid + o]; }
        __syncthreads();
    }
    if (tid < 16) {
        atomicAdd(&g_sum[tid], (double)rs[tid]);
        atomicAdd(&g_sum2[tid], (double)rs2[tid]);
    }
    const size_t base = (size_t)n*5376;
    for (int i = tid; i < 5376; i += 256) {
        int rem = i >> 4, ch = i & 15;
        float v = sx[ch*337 + rem];
        g_xn[base + i] = v;
        g_xnb[base + i] = __float2bfloat16(v);
    }
}

// finalize BN + fold into proj weights
__global__ void k_bnfin(const float* __restrict__ gamma, const float* __restrict__ beta,
                        const float* __restrict__ pw, const float* __restrict__ pb) {
    __shared__ float ssc[16], ssh[16];
    int t = threadIdx.x;
    if (t < 16) {
        double cnt = (double)NNODE;
        double mean = g_sum[t] / cnt;
        double var  = g_sum2[t] / cnt - mean*mean;
        float sc = gamma[t] * rsqrtf((float)var + 1e-5f);
        ssc[t] = sc;
        ssh[t] = beta[t] - (float)mean * sc;
    }
    __syncthreads();
    if (t < 64) {
        float acc = pb[t];
        #pragma unroll
        for (int c = 0; c < 16; c++) {
            float w = pw[t*16 + c];
            acc += ssh[c] * w;
            g_pwf[c*64 + t] = w * ssc[c];
        }
        g_pbf[t] = acc;
    }
}

// ---------------- hypergraph ----------------
__global__ void k_deg(const int* __restrict__ hi) {
    int i = blockIdx.x*blockDim.x + threadIdx.x;
    if (i >= EINC) return;
    atomicAdd(&g_D[hi[i]], 1.f);
    atomicAdd(&g_B[hi[EINC + i]], 1.f);
}

__global__ void k_inv() {
    int i = blockIdx.x*blockDim.x + threadIdx.x;
    if (i >= NNODE) return;
    float d = g_D[i]; g_D[i] = (d > 0.f) ? (1.f/d) : 0.f;
    float b = g_B[i]; g_B[i] = (b > 0.f) ? (1.f/b) : 0.f;
}

// one thread per incidence: full 16-ch row (32B) gather + 2 red.v4
__global__ void k_scatter_e(const int* __restrict__ hi) {
    int i = blockIdx.x*blockDim.x + threadIdx.x;
    if (i >= EINC) return;
    int node = __ldg(&hi[i]), edge = __ldg(&hi[EINC + i]);
    const uint4* src = (const uint4*)(g_xnb + (size_t)node*16);
    uint4 v0 = src[0], v1 = src[1];
    __nv_bfloat16* dst = g_e + (size_t)edge*16;
    red_v4bf16x2(dst,     v0.x, v0.y, v0.z, v0.w);
    red_v4bf16x2(dst + 8, v1.x, v1.y, v1.z, v1.w);
}

__global__ void k_scatter_h(const int* __restrict__ hi) {
    int i = blockIdx.x*blockDim.x + threadIdx.x;
    if (i >= EINC) return;
    int node = __ldg(&hi[i]), edge = __ldg(&hi[EINC + i]);
    float w = g_B[edge];
    __nv_bfloat162 w2 = __float2bfloat162_rn(w);
    const uint4* src = (const uint4*)(g_e + (size_t)edge*16);
    uint4 v0 = src[0], v1 = src[1];
    __nv_bfloat162 a0 = __hmul2(*(__nv_bfloat162*)&v0.x, w2);
    __nv_bfloat162 a1 = __hmul2(*(__nv_bfloat162*)&v0.y, w2);
    __nv_bfloat162 a2 = __hmul2(*(__nv_bfloat162*)&v0.z, w2);
    __nv_bfloat162 a3 = __hmul2(*(__nv_bfloat162*)&v0.w, w2);
    __nv_bfloat162 b0 = __hmul2(*(__nv_bfloat162*)&v1.x, w2);
    __nv_bfloat162 b1 = __hmul2(*(__nv_bfloat162*)&v1.y, w2);
    __nv_bfloat162 b2 = __hmul2(*(__nv_bfloat162*)&v1.z, w2);
    __nv_bfloat162 b3 = __hmul2(*(__nv_bfloat162*)&v1.w, w2);
    __nv_bfloat16* dst = g_h + (size_t)node*16;
    red_v4bf16x2(dst,     *(unsigned*)&a0, *(unsigned*)&a1, *(unsigned*)&a2, *(unsigned*)&a3);
    red_v4bf16x2(dst + 8, *(unsigned*)&b0, *(unsigned*)&b1, *(unsigned*)&b2, *(unsigned*)&b3);
}

// ---------------- fused hconv + time-conv -> seq (fp8 out) ----------------
__global__ __launch_bounds__(256) void k_seq2(
        const float* __restrict__ hcw, const float* __restrict__ hcb,
        const float* __restrict__ cw,  const float* __restrict__ cb) {
    __shared__ float sh_h[336*16];
    __shared__ float sh_w[16*64];
    __shared__ float sh_hv[336];
    __shared__ float sh_cw[64], sh_cb[8], sh_hcb[64];
    const int n = blockIdx.x, tid = threadIdx.x;
    const uint4* hsrc = (const uint4*)(g_h + (size_t)n*5376);
    const float* dsrc = g_D + n*336;
    for (int i = tid; i < 672; i += 256) {
        float d = dsrc[i >> 1];
        uint4 v = hsrc[i];
        float2 f0 = __bfloat1622float2(*(__nv_bfloat162*)&v.x);
        float2 f1 = __bfloat1622float2(*(__nv_bfloat162*)&v.y);
        float2 f2 = __bfloat1622float2(*(__nv_bfloat162*)&v.z);
        float2 f3 = __bfloat1622float2(*(__nv_bfloat162*)&v.w);
        float* o = sh_h + 8*i;
        o[0] = f0.x*d; o[1] = f0.y*d; o[2] = f1.x*d; o[3] = f1.y*d;
        o[4] = f2.x*d; o[5] = f2.y*d; o[6] = f3.x*d; o[7] = f3.y*d;
    }
    for (int i = tid; i < 1024; i += 256) {
        int co = i & 63, ci = i >> 6;
        sh_w[ci*64 + co] = hcw[co*16 + ci];
    }
    if (tid < 64) { sh_cw[tid] = cw[tid]; sh_hcb[tid] = hcb[tid]; }
    if (tid < 8)  sh_cb[tid] = cb[tid];

    for (int w = 0; w < 8; w++) {
        __syncthreads();
        for (int inner = tid; inner < 336; inner += 256) {
            int nodeL = w*42 + (inner >> 6);
            int c = inner & 63;
            const float* hr = sh_h + nodeL*16;
            float acc = sh_hcb[c];
            #pragma unroll
            for (int j = 0; j < 16; j++) acc += hr[j] * sh_w[j*64 + c];
            sh_hv[inner] = acc;
        }
        __syncthreads();
        for (int p = tid; p < 336; p += 256) {
            int o = p / 42, vm = p % 42;
            float acc = sh_cb[o];
            #pragma unroll
            for (int t = 0; t < 8; t++) acc += sh_cw[o*8 + t] * sh_hv[t*42 + vm];
            g_seq8[(size_t)(n*8 + o)*KPAD + w*42 + vm] = to8(acc * SA_SEQ);
        }
    }
}

// ---------------- weight folding ----------------
__global__ void k_cw(const float* __restrict__ W1, const float* __restrict__ wq,
                     float* __restrict__ Wc) {
    int i = blockIdx.x*blockDim.x + threadIdx.x;
    if (i >= EMB*EMB) return;
    int o = i / EMB, ii = i % EMB;
    float acc = 0.f;
    for (int m = 0; m < EMB; m++) acc += W1[o*EMB + m] * wq[m*EMB + ii];
    Wc[i] = acc;
}

__global__ void k_cb(const float* __restrict__ W1, const float* __restrict__ b1,
                     const float* __restrict__ bq, float* __restrict__ bc) {
    int o = blockIdx.x*blockDim.x + threadIdx.x;
    if (o >= EMB) return;
    float acc = b1[o];
    for (int m = 0; m < EMB; m++) acc += W1[o*EMB + m] * bq[m];
    bc[o] = acc;
}

__global__ void k_prep8(const float* __restrict__ src, unsigned char* __restrict__ dst,
                        int total_rows, int rows_src) {
    int i = blockIdx.x*blockDim.x + threadIdx.x;
    if (i >= total_rows*KPAD) return;
    int r = i / KPAD, c = i - r*KPAD;
    float v = (r < rows_src && c < 336) ? src[(size_t)r*336 + c] * SW_W : 0.f;
    dst[i] = to8(v);
}

// ---------------- fp8 mma.sync GEMM ----------------
#define STG3     3
#define BUFB     6144
#define ARRB     (STG3*BUFB)
#define SMEM_DYN (2*ARRB + 4096 + 256)

template<int MODE>
__global__ __launch_bounds__(256) void k_gemm_mma(
        const unsigned char* __restrict__ A, const unsigned char* __restrict__ B,
        const float* __restrict__ bias, float* __restrict__ C,
        unsigned char* __restrict__ O8, int Nn, float inv, float outsc) {
    extern __shared__ __align__(16) char dsm[];
    float* s_pw = (float*)(dsm + 2*ARRB);
    float* s_pb = s_pw + 1024;

    const int tid = threadIdx.x, lane = tid & 31, wid = tid >> 5;
    const int warpM = wid & 1, warpN = wid >> 1;
    const int row0 = blockIdx.y << 7, col0 = blockIdx.x << 7;

    if (MODE == 1) {
        for (int i = tid; i < 1024; i += 256) s_pw[i] = g_pwf[i];
        if (tid < 64) s_pb[tid] = g_pbf[tid];
    }

    const int lrow = tid >> 1, lhalf = tid & 1;
    const unsigned char* gA = A + (size_t)(row0 + lrow)*KPAD + lhalf*16;
    const unsigned char* gB = B + (size_t)(col0 + lrow)*KPAD + lhalf*16;
    const unsigned sb = smem_u32(dsm);
    const int so = lrow*48 + lhalf*16;

    const int rsubA = (lane & 7) + ((lane >> 3) & 1)*8;
    const int cA = (warpM*64 + rsubA)*48 + ((lane >> 4) & 1)*16;
    const int rsubB = (lane & 7) + ((lane >> 4) & 1)*8;
    const int cB = (warpN*32 + rsubB)*48 + ((lane >> 3) & 1)*16;

    float acc[4][4][4];
    #pragma unroll
    for (int i = 0; i < 4; i++)
        #pragma unroll
        for (int j = 0; j < 4; j++)
            #pragma unroll
            for (int q = 0; q < 4; q++) acc[i][j][q] = 0.f;

    #pragma unroll
    for (int st = 0; st < 2; st++) {
        unsigned d = sb + st*BUFB + so;
        cpa16(d,        gA + st*32);
        cpa16(d + ARRB, gB + st*32);
        asm volatile("cp.async.commit_group;");
    }

    #pragma unroll 1
    for (int ch = 0; ch < NSTEP; ch++) {
        if (ch == NSTEP-1) asm volatile("cp.async.wait_group 0;");
        else               asm volatile("cp.async.wait_group 1;");
        __syncthreads();
        if (ch + 2 < NSTEP) {
            unsigned d = sb + ((ch+2)%3)*BUFB + so;
            cpa16(d,        gA + (ch+2)*32);
            cpa16(d + ARRB, gB + (ch+2)*32);
            asm volatile("cp.async.commit_group;");
        }
        const unsigned bo = sb + (ch%3)*BUFB;
        unsigned AH[4][4];
        #pragma unroll
        for (int mt = 0; mt < 4; mt++)
            ldm4(AH[mt], bo + cA + mt*768);
        #pragma unroll
        for (int p = 0; p < 2; p++) {
            unsigned BH[4];
            ldm4(BH, bo + ARRB + cB + p*768);
            #pragma unroll
            for (int mt = 0; mt < 4; mt++) {
                #pragma unroll
                for (int q = 0; q < 2; q++)
                    mma_fp8(acc[mt][2*p + q], AH[mt], BH + 2*q);
            }
        }
    }

    if (MODE == 0) {
        #pragma unroll
        for (int mt = 0; mt < 4; mt++) {
            int r1 = row0 + warpM*64 + mt*16 + (lane >> 2);
            #pragma unroll
            for (int nt = 0; nt < 4; nt++) {
                int gc = col0 + warpN*32 + nt*8 + (lane & 3)*2;
                if (gc < Nn) {
                    float b0 = __ldg(bias + gc), b1 = __ldg(bias + gc + 1);
                    float* ac = acc[mt][nt];
                    *(float2*)(C + (size_t)r1*Nn + gc) =
                        make_float2(ac[0]*inv + b0, ac[1]*inv + b1);
                    *(float2*)(C + (size_t)(r1+8)*Nn + gc) =
                        make_float2(ac[2]*inv + b0, ac[3]*inv + b1);
                }
            }
        }
    } else if (MODE == 2) {
        #pragma unroll
        for (int mt = 0; mt < 4; mt++) {
            int r1 = row0 + warpM*64 + mt*16 + (lane >> 2);
            #pragma unroll
            for (int nt = 0; nt < 4; nt++) {
                int gc = col0 + warpN*32 + nt*8 + (lane & 3)*2;
                if (gc < Nn) {
                    float b0 = __ldg(bias + gc), b1 = __ldg(bias + gc + 1);
                    float* ac = acc[mt][nt];
                    unsigned short p0 = (unsigned short)to8((ac[0]*inv + b0)*outsc)
                                      | ((unsigned short)to8((ac[1]*inv + b1)*outsc) << 8);
                    unsigned short p1 = (unsigned short)to8((ac[2]*inv + b0)*outsc)
                                      | ((unsigned short)to8((ac[3]*inv + b1)*outsc) << 8);
                    *(unsigned short*)(O8 + (size_t)r1*KPAD + gc)     = p0;
                    *(unsigned short*)(O8 + (size_t)(r1+8)*KPAD + gc) = p1;
                }
            }
        }
    } else {
        __syncthreads();
        float* xs = (float*)dsm;
        const int v0 = col0 >> 6;
        for (int i = tid; i < 4096; i += 256) {
            int vml = i >> 11, r = (i >> 4) & 127, c = i & 15;
            xs[vml*2176 + r*17 + c] = g_xn[((size_t)(row0 + r)*42 + v0 + vml)*16 + c];
        }
        __syncthreads();

        const int vml = warpN >> 1;
        #pragma unroll
        for (int mt = 0; mt < 4; mt++) {
            int rl1 = warpM*64 + mt*16 + (lane >> 2);
            int rl2 = rl1 + 8;
            float xa[16], xc2[16];
            #pragma unroll
            for (int c = 0; c < 16; c++) {
                xa[c]  = xs[vml*2176 + rl1*17 + c];
                xc2[c] = xs[vml*2176 + rl2*17 + c];
            }
            #pragma unroll
            for (int nt = 0; nt < 4; nt++) {
                int co = (warpN & 1)*32 + nt*8 + (lane & 3)*2;
                int gc = col0 + (warpN & 1)*32 + (vml ? 64 : 0) + nt*8 + (lane & 3)*2;
                float fb0 = __ldg(bias + gc) + s_pb[co];
                float fb1 = __ldg(bias + gc + 1) + s_pb[co + 1];
                unsigned long long rv1 = pack2(fb0, fb1);
                unsigned long long rv2 = rv1;
                #pragma unroll
                for (int c = 0; c < 16; c++) {
                    unsigned long long w2 = *(const unsigned long long*)&s_pw[c*64 + co];
                    rv1 = ffma2(pack2(xa[c],  xa[c]),  w2, rv1);
                    rv2 = ffma2(pack2(xc2[c], xc2[c]), w2, rv2);
                }
                float2 u1 = unpack2(rv1), u2 = unpack2(rv2);
                float* ac = acc[mt][nt];
                int r1 = row0 + rl1, r2 = row0 + rl2;
                *(float2*)(C + (size_t)r1*2688 + gc) =
                    make_float2(fmaxf(ac[0]*inv + u1.x, 0.f), fmaxf(ac[1]*inv + u1.y, 0.f));
                *(float2*)(C + (size_t)r2*2688 + gc) =
                    make_float2(fmaxf(ac[2]*inv + u2.x, 0.f), fmaxf(ac[3]*inv + u2.y, 0.f));
            }
        }
    }
}

// ---------------- attention ----------------
__global__ __launch_bounds__(256) void k_attn2() {
    __shared__ float sq[8*1012];
    __shared__ float sc[256], at[256];
    const int n = blockIdx.x, tid = threadIdx.x;
    const float* src = g_qkv + (size_t)n*8064;
    for (int i = tid; i < 8064; i += 256) {
        int r = i / 1008, c = i - r*1008;
        sq[r*1012 + c] = src[i];
    }
    __syncthreads();
    const int h = tid >> 6, s = (tid >> 3) & 7, t = tid & 7;
    {
        const float* qr = sq + s*1012 + h*84;
        const float* kr = sq + t*1012 + 336 + h*84;
        float acc = 0.f;
        #pragma unroll 12
        for (int d = 0; d < 84; d++) acc += qr[d]*kr[d];
        sc[tid] = acc * 0.1091089451179961805f;
    }
    __syncthreads();
    const int rb = tid & ~7;
    float mx = sc[rb];
    #pragma unroll
    for (int k = 1; k < 8; k++) mx = fmaxf(mx, sc[rb + k]);
    float e = expf(sc[tid] - mx);
    at[tid] = e;
    __syncthreads();
    float sum = 0.f;
    #pragma unroll
    for (int k = 0; k < 8; k++) sum += at[rb + k];
    float a = e / sum;
    __syncthreads();
    at[tid] = a;
    __syncthreads();
    for (int idx = tid; idx < 2688; idx += 256) {
        int s2 = idx / 336, c = idx - s2*336;
        int hh = c / 84, d = c - hh*84;
        const float* vr = sq + 672 + hh*84 + d;
        const float* ar = at + hh*64 + s2*8;
        float o = 0.f;
        #pragma unroll
        for (int k = 0; k < 8; k++) o += ar[k] * vr[k*1012];
        g_ao8[(size_t)(n*8 + s2)*KPAD + c] = to8(o * SA_AO);
    }
}

// ---------------- launcher ----------------
extern "C" void kernel_launch(void* const* d_in, const int* in_sizes, int n_in,
                              void* d_out, int out_size) {
    const float* x   = (const float*)d_in[0];
    const int*   hi  = (const int*)  d_in[1];
    const float* hcw = (const float*)d_in[2];
    const float* hcb = (const float*)d_in[3];
    const float* cw  = (const float*)d_in[4];
    const float* cb  = (const float*)d_in[5];
    const float* gam = (const float*)d_in[6];
    const float* bet = (const float*)d_in[7];
    const float* pw  = (const float*)d_in[8];
    const float* pb  = (const float*)d_in[9];
    const float* wq  = (const float*)d_in[10];
    const float* bq  = (const float*)d_in[11];
    const float* wk  = (const float*)d_in[12];
    const float* bk  = (const float*)d_in[13];
    const float* wv  = (const float*)d_in[14];
    const float* bv  = (const float*)d_in[15];
    const float* ipw = (const float*)d_in[16];
    const float* ipb = (const float*)d_in[17];
    const float* opw = (const float*)d_in[18];
    const float* opb = (const float*)d_in[19];
    const float* fw  = (const float*)d_in[20];
    const float* fb  = (const float*)d_in[21];
    float* out = (float*)d_out;

    float *p_qkv, *p_Wc, *p_bc;
    cudaGetSymbolAddress((void**)&p_qkv, g_qkv);
    cudaGetSymbolAddress((void**)&p_Wc,  g_Wc);
    cudaGetSymbolAddress((void**)&p_bc,  g_bc);
    unsigned char *p_seq8,*p_ao8,*p_o28,*p_wc8,*p_op8,*p_fw8;
    cudaGetSymbolAddress((void**)&p_seq8, g_seq8);
    cudaGetSymbolAddress((void**)&p_ao8,  g_ao8);
    cudaGetSymbolAddress((void**)&p_o28,  g_o28);
    cudaGetSymbolAddress((void**)&p_wc8,  g_wc8);
    cudaGetSymbolAddress((void**)&p_op8,  g_op8);
    cudaGetSymbolAddress((void**)&p_fw8,  g_fw8);

    cudaFuncSetAttribute(k_gemm_mma<0>, cudaFuncAttributeMaxDynamicSharedMemorySize, SMEM_DYN);
    cudaFuncSetAttribute(k_gemm_mma<1>, cudaFuncAttributeMaxDynamicSharedMemorySize, SMEM_DYN);
    cudaFuncSetAttribute(k_gemm_mma<2>, cudaFuncAttributeMaxDynamicSharedMemorySize, SMEM_DYN);

    // graph path
    k_zero<<<(NN16/8 + 255)/256, 256>>>();
    k_stage<<<NB, 256>>>(x);
    k_bnfin<<<1, 64>>>(gam, bet, pw, pb);
    k_deg<<<(EINC + 255)/256, 256>>>(hi);
    k_inv<<<(NNODE + 255)/256, 256>>>();
    k_scatter_e<<<(EINC + 255)/256, 256>>>(hi);
    k_scatter_h<<<(EINC + 255)/256, 256>>>(hi);
    k_seq2<<<NB, 256>>>(hcw, hcb, cw, cb);

    // weight folding + fp8 prep
    k_cw<<<(EMB*EMB + 255)/256, 256>>>(ipw,             wq, p_Wc);
    k_cw<<<(EMB*EMB + 255)/256, 256>>>(ipw +   EMB*EMB, wk, p_Wc +   EMB*EMB);
    k_cw<<<(EMB*EMB + 255)/256, 256>>>(ipw + 2*EMB*EMB, wv, p_Wc + 2*EMB*EMB);
    k_cb<<<2, 256>>>(ipw,             ipb,         bq, p_bc);
    k_cb<<<2, 256>>>(ipw +   EMB*EMB, ipb +   EMB, bk, p_bc + EMB);
    k_cb<<<2, 256>>>(ipw + 2*EMB*EMB, ipb + 2*EMB, bv, p_bc + 2*EMB);
    k_prep8<<<(1024*KPAD + 255)/256, 256>>>(p_Wc, p_wc8, 1024, 1008);
    k_prep8<<<(384*KPAD + 255)/256, 256>>>(opw, p_op8, 384, 336);
    k_prep8<<<(2688*KPAD + 255)/256, 256>>>(fw, p_fw8, 2688, 2688);

    // GEMMs + attention
    k_gemm_mma<0><<<dim3(8, ROWS/128), 256, SMEM_DYN>>>(
        p_seq8, p_wc8, p_bc, p_qkv, nullptr, 1008, INV_QKV, 0.f);
    k_attn2<<<NB, 256>>>();
    k_gemm_mma<2><<<dim3(3, ROWS/128), 256, SMEM_DYN>>>(
        p_ao8, p_op8, opb, nullptr, p_o28, 336, INV_OP, SA_O2);
    k_gemm_mma<1><<<dim3(21, ROWS/128), 256, SMEM_DYN>>>(
        p_o28, p_fw8, fb, out, nullptr, 2688, INV_FC, 0.f);
}

// round 12
// speedup vs baseline: 1.6432x; 1.0010x over previous
#include <cuda_runtime.h>
#include <cuda_bf16.h>
#include <cuda_fp8.h>
#include <math.h>

#define NB    2048
#define CIN   16
#define VMD   42
#define NNODE (NB*8*VMD)            // 688128
#define EINC  (4*NNODE)             // 2752512
#define EMB   336
#define ROWS  (NB*8)                // 16384
#define KPAD  352
#define NSTEP 11
#define NN16  (NNODE*16)

// fp8 scales
#define SW_W    256.f
#define SA_SEQ  64.f
#define SA_AO   4096.f
#define SA_O2   8192.f
#define INV_QKV (1.f/(SA_SEQ*SW_W))
#define INV_OP  (1.f/(SA_AO*SW_W))
#define INV_FC  (1.f/(SA_O2*SW_W))

// ---------------- scratch ----------------
__device__ __align__(16) float  g_xn[NN16];
__device__ __align__(16) __nv_bfloat16 g_xnb[NN16];
__device__ __align__(16) __nv_bfloat16 g_e [NN16];
__device__ __align__(16) __nv_bfloat16 g_h [NN16];
__device__ __align__(16) float  g_D [NNODE];   // degree counts
__device__ __align__(16) float  g_B [NNODE];   // degree counts
__device__ __align__(16) __nv_bfloat16 g_qkvb[ROWS*1008];
__device__ __align__(16) float  g_Wc [3*EMB*EMB];
__device__ __align__(16) float  g_bc [3*EMB];
__device__ double g_sum[CIN], g_sum2[CIN];
__device__ float  g_pwf[16*64];
__device__ float  g_pbf[64];
// fp8 staging
__device__ __align__(16) unsigned char g_seq8[ROWS*KPAD];
__device__ __align__(16) unsigned char g_ao8 [ROWS*KPAD];
__device__ __align__(16) unsigned char g_o28 [ROWS*KPAD];
__device__ __align__(16) unsigned char g_wc8 [1024*KPAD];
__device__ __align__(16) unsigned char g_op8 [384*KPAD];
__device__ __align__(16) unsigned char g_fw8 [2688*KPAD];

// ---------------- helpers ----------------
__device__ __forceinline__ unsigned smem_u32(const void* p) {
    unsigned a;
    asm("{ .reg .u64 t; cvta.to.shared.u64 t, %1; cvt.u32.u64 %0, t; }" : "=r"(a) : "l"(p));
    return a;
}
__device__ __forceinline__ void ldm4(unsigned* r, unsigned addr) {
    asm volatile("ldmatrix.sync.aligned.m8n8.x4.shared.b16 {%0,%1,%2,%3}, [%4];"
        : "=r"(r[0]), "=r"(r[1]), "=r"(r[2]), "=r"(r[3]) : "r"(addr));
}
__device__ __forceinline__ void mma_fp8(float* d, const unsigned* a, const unsigned* b) {
    asm volatile("mma.sync.aligned.m16n8k32.row.col.f32.e4m3.e4m3.f32 "
        "{%0,%1,%2,%3}, {%4,%5,%6,%7}, {%8,%9}, {%0,%1,%2,%3};"
        : "+f"(d[0]), "+f"(d[1]), "+f"(d[2]), "+f"(d[3])
        : "r"(a[0]), "r"(a[1]), "r"(a[2]), "r"(a[3]), "r"(b[0]), "r"(b[1]));
}
__device__ __forceinline__ void cpa16(unsigned dst, const void* src) {
    asm volatile("cp.async.cg.shared.global [%0], [%1], 16;" :: "r"(dst), "l"(src));
}
__device__ __forceinline__ unsigned long long ffma2(unsigned long long a,
                                                    unsigned long long b,
                                                    unsigned long long c) {
    unsigned long long d;
    asm("fma.rn.f32x2 %0, %1, %2, %3;" : "=l"(d) : "l"(a), "l"(b), "l"(c));
    return d;
}
__device__ __forceinline__ unsigned long long pack2(float x, float y) {
    unsigned long long d;
    asm("mov.b64 %0, {%1, %2};" : "=l"(d) : "f"(x), "f"(y));
    return d;
}
__device__ __forceinline__ float2 unpack2(unsigned long long v) {
    float2 r;
    asm("mov.b64 {%0, %1}, %2;" : "=f"(r.x), "=f"(r.y) : "l"(v));
    return r;
}
__device__ __forceinline__ unsigned char to8(float v) {
    __nv_fp8_e4m3 f(v);
    return *(unsigned char*)&f;
}
__device__ __forceinline__ void red_v4bf16x2(__nv_bfloat16* dst, unsigned r0, unsigned r1,
                                             unsigned r2, unsigned r3) {
    asm volatile("red.global.add.noftz.v4.bf16x2 [%0], {%1, %2, %3, %4};"
                 :: "l"(dst), "r"(r0), "r"(r1), "r"(r2), "r"(r3) : "memory");
}

// ---------------- init (zero + fp8 pad) ----------------
__global__ void k_zero() {
    int i = blockIdx.x*blockDim.x + threadIdx.x;
    uint4 z = make_uint4(0u,0u,0u,0u);
    if (i < NN16/8) { ((uint4*)g_e)[i] = z; ((uint4*)g_h)[i] = z; }
    if (i < NNODE) { g_D[i] = 0.f; g_B[i] = 0.f; }
    if (i < CIN) { g_sum[i] = 0.0; g_sum2[i] = 0.0; }
    if (i < ROWS*16) {
        size_t off = (size_t)(i >> 4)*KPAD + 336 + (i & 15);
        g_seq8[off] = 0; g_ao8[off] = 0; g_o28[off] = 0;
    }
}

// ---------------- stage x node-major + fused BN stats ----------------
__global__ __launch_bounds__(256) void k_stage(const float* __restrict__ x) {
    __shared__ float sx[16*337];
    __shared__ float rs[256], rs2[256];
    const int n = blockIdx.x, tid = threadIdx.x;
    const float* xp = x + (size_t)n*5376;
    for (int i = tid; i < 5376; i += 256) {
        int c = i / 336, rem = i % 336;
        sx[c*337 + rem] = xp[i];
    }
    __syncthreads();
    const int c = tid & 15, no = tid >> 4;
    float cs = 0.f, cs2 = 0.f;
    for (int node = no; node < 336; node += 16) {
        float v = sx[c*337 + node];
        cs += v; cs2 += v*v;
    }
    rs[tid] = cs; rs2[tid] = cs2;
    __syncthreads();
    for (int o = 128; o >= 16; o >>= 1) {
        if (tid < o) { rs[tid] += rs[tid + o]; rs2[tid] += rs2[tid + o]; }
        __syncthreads();
    }
    if (tid < 16) {
        atomicAdd(&g_sum[tid], (double)rs[tid]);
        atomicAdd(&g_sum2[tid], (double)rs2[tid]);
    }
    const size_t base = (size_t)n*5376;
    for (int i = tid; i < 5376; i += 256) {
        int rem = i >> 4, ch = i & 15;
        float v = sx[ch*337 + rem];
        g_xn[base + i] = v;
        g_xnb[base + i] = __float2bfloat16(v);
    }
}

// finalize BN + fold into proj weights
__global__ void k_bnfin(const float* __restrict__ gamma, const float* __restrict__ beta,
                        const float* __restrict__ pw, const float* __restrict__ pb) {
    __shared__ float ssc[16], ssh[16];
    int t = threadIdx.x;
    if (t < 16) {
        double cnt = (double)NNODE;
        double mean = g_sum[t] / cnt;
        double var  = g_sum2[t] / cnt - mean*mean;
        float sc = gamma[t] * rsqrtf((float)var + 1e-5f);
        ssc[t] = sc;
        ssh[t] = beta[t] - (float)mean * sc;
    }
    __syncthreads();
    if (t < 64) {
        float acc = pb[t];
        #pragma unroll
        for (int c = 0; c < 16; c++) {
            float w = pw[t*16 + c];
            acc += ssh[c] * w;
            g_pwf[c*64 + t] = w * ssc[c];
        }
        g_pbf[t] = acc;
    }
}

// ---------------- scatter pass 1 + degree counting fused ----------------
__global__ void k_scatter_e(const int* __restrict__ hi) {
    int i = blockIdx.x*blockDim.x + threadIdx.x;
    if (i >= EINC) return;
    int node = __ldg(&hi[i]), edge = __ldg(&hi[EINC + i]);
    atomicAdd(&g_D[node], 1.f);
    atomicAdd(&g_B[edge], 1.f);
    const uint4* src = (const uint4*)(g_xnb + (size_t)node*16);
    uint4 v0 = src[0], v1 = src[1];
    __nv_bfloat16* dst = g_e + (size_t)edge*16;
    red_v4bf16x2(dst,     v0.x, v0.y, v0.z, v0.w);
    red_v4bf16x2(dst + 8, v1.x, v1.y, v1.z, v1.w);
}

// ---------------- scatter pass 2 (Binv inline) ----------------
__global__ void k_scatter_h(const int* __restrict__ hi) {
    int i = blockIdx.x*blockDim.x + threadIdx.x;
    if (i >= EINC) return;
    int node = __ldg(&hi[i]), edge = __ldg(&hi[EINC + i]);
    float b = g_B[edge];
    float w = (b > 0.f) ? (1.f / b) : 0.f;
    __nv_bfloat162 w2 = __float2bfloat162_rn(w);
    const uint4* src = (const uint4*)(g_e + (size_t)edge*16);
    uint4 v0 = src[0], v1 = src[1];
    __nv_bfloat162 a0 = __hmul2(*(__nv_bfloat162*)&v0.x, w2);
    __nv_bfloat162 a1 = __hmul2(*(__nv_bfloat162*)&v0.y, w2);
    __nv_bfloat162 a2 = __hmul2(*(__nv_bfloat162*)&v0.z, w2);
    __nv_bfloat162 a3 = __hmul2(*(__nv_bfloat162*)&v0.w, w2);
    __nv_bfloat162 b0 = __hmul2(*(__nv_bfloat162*)&v1.x, w2);
    __nv_bfloat162 b1 = __hmul2(*(__nv_bfloat162*)&v1.y, w2);
    __nv_bfloat162 b2 = __hmul2(*(__nv_bfloat162*)&v1.z, w2);
    __nv_bfloat162 b3 = __hmul2(*(__nv_bfloat162*)&v1.w, w2);
    __nv_bfloat16* dst = g_h + (size_t)node*16;
    red_v4bf16x2(dst,     *(unsigned*)&a0, *(unsigned*)&a1, *(unsigned*)&a2, *(unsigned*)&a3);
    red_v4bf16x2(dst + 8, *(unsigned*)&b0, *(unsigned*)&b1, *(unsigned*)&b2, *(unsigned*)&b3);
}

// ---------------- fused hconv + time-conv -> seq (fp8 out; Dinv inline) ----------------
__global__ __launch_bounds__(256) void k_seq2(
        const float* __restrict__ hcw, const float* __restrict__ hcb,
        const float* __restrict__ cw,  const float* __restrict__ cb) {
    __shared__ float sh_h[336*16];
    __shared__ float sh_w[16*64];
    __shared__ float sh_hv[336];
    __shared__ float sh_cw[64], sh_cb[8], sh_hcb[64];
    const int n = blockIdx.x, tid = threadIdx.x;
    const uint4* hsrc = (const uint4*)(g_h + (size_t)n*5376);
    const float* dsrc = g_D + n*336;
    for (int i = tid; i < 672; i += 256) {
        float dc = dsrc[i >> 1];
        float d = (dc > 0.f) ? (1.f / dc) : 0.f;
        uint4 v = hsrc[i];
        float2 f0 = __bfloat1622float2(*(__nv_bfloat162*)&v.x);
        float2 f1 = __bfloat1622float2(*(__nv_bfloat162*)&v.y);
        float2 f2 = __bfloat1622float2(*(__nv_bfloat162*)&v.z);
        float2 f3 = __bfloat1622float2(*(__nv_bfloat162*)&v.w);
        float* o = sh_h + 8*i;
        o[0] = f0.x*d; o[1] = f0.y*d; o[2] = f1.x*d; o[3] = f1.y*d;
        o[4] = f2.x*d; o[5] = f2.y*d; o[6] = f3.x*d; o[7] = f3.y*d;
    }
    for (int i = tid; i < 1024; i += 256) {
        int co = i & 63, ci = i >> 6;
        sh_w[ci*64 + co] = hcw[co*16 + ci];
    }
    if (tid < 64) { sh_cw[tid] = cw[tid]; sh_hcb[tid] = hcb[tid]; }
    if (tid < 8)  sh_cb[tid] = cb[tid];

    for (int w = 0; w < 8; w++) {
        __syncthreads();
        for (int inner = tid; inner < 336; inner += 256) {
            int nodeL = w*42 + (inner >> 6);
            int c = inner & 63;
            const float* hr = sh_h + nodeL*16;
            float acc = sh_hcb[c];
            #pragma unroll
            for (int j = 0; j < 16; j++) acc += hr[j] * sh_w[j*64 + c];
            sh_hv[inner] = acc;
        }
        __syncthreads();
        for (int p = tid; p < 336; p += 256) {
            int o = p / 42, vm = p % 42;
            float acc = sh_cb[o];
            #pragma unroll
            for (int t = 0; t < 8; t++) acc += sh_cw[o*8 + t] * sh_hv[t*42 + vm];
            g_seq8[(size_t)(n*8 + o)*KPAD + w*42 + vm] = to8(acc * SA_SEQ);
        }
    }
}

// ---------------- weight folding ----------------
__global__ void k_cw(const float* __restrict__ W1, const float* __restrict__ wq,
                     float* __restrict__ Wc) {
    int i = blockIdx.x*blockDim.x + threadIdx.x;
    if (i >= EMB*EMB) return;
    int o = i / EMB, ii = i % EMB;
    float acc = 0.f;
    for (int m = 0; m < EMB; m++) acc += W1[o*EMB + m] * wq[m*EMB + ii];
    Wc[i] = acc;
}

__global__ void k_cb(const float* __restrict__ W1, const float* __restrict__ b1,
                     const float* __restrict__ bq, float* __restrict__ bc) {
    int o = blockIdx.x*blockDim.x + threadIdx.x;
    if (o >= EMB) return;
    float acc = b1[o];
    for (int m = 0; m < EMB; m++) acc += W1[o*EMB + m] * bq[m];
    bc[o] = acc;
}

__global__ void k_prep8(const float* __restrict__ src, unsigned char* __restrict__ dst,
                        int total_rows, int rows_src) {
    int i = blockIdx.x*blockDim.x + threadIdx.x;
    if (i >= total_rows*KPAD) return;
    int r = i / KPAD, c = i - r*KPAD;
    float v = (r < rows_src && c < 336) ? src[(size_t)r*336 + c] * SW_W : 0.f;
    dst[i] = to8(v);
}

// ---------------- fp8 mma.sync GEMM ----------------
// MODE 1: fc fused residual+relu (fp32 out).  MODE 2: fp8 out.  MODE 3: bf16 out.
#define STG3     3
#define BUFB     6144
#define ARRB     (STG3*BUFB)
#define SMEM_DYN (2*ARRB + 4096 + 256)

template<int MODE>
__global__ __launch_bounds__(256) void k_gemm_mma(
        const unsigned char* __restrict__ A, const unsigned char* __restrict__ B,
        const float* __restrict__ bias, float* __restrict__ C,
        unsigned char* __restrict__ O8, __nv_bfloat16* __restrict__ Ob,
        int Nn, float inv, float outsc) {
    extern __shared__ __align__(16) char dsm[];
    float* s_pw = (float*)(dsm + 2*ARRB);
    float* s_pb = s_pw + 1024;

    const int tid = threadIdx.x, lane = tid & 31, wid = tid >> 5;
    const int warpM = wid & 1, warpN = wid >> 1;
    const int row0 = blockIdx.y << 7, col0 = blockIdx.x << 7;

    if (MODE == 1) {
        for (int i = tid; i < 1024; i += 256) s_pw[i] = g_pwf[i];
        if (tid < 64) s_pb[tid] = g_pbf[tid];
    }

    const int lrow = tid >> 1, lhalf = tid & 1;
    const unsigned char* gA = A + (size_t)(row0 + lrow)*KPAD + lhalf*16;
    const unsigned char* gB = B + (size_t)(col0 + lrow)*KPAD + lhalf*16;
    const unsigned sb = smem_u32(dsm);
    const int so = lrow*48 + lhalf*16;

    const int rsubA = (lane & 7) + ((lane >> 3) & 1)*8;
    const int cA = (warpM*64 + rsubA)*48 + ((lane >> 4) & 1)*16;
    const int rsubB = (lane & 7) + ((lane >> 4) & 1)*8;
    const int cB = (warpN*32 + rsubB)*48 + ((lane >> 3) & 1)*16;

    float acc[4][4][4];
    #pragma unroll
    for (int i = 0; i < 4; i++)
        #pragma unroll
        for (int j = 0; j < 4; j++)
            #pragma unroll
            for (int q = 0; q < 4; q++) acc[i][j][q] = 0.f;

    #pragma unroll
    for (int st = 0; st < 2; st++) {
        unsigned d = sb + st*BUFB + so;
        cpa16(d,        gA + st*32);
        cpa16(d + ARRB, gB + st*32);
        asm volatile("cp.async.commit_group;");
    }

    #pragma unroll 1
    for (int ch = 0; ch < NSTEP; ch++) {
        if (ch == NSTEP-1) asm volatile("cp.async.wait_group 0;");
        else               asm volatile("cp.async.wait_group 1;");
        __syncthreads();
        if (ch + 2 < NSTEP) {
            unsigned d = sb + ((ch+2)%3)*BUFB + so;
            cpa16(d,        gA + (ch+2)*32);
            cpa16(d + ARRB, gB + (ch+2)*32);
            asm volatile("cp.async.commit_group;");
        }
        const unsigned bo = sb + (ch%3)*BUFB;
        unsigned AH[4][4];
        #pragma unroll
        for (int mt = 0; mt < 4; mt++)
            ldm4(AH[mt], bo + cA + mt*768);
        #pragma unroll
        for (int p = 0; p < 2; p++) {
            unsigned BH[4];
            ldm4(BH, bo + ARRB + cB + p*768);
            #pragma unroll
            for (int mt = 0; mt < 4; mt++) {
                #pragma unroll
                for (int q = 0; q < 2; q++)
                    mma_fp8(acc[mt][2*p + q], AH[mt], BH + 2*q);
            }
        }
    }

    if (MODE == 3) {
        #pragma unroll
        for (int mt = 0; mt < 4; mt++) {
            int r1 = row0 + warpM*64 + mt*16 + (lane >> 2);
            #pragma unroll
            for (int nt = 0; nt < 4; nt++) {
                int gc = col0 + warpN*32 + nt*8 + (lane & 3)*2;
                if (gc < Nn) {
                    float b0 = __ldg(bias + gc), b1 = __ldg(bias + gc + 1);
                    float* ac = acc[mt][nt];
                    __nv_bfloat162 v0 = __floats2bfloat162_rn(ac[0]*inv + b0, ac[1]*inv + b1);
                    __nv_bfloat162 v1 = __floats2bfloat162_rn(ac[2]*inv + b0, ac[3]*inv + b1);
                    *(__nv_bfloat162*)(Ob + (size_t)r1*Nn + gc)     = v0;
                    *(__nv_bfloat162*)(Ob + (size_t)(r1+8)*Nn + gc) = v1;
                }
            }
        }
    } else if (MODE == 2) {
        #pragma unroll
        for (int mt = 0; mt < 4; mt++) {
            int r1 = row0 + warpM*64 + mt*16 + (lane >> 2);
            #pragma unroll
            for (int nt = 0; nt < 4; nt++) {
                int gc = col0 + warpN*32 + nt*8 + (lane & 3)*2;
                if (gc < Nn) {
                    float b0 = __ldg(bias + gc), b1 = __ldg(bias + gc + 1);
                    float* ac = acc[mt][nt];
                    unsigned short p0 = (unsigned short)to8((ac[0]*inv + b0)*outsc)
                                      | ((unsigned short)to8((ac[1]*inv + b1)*outsc) << 8);
                    unsigned short p1 = (unsigned short)to8((ac[2]*inv + b0)*outsc)
                                      | ((unsigned short)to8((ac[3]*inv + b1)*outsc) << 8);
                    *(unsigned short*)(O8 + (size_t)r1*KPAD + gc)     = p0;
                    *(unsigned short*)(O8 + (size_t)(r1+8)*KPAD + gc) = p1;
                }
            }
        }
    } else {
        __syncthreads();
        float* xs = (float*)dsm;
        const int v0 = col0 >> 6;
        for (int i = tid; i < 4096; i += 256) {
            int vml = i >> 11, r = (i >> 4) & 127, c = i & 15;
            xs[vml*2176 + r*17 + c] = g_xn[((size_t)(row0 + r)*42 + v0 + vml)*16 + c];
        }
        __syncthreads();

        const int vml = warpN >> 1;
        #pragma unroll
        for (int mt = 0; mt < 4; mt++) {
            int rl1 = warpM*64 + mt*16 + (lane >> 2);
            int rl2 = rl1 + 8;
            float xa[16], xc2[16];
            #pragma unroll
            for (int c = 0; c < 16; c++) {
                xa[c]  = xs[vml*2176 + rl1*17 + c];
                xc2[c] = xs[vml*2176 + rl2*17 + c];
            }
            #pragma unroll
            for (int nt = 0; nt < 4; nt++) {
                int co = (warpN & 1)*32 + nt*8 + (lane & 3)*2;
                int gc = col0 + (warpN & 1)*32 + (vml ? 64 : 0) + nt*8 + (lane & 3)*2;
                float fb0 = __ldg(bias + gc) + s_pb[co];
                float fb1 = __ldg(bias + gc + 1) + s_pb[co + 1];
                unsigned long long rv1 = pack2(fb0, fb1);
                unsigned long long rv2 = rv1;
                #pragma unroll
                for (int c = 0; c < 16; c++) {
                    unsigned long long w2 = *(const unsigned long long*)&s_pw[c*64 + co];
                    rv1 = ffma2(pack2(xa[c],  xa[c]),  w2, rv1);
                    rv2 = ffma2(pack2(xc2[c], xc2[c]), w2, rv2);
                }
                float2 u1 = unpack2(rv1), u2 = unpack2(rv2);
                float* ac = acc[mt][nt];
                int r1 = row0 + rl1, r2 = row0 + rl2;
                *(float2*)(C + (size_t)r1*2688 + gc) =
                    make_float2(fmaxf(ac[0]*inv + u1.x, 0.f), fmaxf(ac[1]*inv + u1.y, 0.f));
                *(float2*)(C + (size_t)r2*2688 + gc) =
                    make_float2(fmaxf(ac[2]*inv + u2.x, 0.f), fmaxf(ac[3]*inv + u2.y, 0.f));
            }
        }
    }
}

// ---------------- attention (bf16 qkv in, fp8 ao out) ----------------
__global__ __launch_bounds__(256) void k_attn2() {
    __shared__ float sq[8*1012];
    __shared__ float sc[256], at[256];
    const int n = blockIdx.x, tid = threadIdx.x;
    const __nv_bfloat16* src = g_qkvb + (size_t)n*8064;
    for (int i = tid; i < 4032; i += 256) {          // 2 bf16 per iter
        int j = i*2;
        int r = j / 1008, c = j - r*1008;
        float2 f = __bfloat1622float2(*(const __nv_bfloat162*)(src + j));
        sq[r*1012 + c]     = f.x;
        sq[r*1012 + c + 1] = f.y;
    }
    __syncthreads();
    const int h = tid >> 6, s = (tid >> 3) & 7, t = tid & 7;
    {
        const float* qr = sq + s*1012 + h*84;
        const float* kr = sq + t*1012 + 336 + h*84;
        float acc = 0.f;
        #pragma unroll 12
        for (int d = 0; d < 84; d++) acc += qr[d]*kr[d];
        sc[tid] = acc * 0.1091089451179961805f;
    }
    __syncthreads();
    const int rb = tid & ~7;
    float mx = sc[rb];
    #pragma unroll
    for (int k = 1; k < 8; k++) mx = fmaxf(mx, sc[rb + k]);
    float e = expf(sc[tid] - mx);
    at[tid] = e;
    __syncthreads();
    float sum = 0.f;
    #pragma unroll
    for (int k = 0; k < 8; k++) sum += at[rb + k];
    float a = e / sum;
    __syncthreads();
    at[tid] = a;
    __syncthreads();
    for (int idx = tid; idx < 2688; idx += 256) {
        int s2 = idx / 336, c = idx - s2*336;
        int hh = c / 84, d = c - hh*84;
        const float* vr = sq + 672 + hh*84 + d;
        const float* ar = at + hh*64 + s2*8;
        float o = 0.f;
        #pragma unroll
        for (int k = 0; k < 8; k++) o += ar[k] * vr[k*1012];
        g_ao8[(size_t)(n*8 + s2)*KPAD + c] = to8(o * SA_AO);
    }
}

// ---------------- launcher ----------------
extern "C" void kernel_launch(void* const* d_in, const int* in_sizes, int n_in,
                              void* d_out, int out_size) {
    const float* x   = (const float*)d_in[0];
    const int*   hi  = (const int*)  d_in[1];
    const float* hcw = (const float*)d_in[2];
    const float* hcb = (const float*)d_in[3];
    const float* cw  = (const float*)d_in[4];
    const float* cb  = (const float*)d_in[5];
    const float* gam = (const float*)d_in[6];
    const float* bet = (const float*)d_in[7];
    const float* pw  = (const float*)d_in[8];
    const float* pb  = (const float*)d_in[9];
    const float* wq  = (const float*)d_in[10];
    const float* bq  = (const float*)d_in[11];
    const float* wk  = (const float*)d_in[12];
    const float* bk  = (const float*)d_in[13];
    const float* wv  = (const float*)d_in[14];
    const float* bv  = (const float*)d_in[15];
    const float* ipw = (const float*)d_in[16];
    const float* ipb = (const float*)d_in[17];
    const float* opw = (const float*)d_in[18];
    const float* opb = (const float*)d_in[19];
    const float* fw  = (const float*)d_in[20];
    const float* fb  = (const float*)d_in[21];
    float* out = (float*)d_out;

    float *p_Wc, *p_bc;
    cudaGetSymbolAddress((void**)&p_Wc,  g_Wc);
    cudaGetSymbolAddress((void**)&p_bc,  g_bc);
    __nv_bfloat16* p_qkvb;
    cudaGetSymbolAddress((void**)&p_qkvb, g_qkvb);
    unsigned char *p_seq8,*p_ao8,*p_o28,*p_wc8,*p_op8,*p_fw8;
    cudaGetSymbolAddress((void**)&p_seq8, g_seq8);
    cudaGetSymbolAddress((void**)&p_ao8,  g_ao8);
    cudaGetSymbolAddress((void**)&p_o28,  g_o28);
    cudaGetSymbolAddress((void**)&p_wc8,  g_wc8);
    cudaGetSymbolAddress((void**)&p_op8,  g_op8);
    cudaGetSymbolAddress((void**)&p_fw8,  g_fw8);

    cudaFuncSetAttribute(k_gemm_mma<1>, cudaFuncAttributeMaxDynamicSharedMemorySize, SMEM_DYN);
    cudaFuncSetAttribute(k_gemm_mma<2>, cudaFuncAttributeMaxDynamicSharedMemorySize, SMEM_DYN);
    cudaFuncSetAttribute(k_gemm_mma<3>, cudaFuncAttributeMaxDynamicSharedMemorySize, SMEM_DYN);

    // graph path
    k_zero<<<(NN16/8 + 255)/256, 256>>>();
    k_stage<<<NB, 256>>>(x);
    k_bnfin<<<1, 64>>>(gam, bet, pw, pb);
    k_scatter_e<<<(EINC + 255)/256, 256>>>(hi);
    k_scatter_h<<<(EINC + 255)/256, 256>>>(hi);
    k_seq2<<<NB, 256>>>(hcw, hcb, cw, cb);

    // weight folding + fp8 prep
    k_cw<<<(EMB*EMB + 255)/256, 256>>>(ipw,             wq, p_Wc);
    k_cw<<<(EMB*EMB + 255)/256, 256>>>(ipw +   EMB*EMB, wk, p_Wc +   EMB*EMB);
    k_cw<<<(EMB*EMB + 255)/256, 256>>>(ipw + 2*EMB*EMB, wv, p_Wc + 2*EMB*EMB);
    k_cb<<<2, 256>>>(ipw,             ipb,         bq, p_bc);
    k_cb<<<2, 256>>>(ipw +   EMB*EMB, ipb +   EMB, bk, p_bc + EMB);
    k_cb<<<2, 256>>>(ipw + 2*EMB*EMB, ipb + 2*EMB, bv, p_bc + 2*EMB);
    k_prep8<<<(1024*KPAD + 255)/256, 256>>>(p_Wc, p_wc8, 1024, 1008);
    k_prep8<<<(384*KPAD + 255)/256, 256>>>(opw, p_op8, 384, 336);
    k_prep8<<<(2688*KPAD + 255)/256, 256>>>(fw, p_fw8, 2688, 2688);

    // GEMMs + attention
    k_gemm_mma<3><<<dim3(8, ROWS/128), 256, SMEM_DYN>>>(
        p_seq8, p_wc8, p_bc, nullptr, nullptr, p_qkvb, 1008, INV_QKV, 0.f);
    k_attn2<<<NB, 256>>>();
    k_gemm_mma<2><<<dim3(3, ROWS/128), 256, SMEM_DYN>>>(
        p_ao8, p_op8, opb, nullptr, p_o28, nullptr, 336, INV_OP, SA_O2);
    k_gemm_mma<1><<<dim3(21, ROWS/128), 256, SMEM_DYN>>>(
        p_o28, p_fw8, fb, out, nullptr, nullptr, 2688, INV_FC, 0.f);
}

// round 13
// speedup vs baseline: 2.4469x; 1.4891x over previous
#include <cuda_runtime.h>
#include <cuda_bf16.h>
#include <cuda_fp8.h>
#include <math.h>

#define NB    2048
#define CIN   16
#define VMD   42
#define NNODE (NB*8*VMD)            // 688128
#define EINC  (4*NNODE)             // 2752512
#define EMB   336
#define ROWS  (NB*8)                // 16384
#define KPAD  352
#define NSTEP 11
#define NN16  (NNODE*16)

// fp8 scales
#define SW_W    256.f
#define SA_SEQ  64.f
#define SA_AO   4096.f
#define SA_O2   8192.f
#define INV_QKV (1.f/(SA_SEQ*SW_W))
#define INV_OP  (1.f/(SA_AO*SW_W))
#define INV_FC  (1.f/(SA_O2*SW_W))

// ---------------- scratch ----------------
__device__ __align__(16) float  g_xn[NN16];
__device__ __align__(16) __nv_bfloat16 g_xnb[NN16];
__device__ __align__(16) __nv_bfloat16 g_e [NN16];
__device__ __align__(16) __nv_bfloat16 g_h [NN16];
__device__ __align__(16) float  g_D [NNODE];
__device__ __align__(16) float  g_B [NNODE];
__device__ __align__(16) __nv_bfloat16 g_qkvb[ROWS*1008];
__device__ __align__(16) float  g_Wc [3*EMB*EMB];
__device__ __align__(16) float  g_bc [3*EMB];
__device__ double g_sum[CIN], g_sum2[CIN];
__device__ float  g_pwf[16*64];
__device__ float  g_pbf[64];
// fp8 staging
__device__ __align__(16) unsigned char g_seq8[ROWS*KPAD];
__device__ __align__(16) unsigned char g_ao8 [ROWS*KPAD];
__device__ __align__(16) unsigned char g_o28 [ROWS*KPAD];
__device__ __align__(16) unsigned char g_wc8 [1024*KPAD];
__device__ __align__(16) unsigned char g_op8 [384*KPAD];
__device__ __align__(16) unsigned char g_fw8 [2688*KPAD];

// ---------------- helpers ----------------
__device__ __forceinline__ unsigned smem_u32(const void* p) {
    unsigned a;
    asm("{ .reg .u64 t; cvta.to.shared.u64 t, %1; cvt.u32.u64 %0, t; }" : "=r"(a) : "l"(p));
    return a;
}
__device__ __forceinline__ void ldm4(unsigned* r, unsigned addr) {
    asm volatile("ldmatrix.sync.aligned.m8n8.x4.shared.b16 {%0,%1,%2,%3}, [%4];"
        : "=r"(r[0]), "=r"(r[1]), "=r"(r[2]), "=r"(r[3]) : "r"(addr));
}
__device__ __forceinline__ void mma_fp8(float* d, const unsigned* a, const unsigned* b) {
    asm volatile("mma.sync.aligned.m16n8k32.row.col.f32.e4m3.e4m3.f32 "
        "{%0,%1,%2,%3}, {%4,%5,%6,%7}, {%8,%9}, {%0,%1,%2,%3};"
        : "+f"(d[0]), "+f"(d[1]), "+f"(d[2]), "+f"(d[3])
        : "r"(a[0]), "r"(a[1]), "r"(a[2]), "r"(a[3]), "r"(b[0]), "r"(b[1]));
}
__device__ __forceinline__ void cpa16(unsigned dst, const void* src) {
    asm volatile("cp.async.cg.shared.global [%0], [%1], 16;" :: "r"(dst), "l"(src));
}
__device__ __forceinline__ unsigned long long ffma2(unsigned long long a,
                                                    unsigned long long b,
                                                    unsigned long long c) {
    unsigned long long d;
    asm("fma.rn.f32x2 %0, %1, %2, %3;" : "=l"(d) : "l"(a), "l"(b), "l"(c));
    return d;
}
__device__ __forceinline__ unsigned long long pack2(float x, float y) {
    unsigned long long d;
    asm("mov.b64 %0, {%1, %2};" : "=l"(d) : "f"(x), "f"(y));
    return d;
}
__device__ __forceinline__ float2 unpack2(unsigned long long v) {
    float2 r;
    asm("mov.b64 {%0, %1}, %2;" : "=f"(r.x), "=f"(r.y) : "l"(v));
    return r;
}
__device__ __forceinline__ unsigned char to8(float v) {
    __nv_fp8_e4m3 f(v);
    return *(unsigned char*)&f;
}
__device__ __forceinline__ void red_v4bf16x2(__nv_bfloat16* dst, unsigned r0, unsigned r1,
                                             unsigned r2, unsigned r3) {
    asm volatile("red.global.add.noftz.v4.bf16x2 [%0], {%1, %2, %3, %4};"
                 :: "l"(dst), "r"(r0), "r"(r1), "r"(r2), "r"(r3) : "memory");
}

// ---------------- init ----------------
__global__ void k_zero() {
    int i = blockIdx.x*blockDim.x + threadIdx.x;
    uint4 z = make_uint4(0u,0u,0u,0u);
    if (i < NN16/8) { ((uint4*)g_e)[i] = z; ((uint4*)g_h)[i] = z; }
    if (i < NNODE) { g_D[i] = 0.f; g_B[i] = 0.f; }
    if (i < CIN) { g_sum[i] = 0.0; g_sum2[i] = 0.0; }
    if (i < ROWS*16) {
        size_t off = (size_t)(i >> 4)*KPAD + 336 + (i & 15);
        g_seq8[off] = 0; g_ao8[off] = 0; g_o28[off] = 0;
    }
}

// ---------------- stage x node-major + fused BN stats ----------------
__global__ __launch_bounds__(256) void k_stage(const float* __restrict__ x) {
    __shared__ float sx[16*337];
    __shared__ float rs[256], rs2[256];
    const int n = blockIdx.x, tid = threadIdx.x;
    const float* xp = x + (size_t)n*5376;
    for (int i = tid; i < 5376; i += 256) {
        int c = i / 336, rem = i % 336;
        sx[c*337 + rem] = xp[i];
    }
    __syncthreads();
    const int c = tid & 15, no = tid >> 4;
    float cs = 0.f, cs2 = 0.f;
    for (int node = no; node < 336; node += 16) {
        float v = sx[c*337 + node];
        cs += v; cs2 += v*v;
    }
    rs[tid] = cs; rs2[tid] = cs2;
    __syncthreads();
    for (int o = 128; o >= 16; o >>= 1) {
        if (tid < o) { rs[tid] += rs[tid + o]; rs2[tid] += rs2[tid + o]; }
        __syncthreads();
    }
    if (tid < 16) {
        atomicAdd(&g_sum[tid], (double)rs[tid]);
        atomicAdd(&g_sum2[tid], (double)rs2[tid]);
    }
    const size_t base = (size_t)n*5376;
    for (int i = tid; i < 5376; i += 256) {
        int rem = i >> 4, ch = i & 15;
        float v = sx[ch*337 + rem];
        g_xn[base + i] = v;
        g_xnb[base + i] = __float2bfloat16(v);
    }
}

// finalize BN + fold into proj weights
__global__ void k_bnfin(const float* __restrict__ gamma, const float* __restrict__ beta,
                        const float* __restrict__ pw, const float* __restrict__ pb) {
    __shared__ float ssc[16], ssh[16];
    int t = threadIdx.x;
    if (t < 16) {
        double cnt = (double)NNODE;
        double mean = g_sum[t] / cnt;
        double var  = g_sum2[t] / cnt - mean*mean;
        float sc = gamma[t] * rsqrtf((float)var + 1e-5f);
        ssc[t] = sc;
        ssh[t] = beta[t] - (float)mean * sc;
    }
    __syncthreads();
    if (t < 64) {
        float acc = pb[t];
        #pragma unroll
        for (int c = 0; c < 16; c++) {
            float w = pw[t*16 + c];
            acc += ssh[c] * w;
            g_pwf[c*64 + t] = w * ssc[c];
        }
        g_pbf[t] = acc;
    }
}

// ---------------- scatter pass 1 + degree counting ----------------
__global__ void k_scatter_e(const int* __restrict__ hi) {
    int i = blockIdx.x*blockDim.x + threadIdx.x;
    if (i >= EINC) return;
    int node = __ldg(&hi[i]), edge = __ldg(&hi[EINC + i]);
    atomicAdd(&g_D[node], 1.f);
    atomicAdd(&g_B[edge], 1.f);
    const uint4* src = (const uint4*)(g_xnb + (size_t)node*16);
    uint4 v0 = src[0], v1 = src[1];
    __nv_bfloat16* dst = g_e + (size_t)edge*16;
    red_v4bf16x2(dst,     v0.x, v0.y, v0.z, v0.w);
    red_v4bf16x2(dst + 8, v1.x, v1.y, v1.z, v1.w);
}

// ---------------- scatter pass 2 (Binv inline) ----------------
__global__ void k_scatter_h(const int* __restrict__ hi) {
    int i = blockIdx.x*blockDim.x + threadIdx.x;
    if (i >= EINC) return;
    int node = __ldg(&hi[i]), edge = __ldg(&hi[EINC + i]);
    float b = g_B[edge];
    float w = (b > 0.f) ? (1.f / b) : 0.f;
    __nv_bfloat162 w2 = __float2bfloat162_rn(w);
    const uint4* src = (const uint4*)(g_e + (size_t)edge*16);
    uint4 v0 = src[0], v1 = src[1];
    __nv_bfloat162 a0 = __hmul2(*(__nv_bfloat162*)&v0.x, w2);
    __nv_bfloat162 a1 = __hmul2(*(__nv_bfloat162*)&v0.y, w2);
    __nv_bfloat162 a2 = __hmul2(*(__nv_bfloat162*)&v0.z, w2);
    __nv_bfloat162 a3 = __hmul2(*(__nv_bfloat162*)&v0.w, w2);
    __nv_bfloat162 b0 = __hmul2(*(__nv_bfloat162*)&v1.x, w2);
    __nv_bfloat162 b1 = __hmul2(*(__nv_bfloat162*)&v1.y, w2);
    __nv_bfloat162 b2 = __hmul2(*(__nv_bfloat162*)&v1.z, w2);
    __nv_bfloat162 b3 = __hmul2(*(__nv_bfloat162*)&v1.w, w2);
    __nv_bfloat16* dst = g_h + (size_t)node*16;
    red_v4bf16x2(dst,     *(unsigned*)&a0, *(unsigned*)&a1, *(unsigned*)&a2, *(unsigned*)&a3);
    red_v4bf16x2(dst + 8, *(unsigned*)&b0, *(unsigned*)&b1, *(unsigned*)&b2, *(unsigned*)&b3);
}

// ---------------- fused hconv + time-conv -> seq (fp8 out; Dinv inline) ----------------
__global__ __launch_bounds__(256) void k_seq2(
        const float* __restrict__ hcw, const float* __restrict__ hcb,
        const float* __restrict__ cw,  const float* __restrict__ cb) {
    __shared__ float sh_h[336*16];
    __shared__ float sh_w[16*64];
    __shared__ float sh_hv[336];
    __shared__ float sh_cw[64], sh_cb[8], sh_hcb[64];
    const int n = blockIdx.x, tid = threadIdx.x;
    const uint4* hsrc = (const uint4*)(g_h + (size_t)n*5376);
    const float* dsrc = g_D + n*336;
    for (int i = tid; i < 672; i += 256) {
        float dc = dsrc[i >> 1];
        float d = (dc > 0.f) ? (1.f / dc) : 0.f;
        uint4 v = hsrc[i];
        float2 f0 = __bfloat1622float2(*(__nv_bfloat162*)&v.x);
        float2 f1 = __bfloat1622float2(*(__nv_bfloat162*)&v.y);
        float2 f2 = __bfloat1622float2(*(__nv_bfloat162*)&v.z);
        float2 f3 = __bfloat1622float2(*(__nv_bfloat162*)&v.w);
        float* o = sh_h + 8*i;
        o[0] = f0.x*d; o[1] = f0.y*d; o[2] = f1.x*d; o[3] = f1.y*d;
        o[4] = f2.x*d; o[5] = f2.y*d; o[6] = f3.x*d; o[7] = f3.y*d;
    }
    for (int i = tid; i < 1024; i += 256) {
        int co = i & 63, ci = i >> 6;
        sh_w[ci*64 + co] = hcw[co*16 + ci];
    }
    if (tid < 64) { sh_cw[tid] = cw[tid]; sh_hcb[tid] = hcb[tid]; }
    if (tid < 8)  sh_cb[tid] = cb[tid];

    for (int w = 0; w < 8; w++) {
        __syncthreads();
        for (int inner = tid; inner < 336; inner += 256) {
            int nodeL = w*42 + (inner >> 6);
            int c = inner & 63;
            const float* hr = sh_h + nodeL*16;
            float acc = sh_hcb[c];
            #pragma unroll
            for (int j = 0; j < 16; j++) acc += hr[j] * sh_w[j*64 + c];
            sh_hv[inner] = acc;
        }
        __syncthreads();
        for (int p = tid; p < 336; p += 256) {
            int o = p / 42, vm = p % 42;
            float acc = sh_cb[o];
            #pragma unroll
            for (int t = 0; t < 8; t++) acc += sh_cw[o*8 + t] * sh_hv[t*42 + vm];
            g_seq8[(size_t)(n*8 + o)*KPAD + w*42 + vm] = to8(acc * SA_SEQ);
        }
    }
}

// ---------------- weight folding ----------------
__global__ void k_cw(const float* __restrict__ W1, const float* __restrict__ wq,
                     float* __restrict__ Wc) {
    int i = blockIdx.x*blockDim.x + threadIdx.x;
    if (i >= EMB*EMB) return;
    int o = i / EMB, ii = i % EMB;
    float acc = 0.f;
    for (int m = 0; m < EMB; m++) acc += W1[o*EMB + m] * wq[m*EMB + ii];
    Wc[i] = acc;
}

__global__ void k_cb(const float* __restrict__ W1, const float* __restrict__ b1,
                     const float* __restrict__ bq, float* __restrict__ bc) {
    int o = blockIdx.x*blockDim.x + threadIdx.x;
    if (o >= EMB) return;
    float acc = b1[o];
    for (int m = 0; m < EMB; m++) acc += W1[o*EMB + m] * bq[m];
    bc[o] = acc;
}

__global__ void k_prep8(const float* __restrict__ src, unsigned char* __restrict__ dst,
                        int total_rows, int rows_src) {
    int i = blockIdx.x*blockDim.x + threadIdx.x;
    if (i >= total_rows*KPAD) return;
    int r = i / KPAD, c = i - r*KPAD;
    float v = (r < rows_src && c < 336) ? src[(size_t)r*336 + c] * SW_W : 0.f;
    dst[i] = to8(v);
}

// ---------------- fp8 mma.sync GEMM ----------------
#define STG3     3
#define BUFB     6144
#define ARRB     (STG3*BUFB)
#define SMEM_DYN (2*ARRB + 4096 + 256)

template<int MODE>
__global__ __launch_bounds__(256) void k_gemm_mma(
        const unsigned char* __restrict__ A, const unsigned char* __restrict__ B,
        const float* __restrict__ bias, float* __restrict__ C,
        unsigned char* __restrict__ O8, __nv_bfloat16* __restrict__ Ob,
        int Nn, float inv, float outsc) {
    extern __shared__ __align__(16) char dsm[];
    float* s_pw = (float*)(dsm + 2*ARRB);
    float* s_pb = s_pw + 1024;

    const int tid = threadIdx.x, lane = tid & 31, wid = tid >> 5;
    const int warpM = wid & 1, warpN = wid >> 1;
    const int row0 = blockIdx.y << 7, col0 = blockIdx.x << 7;

    if (MODE == 1) {
        for (int i = tid; i < 1024; i += 256) s_pw[i] = g_pwf[i];
        if (tid < 64) s_pb[tid] = g_pbf[tid];
    }

    const int lrow = tid >> 1, lhalf = tid & 1;
    const unsigned char* gA = A + (size_t)(row0 + lrow)*KPAD + lhalf*16;
    const unsigned char* gB = B + (size_t)(col0 + lrow)*KPAD + lhalf*16;
    const unsigned sb = smem_u32(dsm);
    const int so = lrow*48 + lhalf*16;

    const int rsubA = (lane & 7) + ((lane >> 3) & 1)*8;
    const int cA = (warpM*64 + rsubA)*48 + ((lane >> 4) & 1)*16;
    const int rsubB = (lane & 7) + ((lane >> 4) & 1)*8;
    const int cB = (warpN*32 + rsubB)*48 + ((lane >> 3) & 1)*16;

    float acc[4][4][4];
    #pragma unroll
    for (int i = 0; i < 4; i++)
        #pragma unroll
        for (int j = 0; j < 4; j++)
            #pragma unroll
            for (int q = 0; q < 4; q++) acc[i][j][q] = 0.f;

    #pragma unroll
    for (int st = 0; st < 2; st++) {
        unsigned d = sb + st*BUFB + so;
        cpa16(d,        gA + st*32);
        cpa16(d + ARRB, gB + st*32);
        asm volatile("cp.async.commit_group;");
    }

    #pragma unroll 1
    for (int ch = 0; ch < NSTEP; ch++) {
        if (ch == NSTEP-1) asm volatile("cp.async.wait_group 0;");
        else               asm volatile("cp.async.wait_group 1;");
        __syncthreads();
        if (ch + 2 < NSTEP) {
            unsigned d = sb + ((ch+2)%3)*BUFB + so;
            cpa16(d,        gA + (ch+2)*32);
            cpa16(d + ARRB, gB + (ch+2)*32);
            asm volatile("cp.async.commit_group;");
        }
        const unsigned bo = sb + (ch%3)*BUFB;
        unsigned AH[4][4];
        #pragma unroll
        for (int mt = 0; mt < 4; mt++)
            ldm4(AH[mt], bo + cA + mt*768);
        #pragma unroll
        for (int p = 0; p < 2; p++) {
            unsigned BH[4];
            ldm4(BH, bo + ARRB + cB + p*768);
            #pragma unroll
            for (int mt = 0; mt < 4; mt++) {
                #pragma unroll
                for (int q = 0; q < 2; q++)
                    mma_fp8(acc[mt][2*p + q], AH[mt], BH + 2*q);
            }
        }
    }

    if (MODE == 3) {
        #pragma unroll
        for (int mt = 0; mt < 4; mt++) {
            int r1 = row0 + warpM*64 + mt*16 + (lane >> 2);
            #pragma unroll
            for (int nt = 0; nt < 4; nt++) {
                int gc = col0 + warpN*32 + nt*8 + (lane & 3)*2;
                if (gc < Nn) {
                    float b0 = __ldg(bias + gc), b1 = __ldg(bias + gc + 1);
                    float* ac = acc[mt][nt];
                    __nv_bfloat162 v0 = __floats2bfloat162_rn(ac[0]*inv + b0, ac[1]*inv + b1);
                    __nv_bfloat162 v1 = __floats2bfloat162_rn(ac[2]*inv + b0, ac[3]*inv + b1);
                    *(__nv_bfloat162*)(Ob + (size_t)r1*Nn + gc)     = v0;
                    *(__nv_bfloat162*)(Ob + (size_t)(r1+8)*Nn + gc) = v1;
                }
            }
        }
    } else if (MODE == 2) {
        #pragma unroll
        for (int mt = 0; mt < 4; mt++) {
            int r1 = row0 + warpM*64 + mt*16 + (lane >> 2);
            #pragma unroll
            for (int nt = 0; nt < 4; nt++) {
                int gc = col0 + warpN*32 + nt*8 + (lane & 3)*2;
                if (gc < Nn) {
                    float b0 = __ldg(bias + gc), b1 = __ldg(bias + gc + 1);
                    float* ac = acc[mt][nt];
                    unsigned short p0 = (unsigned short)to8((ac[0]*inv + b0)*outsc)
                                      | ((unsigned short)to8((ac[1]*inv + b1)*outsc) << 8);
                    unsigned short p1 = (unsigned short)to8((ac[2]*inv + b0)*outsc)
                                      | ((unsigned short)to8((ac[3]*inv + b1)*outsc) << 8);
                    *(unsigned short*)(O8 + (size_t)r1*KPAD + gc)     = p0;
                    *(unsigned short*)(O8 + (size_t)(r1+8)*KPAD + gc) = p1;
                }
            }
        }
    } else {
        __syncthreads();
        float* xs = (float*)dsm;
        const int v0 = col0 >> 6;
        for (int i = tid; i < 4096; i += 256) {
            int vml = i >> 11, r = (i >> 4) & 127, c = i & 15;
            xs[vml*2176 + r*17 + c] = g_xn[((size_t)(row0 + r)*42 + v0 + vml)*16 + c];
        }
        __syncthreads();

        const int vml = warpN >> 1;
        #pragma unroll
        for (int mt = 0; mt < 4; mt++) {
            int rl1 = warpM*64 + mt*16 + (lane >> 2);
            int rl2 = rl1 + 8;
            float xa[16], xc2[16];
            #pragma unroll
            for (int c = 0; c < 16; c++) {
                xa[c]  = xs[vml*2176 + rl1*17 + c];
                xc2[c] = xs[vml*2176 + rl2*17 + c];
            }
            #pragma unroll
            for (int nt = 0; nt < 4; nt++) {
                int co = (warpN & 1)*32 + nt*8 + (lane & 3)*2;
                int gc = col0 + (warpN & 1)*32 + (vml ? 64 : 0) + nt*8 + (lane & 3)*2;
                float fb0 = __ldg(bias + gc) + s_pb[co];
                float fb1 = __ldg(bias + gc + 1) + s_pb[co + 1];
                unsigned long long rv1 = pack2(fb0, fb1);
                unsigned long long rv2 = rv1;
                #pragma unroll
                for (int c = 0; c < 16; c++) {
                    unsigned long long w2 = *(const unsigned long long*)&s_pw[c*64 + co];
                    rv1 = ffma2(pack2(xa[c],  xa[c]),  w2, rv1);
                    rv2 = ffma2(pack2(xc2[c], xc2[c]), w2, rv2);
                }
                float2 u1 = unpack2(rv1), u2 = unpack2(rv2);
                float* ac = acc[mt][nt];
                int r1 = row0 + rl1, r2 = row0 + rl2;
                *(float2*)(C + (size_t)r1*2688 + gc) =
                    make_float2(fmaxf(ac[0]*inv + u1.x, 0.f), fmaxf(ac[1]*inv + u1.y, 0.f));
                *(float2*)(C + (size_t)r2*2688 + gc) =
                    make_float2(fmaxf(ac[2]*inv + u2.x, 0.f), fmaxf(ac[3]*inv + u2.y, 0.f));
            }
        }
    }
}

// ---------------- attention (bf16 qkv in, fp8 ao out) ----------------
__global__ __launch_bounds__(256) void k_attn2() {
    __shared__ float sq[8*1012];
    __shared__ float sc[256], at[256];
    const int n = blockIdx.x, tid = threadIdx.x;
    const __nv_bfloat16* src = g_qkvb + (size_t)n*8064;
    for (int i = tid; i < 4032; i += 256) {
        int j = i*2;
        int r = j / 1008, c = j - r*1008;
        float2 f = __bfloat1622float2(*(const __nv_bfloat162*)(src + j));
        sq[r*1012 + c]     = f.x;
        sq[r*1012 + c + 1] = f.y;
    }
    __syncthreads();
    const int h = tid >> 6, s = (tid >> 3) & 7, t = tid & 7;
    {
        const float* qr = sq + s*1012 + h*84;
        const float* kr = sq + t*1012 + 336 + h*84;
        float acc = 0.f;
        #pragma unroll 12
        for (int d = 0; d < 84; d++) acc += qr[d]*kr[d];
        sc[tid] = acc * 0.1091089451179961805f;
    }
    __syncthreads();
    const int rb = tid & ~7;
    float mx = sc[rb];
    #pragma unroll
    for (int k = 1; k < 8; k++) mx = fmaxf(mx, sc[rb + k]);
    float e = expf(sc[tid] - mx);
    at[tid] = e;
    __syncthreads();
    float sum = 0.f;
    #pragma unroll
    for (int k = 0; k < 8; k++) sum += at[rb + k];
    float a = e / sum;
    __syncthreads();
    at[tid] = a;
    __syncthreads();
    for (int idx = tid; idx < 2688; idx += 256) {
        int s2 = idx / 336, c = idx - s2*336;
        int hh = c / 84, d = c - hh*84;
        const float* vr = sq + 672 + hh*84 + d;
        const float* ar = at + hh*64 + s2*8;
        float o = 0.f;
        #pragma unroll
        for (int k = 0; k < 8; k++) o += ar[k] * vr[k*1012];
        g_ao8[(size_t)(n*8 + s2)*KPAD + c] = to8(o * SA_AO);
    }
}

// ---------------- launcher (two-stream overlap) ----------------
extern "C" void kernel_launch(void* const* d_in, const int* in_sizes, int n_in,
                              void* d_out, int out_size) {
    const float* x   = (const float*)d_in[0];
    const int*   hi  = (const int*)  d_in[1];
    const float* hcw = (const float*)d_in[2];
    const float* hcb = (const float*)d_in[3];
    const float* cw  = (const float*)d_in[4];
    const float* cb  = (const float*)d_in[5];
    const float* gam = (const float*)d_in[6];
    const float* bet = (const float*)d_in[7];
    const float* pw  = (const float*)d_in[8];
    const float* pb  = (const float*)d_in[9];
    const float* wq  = (const float*)d_in[10];
    const float* bq  = (const float*)d_in[11];
    const float* wk  = (const float*)d_in[12];
    const float* bk  = (const float*)d_in[13];
    const float* wv  = (const float*)d_in[14];
    const float* bv  = (const float*)d_in[15];
    const float* ipw = (const float*)d_in[16];
    const float* ipb = (const float*)d_in[17];
    const float* opw = (const float*)d_in[18];
    const float* opb = (const float*)d_in[19];
    const float* fw  = (const float*)d_in[20];
    const float* fb  = (const float*)d_in[21];
    float* out = (float*)d_out;

    float *p_Wc, *p_bc;
    cudaGetSymbolAddress((void**)&p_Wc,  g_Wc);
    cudaGetSymbolAddress((void**)&p_bc,  g_bc);
    __nv_bfloat16* p_qkvb;
    cudaGetSymbolAddress((void**)&p_qkvb, g_qkvb);
    unsigned char *p_seq8,*p_ao8,*p_o28,*p_wc8,*p_op8,*p_fw8;
    cudaGetSymbolAddress((void**)&p_seq8, g_seq8);
    cudaGetSymbolAddress((void**)&p_ao8,  g_ao8);
    cudaGetSymbolAddress((void**)&p_o28,  g_o28);
    cudaGetSymbolAddress((void**)&p_wc8,  g_wc8);
    cudaGetSymbolAddress((void**)&p_op8,  g_op8);
    cudaGetSymbolAddress((void**)&p_fw8,  g_fw8);

    cudaFuncSetAttribute(k_gemm_mma<1>, cudaFuncAttributeMaxDynamicSharedMemorySize, SMEM_DYN);
    cudaFuncSetAttribute(k_gemm_mma<2>, cudaFuncAttributeMaxDynamicSharedMemorySize, SMEM_DYN);
    cudaFuncSetAttribute(k_gemm_mma<3>, cudaFuncAttributeMaxDynamicSharedMemorySize, SMEM_DYN);

    // side stream + events (created once, on first — uncaptured — call)
    static cudaStream_t s2 = nullptr;
    static cudaEvent_t evStage = nullptr, evJoin = nullptr;
    if (!s2) {
        cudaStreamCreateWithFlags(&s2, cudaStreamNonBlocking);
        cudaEventCreateWithFlags(&evStage, cudaEventDisableTiming);
        cudaEventCreateWithFlags(&evJoin,  cudaEventDisableTiming);
    }

    // ---- main stream (0): graph path ----
    k_zero<<<(NN16/8 + 255)/256, 256>>>();
    k_stage<<<NB, 256>>>(x);
    cudaEventRecord(evStage, 0);            // stats ready (for bnfin on s2)

    // ---- side stream: weight folding + fp8 prep (independent of graph path) ----
    k_cw<<<(EMB*EMB + 255)/256, 256, 0, s2>>>(ipw,             wq, p_Wc);
    k_cw<<<(EMB*EMB + 255)/256, 256, 0, s2>>>(ipw +   EMB*EMB, wk, p_Wc +   EMB*EMB);
    k_cw<<<(EMB*EMB + 255)/256, 256, 0, s2>>>(ipw + 2*EMB*EMB, wv, p_Wc + 2*EMB*EMB);
    k_cb<<<2, 256, 0, s2>>>(ipw,             ipb,         bq, p_bc);
    k_cb<<<2, 256, 0, s2>>>(ipw +   EMB*EMB, ipb +   EMB, bk, p_bc + EMB);
    k_cb<<<2, 256, 0, s2>>>(ipw + 2*EMB*EMB, ipb + 2*EMB, bv, p_bc + 2*EMB);
    k_prep8<<<(1024*KPAD + 255)/256, 256, 0, s2>>>(p_Wc, p_wc8, 1024, 1008);
    k_prep8<<<(384*KPAD + 255)/256, 256, 0, s2>>>(opw, p_op8, 384, 336);
    k_prep8<<<(2688*KPAD + 255)/256, 256, 0, s2>>>(fw, p_fw8, 2688, 2688);
    cudaStreamWaitEvent(s2, evStage, 0);
    k_bnfin<<<1, 64, 0, s2>>>(gam, bet, pw, pb);
    cudaEventRecord(evJoin, s2);

    // ---- main stream continues: scatters + seq ----
    k_scatter_e<<<(EINC + 255)/256, 256>>>(hi);
    k_scatter_h<<<(EINC + 255)/256, 256>>>(hi);
    k_seq2<<<NB, 256>>>(hcw, hcb, cw, cb);

    // join: GEMMs need weight prep results
    cudaStreamWaitEvent(0, evJoin, 0);

    k_gemm_mma<3><<<dim3(8, ROWS/128), 256, SMEM_DYN>>>(
        p_seq8, p_wc8, p_bc, nullptr, nullptr, p_qkvb, 1008, INV_QKV, 0.f);
    k_attn2<<<NB, 256>>>();
    k_gemm_mma<2><<<dim3(3, ROWS/128), 256, SMEM_DYN>>>(
        p_ao8, p_op8, opb, nullptr, p_o28, nullptr, 336, INV_OP, SA_O2);
    k_gemm_mma<1><<<dim3(21, ROWS/128), 256, SMEM_DYN>>>(
        p_o28, p_fw8, fb, out, nullptr, nullptr, 2688, INV_FC, 0.f);
}

// round 14
// speedup vs baseline: 2.4471x; 1.0001x over previous
#include <cuda_runtime.h>
#include <cuda_bf16.h>
#include <cuda_fp8.h>
#include <math.h>

#define NB    2048
#define CIN   16
#define VMD   42
#define NNODE (NB*8*VMD)            // 688128
#define EINC  (4*NNODE)             // 2752512
#define EMB   336
#define ROWS  (NB*8)                // 16384
#define KPAD  352
#define NSTEP 11
#define NN16  (NNODE*16)

// fp8 scales
#define SW_W    256.f
#define SA_SEQ  64.f
#define SA_AO   4096.f
#define SA_O2   8192.f
#define INV_QKV (1.f/(SA_SEQ*SW_W))
#define INV_OP  (1.f/(SA_AO*SW_W))
#define INV_FC  (1.f/(SA_O2*SW_W))

// ---------------- scratch ----------------
__device__ __align__(16) float  g_xn[NN16];
__device__ __align__(16) __nv_bfloat16 g_xnb[NN16];
__device__ __align__(16) __nv_bfloat16 g_e [NN16];
__device__ __align__(16) __nv_bfloat16 g_h [NN16];
__device__ __align__(16) float  g_D [NNODE];
__device__ __align__(16) float  g_B [NNODE];
__device__ __align__(16) __nv_bfloat16 g_qkvb[ROWS*1008];
__device__ __align__(16) float  g_bc [3*EMB];
__device__ double g_sum[CIN], g_sum2[CIN];
__device__ float  g_pwf[16*64];
__device__ float  g_pbf[64];
// fp8 staging
__device__ __align__(16) unsigned char g_seq8[ROWS*KPAD];
__device__ __align__(16) unsigned char g_ao8 [ROWS*KPAD];
__device__ __align__(16) unsigned char g_o28 [ROWS*KPAD];
__device__ __align__(16) unsigned char g_wc8 [1024*KPAD];
__device__ __align__(16) unsigned char g_op8 [384*KPAD];
__device__ __align__(16) unsigned char g_fw8 [2688*KPAD];

// ---------------- helpers ----------------
__device__ __forceinline__ unsigned smem_u32(const void* p) {
    unsigned a;
    asm("{ .reg .u64 t; cvta.to.shared.u64 t, %1; cvt.u32.u64 %0, t; }" : "=r"(a) : "l"(p));
    return a;
}
__device__ __forceinline__ void ldm4(unsigned* r, unsigned addr) {
    asm volatile("ldmatrix.sync.aligned.m8n8.x4.shared.b16 {%0,%1,%2,%3}, [%4];"
        : "=r"(r[0]), "=r"(r[1]), "=r"(r[2]), "=r"(r[3]) : "r"(addr));
}
__device__ __forceinline__ void mma_fp8(float* d, const unsigned* a, const unsigned* b) {
    asm volatile("mma.sync.aligned.m16n8k32.row.col.f32.e4m3.e4m3.f32 "
        "{%0,%1,%2,%3}, {%4,%5,%6,%7}, {%8,%9}, {%0,%1,%2,%3};"
        : "+f"(d[0]), "+f"(d[1]), "+f"(d[2]), "+f"(d[3])
        : "r"(a[0]), "r"(a[1]), "r"(a[2]), "r"(a[3]), "r"(b[0]), "r"(b[1]));
}
__device__ __forceinline__ void cpa16(unsigned dst, const void* src) {
    asm volatile("cp.async.cg.shared.global [%0], [%1], 16;" :: "r"(dst), "l"(src));
}
__device__ __forceinline__ unsigned long long ffma2(unsigned long long a,
                                                    unsigned long long b,
                                                    unsigned long long c) {
    unsigned long long d;
    asm("fma.rn.f32x2 %0, %1, %2, %3;" : "=l"(d) : "l"(a), "l"(b), "l"(c));
    return d;
}
__device__ __forceinline__ unsigned long long pack2(float x, float y) {
    unsigned long long d;
    asm("mov.b64 %0, {%1, %2};" : "=l"(d) : "f"(x), "f"(y));
    return d;
}
__device__ __forceinline__ float2 unpack2(unsigned long long v) {
    float2 r;
    asm("mov.b64 {%0, %1}, %2;" : "=f"(r.x), "=f"(r.y) : "l"(v));
    return r;
}
__device__ __forceinline__ unsigned char to8(float v) {
    __nv_fp8_e4m3 f(v);
    return *(unsigned char*)&f;
}
__device__ __forceinline__ void red_v4bf16x2(__nv_bfloat16* dst, unsigned r0, unsigned r1,
                                             unsigned r2, unsigned r3) {
    asm volatile("red.global.add.noftz.v4.bf16x2 [%0], {%1, %2, %3, %4};"
                 :: "l"(dst), "r"(r0), "r"(r1), "r"(r2), "r"(r3) : "memory");
}

// ---------------- init ----------------
__global__ void k_zero() {
    int i = blockIdx.x*blockDim.x + threadIdx.x;
    uint4 z = make_uint4(0u,0u,0u,0u);
    if (i < NN16/8) { ((uint4*)g_e)[i] = z; ((uint4*)g_h)[i] = z; }
    if (i < NNODE) { g_D[i] = 0.f; g_B[i] = 0.f; }
    if (i < CIN) { g_sum[i] = 0.0; g_sum2[i] = 0.0; }
    if (i < ROWS*16) {
        size_t off = (size_t)(i >> 4)*KPAD + 336 + (i & 15);
        g_seq8[off] = 0; g_ao8[off] = 0; g_o28[off] = 0;
    }
    // wc8 pad columns (rows 0..1023) + tail rows 1008..1023
    if (i < 1024*16)
        g_wc8[(size_t)(i >> 4)*KPAD + 336 + (i & 15)] = 0;
    if (i < 16*336)
        g_wc8[(size_t)(1008 + i/336)*KPAD + (i % 336)] = 0;
}

// ---------------- stage x node-major + fused BN stats ----------------
__global__ __launch_bounds__(256) void k_stage(const float* __restrict__ x) {
    __shared__ float sx[16*337];
    __shared__ float rs[256], rs2[256];
    const int n = blockIdx.x, tid = threadIdx.x;
    const float* xp = x + (size_t)n*5376;
    for (int i = tid; i < 5376; i += 256) {
        int c = i / 336, rem = i % 336;
        sx[c*337 + rem] = xp[i];
    }
    __syncthreads();
    const int c = tid & 15, no = tid >> 4;
    float cs = 0.f, cs2 = 0.f;
    for (int node = no; node < 336; node += 16) {
        float v = sx[c*337 + node];
        cs += v; cs2 += v*v;
    }
    rs[tid] = cs; rs2[tid] = cs2;
    __syncthreads();
    for (int o = 128; o >= 16; o >>= 1) {
        if (tid < o) { rs[tid] += rs[tid + o]; rs2[tid] += rs2[tid + o]; }
        __syncthreads();
    }
    if (tid < 16) {
        atomicAdd(&g_sum[tid], (double)rs[tid]);
        atomicAdd(&g_sum2[tid], (double)rs2[tid]);
    }
    const size_t base = (size_t)n*5376;
    for (int i = tid; i < 5376; i += 256) {
        int rem = i >> 4, ch = i & 15;
        float v = sx[ch*337 + rem];
        g_xn[base + i] = v;
        g_xnb[base + i] = __float2bfloat16(v);
    }
}

// finalize BN + fold into proj weights
__global__ void k_bnfin(const float* __restrict__ gamma, const float* __restrict__ beta,
                        const float* __restrict__ pw, const float* __restrict__ pb) {
    __shared__ float ssc[16], ssh[16];
    int t = threadIdx.x;
    if (t < 16) {
        double cnt = (double)NNODE;
        double mean = g_sum[t] / cnt;
        double var  = g_sum2[t] / cnt - mean*mean;
        float sc = gamma[t] * rsqrtf((float)var + 1e-5f);
        ssc[t] = sc;
        ssh[t] = beta[t] - (float)mean * sc;
    }
    __syncthreads();
    if (t < 64) {
        float acc = pb[t];
        #pragma unroll
        for (int c = 0; c < 16; c++) {
            float w = pw[t*16 + c];
            acc += ssh[c] * w;
            g_pwf[c*64 + t] = w * ssc[c];
        }
        g_pbf[t] = acc;
    }
}

// ---------------- scatter pass 1 + degree counting ----------------
__global__ void k_scatter_e(const int* __restrict__ hi) {
    int i = blockIdx.x*blockDim.x + threadIdx.x;
    if (i >= EINC) return;
    int node = __ldg(&hi[i]), edge = __ldg(&hi[EINC + i]);
    atomicAdd(&g_D[node], 1.f);
    atomicAdd(&g_B[edge], 1.f);
    const uint4* src = (const uint4*)(g_xnb + (size_t)node*16);
    uint4 v0 = src[0], v1 = src[1];
    __nv_bfloat16* dst = g_e + (size_t)edge*16;
    red_v4bf16x2(dst,     v0.x, v0.y, v0.z, v0.w);
    red_v4bf16x2(dst + 8, v1.x, v1.y, v1.z, v1.w);
}

// ---------------- scatter pass 2 (Binv inline) ----------------
__global__ void k_scatter_h(const int* __restrict__ hi) {
    int i = blockIdx.x*blockDim.x + threadIdx.x;
    if (i >= EINC) return;
    int node = __ldg(&hi[i]), edge = __ldg(&hi[EINC + i]);
    float b = g_B[edge];
    float w = (b > 0.f) ? (1.f / b) : 0.f;
    __nv_bfloat162 w2 = __float2bfloat162_rn(w);
    const uint4* src = (const uint4*)(g_e + (size_t)edge*16);
    uint4 v0 = src[0], v1 = src[1];
    __nv_bfloat162 a0 = __hmul2(*(__nv_bfloat162*)&v0.x, w2);
    __nv_bfloat162 a1 = __hmul2(*(__nv_bfloat162*)&v0.y, w2);
    __nv_bfloat162 a2 = __hmul2(*(__nv_bfloat162*)&v0.z, w2);
    __nv_bfloat162 a3 = __hmul2(*(__nv_bfloat162*)&v0.w, w2);
    __nv_bfloat162 b0 = __hmul2(*(__nv_bfloat162*)&v1.x, w2);
    __nv_bfloat162 b1 = __hmul2(*(__nv_bfloat162*)&v1.y, w2);
    __nv_bfloat162 b2 = __hmul2(*(__nv_bfloat162*)&v1.z, w2);
    __nv_bfloat162 b3 = __hmul2(*(__nv_bfloat162*)&v1.w, w2);
    __nv_bfloat16* dst = g_h + (size_t)node*16;
    red_v4bf16x2(dst,     *(unsigned*)&a0, *(unsigned*)&a1, *(unsigned*)&a2, *(unsigned*)&a3);
    red_v4bf16x2(dst + 8, *(unsigned*)&b0, *(unsigned*)&b1, *(unsigned*)&b2, *(unsigned*)&b3);
}

// ---------------- fused hconv + time-conv -> seq ----------------
__global__ __launch_bounds__(256) void k_seq2(
        const float* __restrict__ hcw, const float* __restrict__ hcb,
        const float* __restrict__ cw,  const float* __restrict__ cb) {
    __shared__ float sh_h[336*16];
    __shared__ float sh_w[16*64];
    __shared__ float sh_hv[336];
    __shared__ float sh_cw[64], sh_cb[8], sh_hcb[64];
    const int n = blockIdx.x, tid = threadIdx.x;
    const uint4* hsrc = (const uint4*)(g_h + (size_t)n*5376);
    const float* dsrc = g_D + n*336;
    for (int i = tid; i < 672; i += 256) {
        float dc = dsrc[i >> 1];
        float d = (dc > 0.f) ? (1.f / dc) : 0.f;
        uint4 v = hsrc[i];
        float2 f0 = __bfloat1622float2(*(__nv_bfloat162*)&v.x);
        float2 f1 = __bfloat1622float2(*(__nv_bfloat162*)&v.y);
        float2 f2 = __bfloat1622float2(*(__nv_bfloat162*)&v.z);
        float2 f3 = __bfloat1622float2(*(__nv_bfloat162*)&v.w);
        float* o = sh_h + 8*i;
        o[0] = f0.x*d; o[1] = f0.y*d; o[2] = f1.x*d; o[3] = f1.y*d;
        o[4] = f2.x*d; o[5] = f2.y*d; o[6] = f3.x*d; o[7] = f3.y*d;
    }
    for (int i = tid; i < 1024; i += 256) {
        int co = i & 63, ci = i >> 6;
        sh_w[ci*64 + co] = hcw[co*16 + ci];
    }
    if (tid < 64) { sh_cw[tid] = cw[tid]; sh_hcb[tid] = hcb[tid]; }
    if (tid < 8)  sh_cb[tid] = cb[tid];

    for (int w = 0; w < 8; w++) {
        __syncthreads();
        for (int inner = tid; inner < 336; inner += 256) {
            int nodeL = w*42 + (inner >> 6);
            int c = inner & 63;
            const float* hr = sh_h + nodeL*16;
            float acc = sh_hcb[c];
            #pragma unroll
            for (int j = 0; j < 16; j++) acc += hr[j] * sh_w[j*64 + c];
            sh_hv[inner] = acc;
        }
        __syncthreads();
        for (int p = tid; p < 336; p += 256) {
            int o = p / 42, vm = p % 42;
            float acc = sh_cb[o];
            #pragma unroll
            for (int t = 0; t < 8; t++) acc += sh_cw[o*8 + t] * sh_hv[t*42 + vm];
            g_seq8[(size_t)(n*8 + o)*KPAD + w*42 + vm] = to8(acc * SA_SEQ);
        }
    }
}

// ---------------- fused weight folding -> fp8 (tiled GEMM, 3 pairs in one launch) ----------------
// out wc8[(z*336+o)*KPAD + i] = fp8( SW_W * sum_m W1z[o][m] * wqz[m][i] )
__global__ __launch_bounds__(256) void k_cw8(
        const float* __restrict__ ipw, const float* __restrict__ wq,
        const float* __restrict__ wk,  const float* __restrict__ wv) {
    __shared__ float As[16][68];   // A[o][k] tile transposed: As[k][o]
    __shared__ float Bs[16][68];   // B[k][i]
    const int z = blockIdx.z;
    const float* W1 = ipw + (size_t)z*EMB*EMB;
    const float* Wr = (z == 0) ? wq : (z == 1) ? wk : wv;
    const int tid = threadIdx.x;
    const int row0 = blockIdx.y << 6, col0 = blockIdx.x << 6;
    const int tx = tid & 15, ty = tid >> 4;
    float acc[4][4] = {};
    const int lr = tid >> 2, lk4 = (tid & 3) << 2;   // A: 64 rows x 16 k
    #pragma unroll 1
    for (int kk = 0; kk < EMB; kk += 16) {
        // load A tile: rows row0+lr, cols kk+lk4..+3 (guard row)
        {
            int r = row0 + lr;
            float4 a = (r < EMB) ? *(const float4*)(W1 + (size_t)r*EMB + kk + lk4)
                                 : make_float4(0.f,0.f,0.f,0.f);
            As[lk4+0][lr] = a.x; As[lk4+1][lr] = a.y;
            As[lk4+2][lr] = a.z; As[lk4+3][lr] = a.w;
        }
        // load B tile: rows kk+(tid>>4), cols col0+(tid&15)*4 (guard col)
        {
            int kr = kk + (tid >> 4);
            int cc = col0 + ((tid & 15) << 2);
            float4 b = (cc + 3 < EMB) ? *(const float4*)(Wr + (size_t)kr*EMB + cc)
                      : make_float4(cc < EMB ? Wr[(size_t)kr*EMB+cc] : 0.f,
                                    cc+1 < EMB ? Wr[(size_t)kr*EMB+cc+1] : 0.f,
                                    cc+2 < EMB ? Wr[(size_t)kr*EMB+cc+2] : 0.f, 0.f);
            Bs[tid >> 4][((tid & 15) << 2) + 0] = b.x;
            Bs[tid >> 4][((tid & 15) << 2) + 1] = b.y;
            Bs[tid >> 4][((tid & 15) << 2) + 2] = b.z;
            Bs[tid >> 4][((tid & 15) << 2) + 3] = b.w;
        }
        __syncthreads();
        #pragma unroll
        for (int k = 0; k < 16; k++) {
            float a0 = As[k][(ty<<2)+0], a1 = As[k][(ty<<2)+1];
            float a2 = As[k][(ty<<2)+2], a3 = As[k][(ty<<2)+3];
            float b0 = Bs[k][(tx<<2)+0], b1 = Bs[k][(tx<<2)+1];
            float b2 = Bs[k][(tx<<2)+2], b3 = Bs[k][(tx<<2)+3];
            acc[0][0]+=a0*b0; acc[0][1]+=a0*b1; acc[0][2]+=a0*b2; acc[0][3]+=a0*b3;
            acc[1][0]+=a1*b0; acc[1][1]+=a1*b1; acc[1][2]+=a1*b2; acc[1][3]+=a1*b3;
            acc[2][0]+=a2*b0; acc[2][1]+=a2*b1; acc[2][2]+=a2*b2; acc[2][3]+=a2*b3;
            acc[3][0]+=a3*b0; acc[3][1]+=a3*b1; acc[3][2]+=a3*b2; acc[3][3]+=a3*b3;
        }
        __syncthreads();
    }
    #pragma unroll
    for (int i = 0; i < 4; i++) {
        int o = row0 + (ty<<2) + i;
        if (o >= EMB) break;
        #pragma unroll
        for (int j = 0; j < 4; j++) {
            int c = col0 + (tx<<2) + j;
            if (c < EMB)
                g_wc8[(size_t)(z*EMB + o)*KPAD + c] = to8(acc[i][j] * SW_W);
        }
    }
}

// ---------------- bias folding ----------------
__global__ void k_cb(const float* __restrict__ W1, const float* __restrict__ b1,
                     const float* __restrict__ bq, float* __restrict__ bc) {
    int o = blockIdx.x*blockDim.x + threadIdx.x;
    if (o >= EMB) return;
    float acc = b1[o];
    for (int m = 0; m < EMB; m++) acc += W1[o*EMB + m] * bq[m];
    bc[o] = acc;
}

__global__ void k_prep8(const float* __restrict__ src, unsigned char* __restrict__ dst,
                        int total_rows, int rows_src) {
    int i = blockIdx.x*blockDim.x + threadIdx.x;
    if (i >= total_rows*KPAD) return;
    int r = i / KPAD, c = i - r*KPAD;
    float v = (r < rows_src && c < 336) ? src[(size_t)r*336 + c] * SW_W : 0.f;
    dst[i] = to8(v);
}

// ---------------- fp8 mma.sync GEMM ----------------
#define STG3     3
#define BUFB     6144
#define ARRB     (STG3*BUFB)
#define SMEM_DYN (2*ARRB + 4096 + 256)

template<int MODE>
__global__ __launch_bounds__(256) void k_gemm_mma(
        const unsigned char* __restrict__ A, const unsigned char* __restrict__ B,
        const float* __restrict__ bias, float* __restrict__ C,
        unsigned char* __restrict__ O8, __nv_bfloat16* __restrict__ Ob,
        int Nn, float inv, float outsc) {
    extern __shared__ __align__(16) char dsm[];
    float* s_pw = (float*)(dsm + 2*ARRB);
    float* s_pb = s_pw + 1024;

    const int tid = threadIdx.x, lane = tid & 31, wid = tid >> 5;
    const int warpM = wid & 1, warpN = wid >> 1;
    const int row0 = blockIdx.y << 7, col0 = blockIdx.x << 7;

    if (MODE == 1) {
        for (int i = tid; i < 1024; i += 256) s_pw[i] = g_pwf[i];
        if (tid < 64) s_pb[tid] = g_pbf[tid];
    }

    const int lrow = tid >> 1, lhalf = tid & 1;
    const unsigned char* gA = A + (size_t)(row0 + lrow)*KPAD + lhalf*16;
    const unsigned char* gB = B + (size_t)(col0 + lrow)*KPAD + lhalf*16;
    const unsigned sb = smem_u32(dsm);
    const int so = lrow*48 + lhalf*16;

    const int rsubA = (lane & 7) + ((lane >> 3) & 1)*8;
    const int cA = (warpM*64 + rsubA)*48 + ((lane >> 4) & 1)*16;
    const int rsubB = (lane & 7) + ((lane >> 4) & 1)*8;
    const int cB = (warpN*32 + rsubB)*48 + ((lane >> 3) & 1)*16;

    float acc[4][4][4];
    #pragma unroll
    for (int i = 0; i < 4; i++)
        #pragma unroll
        for (int j = 0; j < 4; j++)
            #pragma unroll
            for (int q = 0; q < 4; q++) acc[i][j][q] = 0.f;

    #pragma unroll
    for (int st = 0; st < 2; st++) {
        unsigned d = sb + st*BUFB + so;
        cpa16(d,        gA + st*32);
        cpa16(d + ARRB, gB + st*32);
        asm volatile("cp.async.commit_group;");
    }

    #pragma unroll 1
    for (int ch = 0; ch < NSTEP; ch++) {
        if (ch == NSTEP-1) asm volatile("cp.async.wait_group 0;");
        else               asm volatile("cp.async.wait_group 1;");
        __syncthreads();
        if (ch + 2 < NSTEP) {
            unsigned d = sb + ((ch+2)%3)*BUFB + so;
            cpa16(d,        gA + (ch+2)*32);
            cpa16(d + ARRB, gB + (ch+2)*32);
            asm volatile("cp.async.commit_group;");
        }
        const unsigned bo = sb + (ch%3)*BUFB;
        unsigned AH[4][4];
        #pragma unroll
        for (int mt = 0; mt < 4; mt++)
            ldm4(AH[mt], bo + cA + mt*768);
        #pragma unroll
        for (int p = 0; p < 2; p++) {
            unsigned BH[4];
            ldm4(BH, bo + ARRB + cB + p*768);
            #pragma unroll
            for (int mt = 0; mt < 4; mt++) {
                #pragma unroll
                for (int q = 0; q < 2; q++)
                    mma_fp8(acc[mt][2*p + q], AH[mt], BH + 2*q);
            }
        }
    }

    if (MODE == 3) {
        #pragma unroll
        for (int mt = 0; mt < 4; mt++) {
            int r1 = row0 + warpM*64 + mt*16 + (lane >> 2);
            #pragma unroll
            for (int nt = 0; nt < 4; nt++) {
                int gc = col0 + warpN*32 + nt*8 + (lane & 3)*2;
                if (gc < Nn) {
                    float b0 = __ldg(bias + gc), b1 = __ldg(bias + gc + 1);
                    float* ac = acc[mt][nt];
                    __nv_bfloat162 v0 = __floats2bfloat162_rn(ac[0]*inv + b0, ac[1]*inv + b1);
                    __nv_bfloat162 v1 = __floats2bfloat162_rn(ac[2]*inv + b0, ac[3]*inv + b1);
                    *(__nv_bfloat162*)(Ob + (size_t)r1*Nn + gc)     = v0;
                    *(__nv_bfloat162*)(Ob + (size_t)(r1+8)*Nn + gc) = v1;
                }
            }
        }
    } else if (MODE == 2) {
        #pragma unroll
        for (int mt = 0; mt < 4; mt++) {
            int r1 = row0 + warpM*64 + mt*16 + (lane >> 2);
            #pragma unroll
            for (int nt = 0; nt < 4; nt++) {
                int gc = col0 + warpN*32 + nt*8 + (lane & 3)*2;
                if (gc < Nn) {
                    float b0 = __ldg(bias + gc), b1 = __ldg(bias + gc + 1);
                    float* ac = acc[mt][nt];
                    unsigned short p0 = (unsigned short)to8((ac[0]*inv + b0)*outsc)
                                      | ((unsigned short)to8((ac[1]*inv + b1)*outsc) << 8);
                    unsigned short p1 = (unsigned short)to8((ac[2]*inv + b0)*outsc)
                                      | ((unsigned short)to8((ac[3]*inv + b1)*outsc) << 8);
                    *(unsigned short*)(O8 + (size_t)r1*KPAD + gc)     = p0;
                    *(unsigned short*)(O8 + (size_t)(r1+8)*KPAD + gc) = p1;
                }
            }
        }
    } else {
        __syncthreads();
        float* xs = (float*)dsm;
        const int v0 = col0 >> 6;
        for (int i = tid; i < 4096; i += 256) {
            int vml = i >> 11, r = (i >> 4) & 127, c = i & 15;
            xs[vml*2176 + r*17 + c] = g_xn[((size_t)(row0 + r)*42 + v0 + vml)*16 + c];
        }
        __syncthreads();

        const int vml = warpN >> 1;
        #pragma unroll
        for (int mt = 0; mt < 4; mt++) {
            int rl1 = warpM*64 + mt*16 + (lane >> 2);
            int rl2 = rl1 + 8;
            float xa[16], xc2[16];
            #pragma unroll
            for (int c = 0; c < 16; c++) {
                xa[c]  = xs[vml*2176 + rl1*17 + c];
                xc2[c] = xs[vml*2176 + rl2*17 + c];
            }
            #pragma unroll
            for (int nt = 0; nt < 4; nt++) {
                int co = (warpN & 1)*32 + nt*8 + (lane & 3)*2;
                int gc = col0 + (warpN & 1)*32 + (vml ? 64 : 0) + nt*8 + (lane & 3)*2;
                float fb0 = __ldg(bias + gc) + s_pb[co];
                float fb1 = __ldg(bias + gc + 1) + s_pb[co + 1];
                unsigned long long rv1 = pack2(fb0, fb1);
                unsigned long long rv2 = rv1;
                #pragma unroll
                for (int c = 0; c < 16; c++) {
                    unsigned long long w2 = *(const unsigned long long*)&s_pw[c*64 + co];
                    rv1 = ffma2(pack2(xa[c],  xa[c]),  w2, rv1);
                    rv2 = ffma2(pack2(xc2[c], xc2[c]), w2, rv2);
                }
                float2 u1 = unpack2(rv1), u2 = unpack2(rv2);
                float* ac = acc[mt][nt];
                int r1 = row0 + rl1, r2 = row0 + rl2;
                *(float2*)(C + (size_t)r1*2688 + gc) =
                    make_float2(fmaxf(ac[0]*inv + u1.x, 0.f), fmaxf(ac[1]*inv + u1.y, 0.f));
                *(float2*)(C + (size_t)r2*2688 + gc) =
                    make_float2(fmaxf(ac[2]*inv + u2.x, 0.f), fmaxf(ac[3]*inv + u2.y, 0.f));
            }
        }
    }
}

// ---------------- attention (bf16 qkv in, fp8 ao out) ----------------
__global__ __launch_bounds__(256) void k_attn2() {
    __shared__ float sq[8*1012];
    __shared__ float sc[256], at[256];
    const int n = blockIdx.x, tid = threadIdx.x;
    const __nv_bfloat16* src = g_qkvb + (size_t)n*8064;
    for (int i = tid; i < 4032; i += 256) {
        int j = i*2;
        int r = j / 1008, c = j - r*1008;
        float2 f = __bfloat1622float2(*(const __nv_bfloat162*)(src + j));
        sq[r*1012 + c]     = f.x;
        sq[r*1012 + c + 1] = f.y;
    }
    __syncthreads();
    const int h = tid >> 6, s = (tid >> 3) & 7, t = tid & 7;
    {
        const float* qr = sq + s*1012 + h*84;
        const float* kr = sq + t*1012 + 336 + h*84;
        float acc = 0.f;
        #pragma unroll 12
        for (int d = 0; d < 84; d++) acc += qr[d]*kr[d];
        sc[tid] = acc * 0.1091089451179961805f;
    }
    __syncthreads();
    const int rb = tid & ~7;
    float mx = sc[rb];
    #pragma unroll
    for (int k = 1; k < 8; k++) mx = fmaxf(mx, sc[rb + k]);
    float e = expf(sc[tid] - mx);
    at[tid] = e;
    __syncthreads();
    float sum = 0.f;
    #pragma unroll
    for (int k = 0; k < 8; k++) sum += at[rb + k];
    float a = e / sum;
    __syncthreads();
    at[tid] = a;
    __syncthreads();
    for (int idx = tid; idx < 2688; idx += 256) {
        int s2 = idx / 336, c = idx - s2*336;
        int hh = c / 84, d = c - hh*84;
        const float* vr = sq + 672 + hh*84 + d;
        const float* ar = at + hh*64 + s2*8;
        float o = 0.f;
        #pragma unroll
        for (int k = 0; k < 8; k++) o += ar[k] * vr[k*1012];
        g_ao8[(size_t)(n*8 + s2)*KPAD + c] = to8(o * SA_AO);
    }
}

// ---------------- launcher (two-stream overlap) ----------------
extern "C" void kernel_launch(void* const* d_in, const int* in_sizes, int n_in,
                              void* d_out, int out_size) {
    const float* x   = (const float*)d_in[0];
    const int*   hi  = (const int*)  d_in[1];
    const float* hcw = (const float*)d_in[2];
    const float* hcb = (const float*)d_in[3];
    const float* cw  = (const float*)d_in[4];
    const float* cb  = (const float*)d_in[5];
    const float* gam = (const float*)d_in[6];
    const float* bet = (const float*)d_in[7];
    const float* pw  = (const float*)d_in[8];
    const float* pb  = (const float*)d_in[9];
    const float* wq  = (const float*)d_in[10];
    const float* bq  = (const float*)d_in[11];
    const float* wk  = (const float*)d_in[12];
    const float* bk  = (const float*)d_in[13];
    const float* wv  = (const float*)d_in[14];
    const float* bv  = (const float*)d_in[15];
    const float* ipw = (const float*)d_in[16];
    const float* ipb = (const float*)d_in[17];
    const float* opw = (const float*)d_in[18];
    const float* opb = (const float*)d_in[19];
    const float* fw  = (const float*)d_in[20];
    const float* fb  = (const float*)d_in[21];
    float* out = (float*)d_out;

    float *p_bc;
    cudaGetSymbolAddress((void**)&p_bc,  g_bc);
    __nv_bfloat16* p_qkvb;
    cudaGetSymbolAddress((void**)&p_qkvb, g_qkvb);
    unsigned char *p_seq8,*p_ao8,*p_o28,*p_wc8,*p_op8,*p_fw8;
    cudaGetSymbolAddress((void**)&p_seq8, g_seq8);
    cudaGetSymbolAddress((void**)&p_ao8,  g_ao8);
    cudaGetSymbolAddress((void**)&p_o28,  g_o28);
    cudaGetSymbolAddress((void**)&p_wc8,  g_wc8);
    cudaGetSymbolAddress((void**)&p_op8,  g_op8);
    cudaGetSymbolAddress((void**)&p_fw8,  g_fw8);

    cudaFuncSetAttribute(k_gemm_mma<1>, cudaFuncAttributeMaxDynamicSharedMemorySize, SMEM_DYN);
    cudaFuncSetAttribute(k_gemm_mma<2>, cudaFuncAttributeMaxDynamicSharedMemorySize, SMEM_DYN);
    cudaFuncSetAttribute(k_gemm_mma<3>, cudaFuncAttributeMaxDynamicSharedMemorySize, SMEM_DYN);

    static cudaStream_t s2 = nullptr;
    static cudaEvent_t evStage = nullptr, evJoin = nullptr;
    if (!s2) {
        cudaStreamCreateWithFlags(&s2, cudaStreamNonBlocking);
        cudaEventCreateWithFlags(&evStage, cudaEventDisableTiming);
        cudaEventCreateWithFlags(&evJoin,  cudaEventDisableTiming);
    }

    // ---- main stream (0): graph path ----
    k_zero<<<(NN16/8 + 255)/256, 256>>>();
    k_stage<<<NB, 256>>>(x);
    cudaEventRecord(evStage, 0);

    // ---- side stream: weight folding + fp8 prep ----
    k_cw8<<<dim3(6, 6, 3), 256, 0, s2>>>(ipw, wq, wk, wv);
    k_cb<<<2, 256, 0, s2>>>(ipw,             ipb,         bq, p_bc);
    k_cb<<<2, 256, 0, s2>>>(ipw +   EMB*EMB, ipb +   EMB, bk, p_bc + EMB);
    k_cb<<<2, 256, 0, s2>>>(ipw + 2*EMB*EMB, ipb + 2*EMB, bv, p_bc + 2*EMB);
    k_prep8<<<(384*KPAD + 255)/256, 256, 0, s2>>>(opw, p_op8, 384, 336);
    k_prep8<<<(2688*KPAD + 255)/256, 256, 0, s2>>>(fw, p_fw8, 2688, 2688);
    cudaStreamWaitEvent(s2, evStage, 0);
    k_bnfin<<<1, 64, 0, s2>>>(gam, bet, pw, pb);
    cudaEventRecord(evJoin, s2);

    // ---- main stream continues ----
    k_scatter_e<<<(EINC + 255)/256, 256>>>(hi);
    k_scatter_h<<<(EINC + 255)/256, 256>>>(hi);
    k_seq2<<<NB, 256>>>(hcw, hcb, cw, cb);

    cudaStreamWaitEvent(0, evJoin, 0);

    k_gemm_mma<3><<<dim3(8, ROWS/128), 256, SMEM_DYN>>>(
        p_seq8, p_wc8, p_bc, nullptr, nullptr, p_qkvb, 1008, INV_QKV, 0.f);
    k_attn2<<<NB, 256>>>();
    k_gemm_mma<2><<<dim3(3, ROWS/128), 256, SMEM_DYN>>>(
        p_ao8, p_op8, opb, nullptr, p_o28, nullptr, 336, INV_OP, SA_O2);
    k_gemm_mma<1><<<dim3(21, ROWS/128), 256, SMEM_DYN>>>(
        p_o28, p_fw8, fb, out, nullptr, nullptr, 2688, INV_FC, 0.f);
}